// round 5
// baseline (speedup 1.0000x reference)
#include <cuda_runtime.h>
#include <math.h>
#include <stdint.h>

// Problem constants
#define B_    4
#define L_    2048
#define D_    768
#define H_    12
#define DH_   64
#define F_    3072
#define KS_   307              // round(0.15 * 2048)
#define BL_   (B_*L_)          // 8192
#define MSEL_ (B_*KS_)         // 1228

#define WSZ_  589824           // 768*768
#define W1SZ_ 2359296          // 768*3072

// ---------------- scratch (static device globals; allocation-free) ----------
__device__ float g_normed [BL_*(size_t)D_];   // exact fp32 (router/pool path)
__device__ float g_normedr[BL_*(size_t)D_];   // tf32-rounded (GEMM A path)
__device__ float g_scores[BL_];
__device__ float g_ssum[B_];
__device__ int   g_selidx[MSEL_];
__device__ int   g_selpos[BL_];
__device__ float g_ppart[B_*16*D_];
__device__ float g_pooled[B_*D_];
__device__ float g_pooledWm[B_*D_];
__device__ float g_kf[BL_*(size_t)D_];
__device__ float g_vf[BL_*(size_t)D_];
__device__ float g_mixb[BL_*(size_t)D_];
__device__ float g_qsel[MSEL_*(size_t)D_];
__device__ float g_logits[(size_t)B_*H_*KS_*L_];
__device__ float g_ctx[MSEL_*(size_t)D_];
__device__ float g_attno[MSEL_*(size_t)D_];
__device__ float g_h[BL_*(size_t)D_];
__device__ float g_n2[BL_*(size_t)D_];
__device__ float g_t[BL_*(size_t)F_];
__device__ float g_wbuf[5*(size_t)WSZ_ + 2*(size_t)W1SZ_];  // rounded+transposed weights

// ---------------- small helpers ----------------
__device__ __forceinline__ uint32_t smem_u32(const void* p) {
    uint32_t a;
    asm("{ .reg .u64 t; cvta.to.shared.u64 t, %1; cvt.u32.u64 %0, t; }"
        : "=r"(a) : "l"(p));
    return a;
}
__device__ __forceinline__ uint32_t f2tf32(float x) {
    uint32_t u;
    asm("cvt.rna.tf32.f32 %0, %1;" : "=r"(u) : "f"(x));
    return u;
}
__device__ __forceinline__ float tf32r(float x) { return __uint_as_float(f2tf32(x)); }
__device__ __forceinline__ void mma16n8k8(float* c, const uint32_t* a, const uint32_t* b) {
    asm volatile(
        "mma.sync.aligned.m16n8k8.row.col.f32.tf32.tf32.f32 "
        "{%0,%1,%2,%3}, {%4,%5,%6,%7}, {%8,%9}, {%0,%1,%2,%3};"
        : "+f"(c[0]), "+f"(c[1]), "+f"(c[2]), "+f"(c[3])
        : "r"(a[0]), "r"(a[1]), "r"(a[2]), "r"(a[3]), "r"(b[0]), "r"(b[1]));
}
__device__ __forceinline__ void ldsm4(uint32_t* r, uint32_t addr) {
    asm volatile("ldmatrix.sync.aligned.m8n8.x4.shared.b16 {%0,%1,%2,%3}, [%4];"
        : "=r"(r[0]), "=r"(r[1]), "=r"(r[2]), "=r"(r[3]) : "r"(addr));
}
__device__ __forceinline__ void cpasync16(uint32_t dst, const void* src, unsigned sz) {
    asm volatile("cp.async.cg.shared.global [%0], [%1], 16, %2;"
        :: "r"(dst), "l"(src), "r"(sz));
}
__device__ __forceinline__ void cpcommit() { asm volatile("cp.async.commit_group;"); }
__device__ __forceinline__ void cpwait0()  { asm volatile("cp.async.wait_group 0;"); }
__device__ __forceinline__ void cpwait1()  { asm volatile("cp.async.wait_group 1;"); }

// ---------------- reductions ----------------
__device__ __forceinline__ float blockReduceSum(float v, float* sh) {
    __syncthreads();
    int lane = threadIdx.x & 31, w = threadIdx.x >> 5;
    #pragma unroll
    for (int o = 16; o > 0; o >>= 1) v += __shfl_xor_sync(0xffffffffu, v, o);
    if (lane == 0) sh[w] = v;
    __syncthreads();
    int nw = (blockDim.x + 31) >> 5;
    if (w == 0) {
        v = (lane < nw) ? sh[lane] : 0.f;
        #pragma unroll
        for (int o = 16; o > 0; o >>= 1) v += __shfl_xor_sync(0xffffffffu, v, o);
        if (lane == 0) sh[0] = v;
    }
    __syncthreads();
    return sh[0];
}
__device__ __forceinline__ float blockReduceMax(float v, float* sh) {
    __syncthreads();
    int lane = threadIdx.x & 31, w = threadIdx.x >> 5;
    #pragma unroll
    for (int o = 16; o > 0; o >>= 1) v = fmaxf(v, __shfl_xor_sync(0xffffffffu, v, o));
    if (lane == 0) sh[w] = v;
    __syncthreads();
    int nw = (blockDim.x + 31) >> 5;
    if (w == 0) {
        v = (lane < nw) ? sh[lane] : -1e30f;
        #pragma unroll
        for (int o = 16; o > 0; o >>= 1) v = fmaxf(v, __shfl_xor_sync(0xffffffffu, v, o));
        if (lane == 0) sh[0] = v;
    }
    __syncthreads();
    return sh[0];
}

// ---------------- W prep: round to tf32 AND transpose to [N][K] ------------
__global__ void transpose_round_kernel(const float* __restrict__ in, float* __restrict__ out,
                                       int K, int N) {
    __shared__ float tile[32][33];
    int k0 = blockIdx.y * 32, n0 = blockIdx.x * 32;
    int tx = threadIdx.x, ty = threadIdx.y;   // (32, 8)
    #pragma unroll
    for (int i = 0; i < 32; i += 8)
        tile[ty + i][tx] = in[(size_t)(k0 + ty + i) * N + n0 + tx];
    __syncthreads();
    #pragma unroll
    for (int i = 0; i < 32; i += 8)
        out[(size_t)(n0 + ty + i) * K + k0 + tx] = tf32r(tile[tx][ty + i]);
}

// ---------------- K1: LN1 + router score ----------------
__global__ void ln1_router_kernel(const float* __restrict__ x, const float* __restrict__ g1,
                                  const float* __restrict__ b1, const float* __restrict__ Wr,
                                  const float* __restrict__ br) {
    int tok = blockIdx.x;
    int t = threadIdx.x;   // 256
    const float* xr = x + (size_t)tok * D_;
    __shared__ float sh[32];
    float v[3]; float s = 0.f, sq = 0.f;
    #pragma unroll
    for (int i = 0; i < 3; i++) { float u = xr[t + 256*i]; v[i] = u; s += u; sq += u*u; }
    s  = blockReduceSum(s,  sh);
    sq = blockReduceSum(sq, sh);
    float mean = s * (1.f/D_);
    float var  = sq * (1.f/D_) - mean*mean;
    float rstd = rsqrtf(var + 1e-5f);
    float dot = 0.f;
    #pragma unroll
    for (int i = 0; i < 3; i++) {
        int d = t + 256*i;
        float nv = (v[i] - mean) * rstd * g1[d] + b1[d];
        g_normed [(size_t)tok*D_ + d] = nv;
        g_normedr[(size_t)tok*D_ + d] = tf32r(nv);
        dot += nv * Wr[d];
    }
    dot = blockReduceSum(dot, sh);
    if (t == 0) g_scores[tok] = 1.f / (1.f + expf(-(dot + br[0])));
}

// ---------------- K2: exact top-k via bitonic sort ----------
__global__ void topk_kernel() {
    int b = blockIdx.x, t = threadIdx.x;   // 1024 threads
    __shared__ unsigned long long keys[L_];
    __shared__ float sh[32];
    float s0 = g_scores[b*L_ + t];
    float s1 = g_scores[b*L_ + t + 1024];
    keys[t]        = ((unsigned long long)__float_as_uint(s0) << 32) | (unsigned)t;
    keys[t + 1024] = ((unsigned long long)__float_as_uint(s1) << 32) | (unsigned)(t + 1024);
    g_selpos[b*L_ + t] = -1;
    g_selpos[b*L_ + t + 1024] = -1;
    float tot = blockReduceSum(s0 + s1, sh);
    if (t == 0) g_ssum[b] = tot + 1e-6f;
    for (unsigned k = 2; k <= (unsigned)L_; k <<= 1) {
        for (unsigned j = k >> 1; j > 0; j >>= 1) {
            __syncthreads();
            for (unsigned i = t; i < (unsigned)L_; i += 1024) {
                unsigned ixj = i ^ j;
                if (ixj > i) {
                    unsigned long long a = keys[i], c = keys[ixj];
                    bool up = ((i & k) == 0);
                    if ((a > c) == up) { keys[i] = c; keys[ixj] = a; }
                }
            }
        }
    }
    __syncthreads();
    if (t < KS_) {
        int tok = (int)(unsigned)(keys[t] & 0xffffffffULL);
        g_selidx[b*KS_ + t] = b*L_ + tok;
        g_selpos[b*L_ + tok] = b*KS_ + t;
    }
}

// ---------------- K3: coherence-weighted pooling ----------------
__global__ void pooled_part_kernel() {
    int b = blockIdx.y, ch = blockIdx.x;
    int d = threadIdx.x;
    float acc = 0.f;
    int l0 = ch * (L_/16);
    for (int l = l0; l < l0 + L_/16; l++)
        acc += g_scores[b*L_ + l] * g_normed[((size_t)(b*L_ + l))*D_ + d];
    g_ppart[(b*16 + ch)*D_ + d] = acc;
}
__global__ void pooled_fin_kernel() {
    int b = blockIdx.x; int d = threadIdx.x;
    float acc = 0.f;
    #pragma unroll
    for (int c = 0; c < 16; c++) acc += g_ppart[(b*16 + c)*D_ + d];
    g_pooled[b*D_ + d] = acc / g_ssum[b];
}
__global__ void pooledwm_kernel(const float* __restrict__ Wm) {
    int b = blockIdx.y;
    int n = blockIdx.x*256 + threadIdx.x;
    float acc = 0.f;
    for (int d = 0; d < D_; d++) acc += g_pooled[b*D_ + d] * Wm[d*D_ + n];
    g_pooledWm[b*D_ + n] = acc;
}

// ---------------- GEMM v4: tf32 mma, both operands via ldmatrix ------------
// C[M,N] = act( A[M,K] @ Bt[N,K]^T + bias[N] ) (+ Rm[M,N])
// Bt is PRE-TRANSPOSED [N][K] row-major, tf32-rounded. A tf32-rounded.
// 256 threads = 8 warps. Block tile BM x 128. 3-stage cp.async pipeline.
// BM=256: warps 4M x 2N (warp 64x64);  BM=128: warps 2M x 4N (warp 64x32).
template<int BM, int ACT, bool GATHER, bool RESID, bool ROUND_OUT>
__global__ __launch_bounds__(256)
void gemm_tc(const float* __restrict__ A, const int* __restrict__ gidx,
             const float* __restrict__ Bt, const float* __restrict__ bias,
             const float* __restrict__ Rm, float* __restrict__ C,
             int M, int N, int K) {
    constexpr int WM  = (BM == 256) ? 4 : 2;   // warps along M
    constexpr int NT  = (BM == 256) ? 8 : 4;   // n8-tiles per warp
    constexpr int APT = BM / 64;               // A cp.async per thread
    constexpr int ABY = BM * 20 * 4;           // A stage bytes
    constexpr int BBY = 128 * 20 * 4;          // B stage bytes
    __shared__ __align__(128) float As[3][BM][20];
    __shared__ __align__(128) float Bs[3][128][20];
    const int tid = threadIdx.x, lane = tid & 31, wid = tid >> 5;
    const int wm = wid % WM, wn = wid / WM;
    const int g = lane >> 2, t = lane & 3;
    const int m0 = blockIdx.y * BM, n0 = blockIdx.x * 128;

    uint32_t sA = smem_u32(&As[0][0][0]);
    uint32_t sB = smem_u32(&Bs[0][0][0]);

    // loader setup: each thread copies APT A-rows' 16B chunk + 2 B-rows' 16B chunk
    const float* asrc[APT]; unsigned asz[APT]; uint32_t a_dst[APT];
    #pragma unroll
    for (int j = 0; j < APT; j++) {
        int rl = j*64 + (tid >> 2);
        int r = m0 + rl;
        bool v = r < M;
        int gr = v ? (GATHER ? gidx[r] : r) : 0;
        asrc[j]  = A + (size_t)gr*K + (tid & 3)*4;
        asz[j]   = v ? 16u : 0u;
        a_dst[j] = sA + (uint32_t)(rl*20 + (tid & 3)*4) * 4;
    }
    const float* bsrc[2]; uint32_t b_dst[2];
    #pragma unroll
    for (int j = 0; j < 2; j++) {
        int rl = j*64 + (tid >> 2);
        bsrc[j]  = Bt + (size_t)(n0 + rl)*K + (tid & 3)*4;
        b_dst[j] = sB + (uint32_t)(rl*20 + (tid & 3)*4) * 4;
    }

    // ldmatrix addressing (validated layouts from R4: A = gemm A path, B = logits K path)
    uint32_t a_ld = sA + (uint32_t)((wm*64 + (lane & 7) + ((lane >> 3) & 1)*8)*20
                                    + ((lane >> 4) & 1)*4) * 4;
    uint32_t b_ld = sB + (uint32_t)((wn*(NT*8) + (lane & 7) + ((lane >> 4) & 1)*8)*20
                                    + ((lane >> 3) & 1)*4) * 4;

    float acc[4][NT][4] = {};
    const int ntiles = K >> 4;

    auto issue = [&](int stage, int k0) {
        #pragma unroll
        for (int j = 0; j < APT; j++) cpasync16(a_dst[j] + stage*ABY, asrc[j] + k0, asz[j]);
        #pragma unroll
        for (int j = 0; j < 2; j++)  cpasync16(b_dst[j] + stage*BBY, bsrc[j] + k0, 16u);
        cpcommit();
    };

    issue(0, 0);
    if (ntiles > 1) issue(1, 16);
    for (int it = 0; it < ntiles; it++) {
        int st = it % 3;
        if (it == ntiles - 1) cpwait0(); else cpwait1();
        __syncthreads();
        if (it + 2 < ntiles) issue((it + 2) % 3, (it + 2) << 4);
        #pragma unroll
        for (int kk = 0; kk < 16; kk += 8) {
            uint32_t a[4][4];
            #pragma unroll
            for (int mt = 0; mt < 4; mt++)
                ldsm4(a[mt], a_ld + st*ABY + mt*1280 + kk*4);
            uint32_t bb[NT/2][4];
            #pragma unroll
            for (int np = 0; np < NT/2; np++)
                ldsm4(bb[np], b_ld + st*BBY + np*1280 + kk*4);
            #pragma unroll
            for (int mt = 0; mt < 4; mt++)
                #pragma unroll
                for (int nt = 0; nt < NT; nt++) {
                    uint32_t bf[2] = { bb[nt >> 1][(nt & 1)*2], bb[nt >> 1][(nt & 1)*2 + 1] };
                    mma16n8k8(acc[mt][nt], a[mt], bf);
                }
        }
    }

    // ---- epilogue ----
    #pragma unroll
    for (int mt = 0; mt < 4; mt++) {
        #pragma unroll
        for (int nt = 0; nt < NT; nt++) {
            int n = n0 + wn*(NT*8) + nt*8 + t*2;
            float bi0 = bias[n], bi1 = bias[n + 1];
            #pragma unroll
            for (int half = 0; half < 2; half++) {
                int m = m0 + wm*64 + mt*16 + g + half*8;
                if (m < M) {
                    float v0 = acc[mt][nt][half*2 + 0] + bi0;
                    float v1 = acc[mt][nt][half*2 + 1] + bi1;
                    if (ACT == 1) {
                        v0 = 0.5f * v0 * (1.f + erff(v0 * 0.70710678118654752f));
                        v1 = 0.5f * v1 * (1.f + erff(v1 * 0.70710678118654752f));
                    }
                    size_t off = (size_t)m * N + n;
                    if (RESID) { v0 += Rm[off]; v1 += Rm[off + 1]; }
                    if (ROUND_OUT) { v0 = tf32r(v0); v1 = tf32r(v1); }
                    float2 o; o.x = v0; o.y = v1;
                    *(float2*)&C[off] = o;
                }
            }
        }
    }
}

// ---------------- logits: Q @ K^T via mma (both operands LDSM) --------------
__global__ __launch_bounds__(128) void logits_tc() {
    int bh = blockIdx.z; int b = bh / H_, h = bh % H_;
    int i0 = blockIdx.y * 64, j0 = blockIdx.x * 64;
    __shared__ __align__(128) float Qs[64][68];
    __shared__ __align__(128) float Ks[64][68];
    const int tid = threadIdx.x, lane = tid & 31, wid = tid >> 5;
    const int wm = wid & 1, wn = wid >> 1;
    const int g = lane >> 2, t = lane & 3;

    #pragma unroll
    for (int q = 0; q < 8; q++) {
        int idx = q*128 + tid;
        int r = idx >> 4, c4 = (idx & 15) * 4;
        int i = i0 + r;
        float4 v = make_float4(0.f, 0.f, 0.f, 0.f);
        if (i < KS_) v = *(const float4*)&g_qsel[((size_t)(b*KS_ + i))*D_ + h*DH_ + c4];
        Qs[r][c4+0] = tf32r(v.x); Qs[r][c4+1] = tf32r(v.y);
        Qs[r][c4+2] = tf32r(v.z); Qs[r][c4+3] = tf32r(v.w);
        float4 w = *(const float4*)&g_kf[((size_t)(b*L_ + j0 + r))*D_ + h*DH_ + c4];
        Ks[r][c4+0] = tf32r(w.x); Ks[r][c4+1] = tf32r(w.y);
        Ks[r][c4+2] = tf32r(w.z); Ks[r][c4+3] = tf32r(w.w);
    }
    __syncthreads();

    uint32_t sQ = smem_u32(&Qs[0][0]);
    uint32_t sK = smem_u32(&Ks[0][0]);
    int a_row = wm*32 + (lane & 7) + ((lane >> 3) & 1) * 8;
    int a_kc  = ((lane >> 4) & 1) * 4;
    uint32_t a_ld = sQ + (uint32_t)(a_row*68 + a_kc) * 4;
    int b_row = wn*32 + (lane & 7) + ((lane >> 4) & 1) * 8;
    int b_kc  = ((lane >> 3) & 1) * 4;
    uint32_t b_ld = sK + (uint32_t)(b_row*68 + b_kc) * 4;

    float acc[2][4][4] = {};
    #pragma unroll
    for (int kk = 0; kk < 64; kk += 8) {
        uint32_t a[2][4], bb[2][4];
        #pragma unroll
        for (int mt = 0; mt < 2; mt++) ldsm4(a[mt], a_ld + mt*(16*68*4) + kk*4);
        #pragma unroll
        for (int nb = 0; nb < 2; nb++) ldsm4(bb[nb], b_ld + nb*(16*68*4) + kk*4);
        #pragma unroll
        for (int mt = 0; mt < 2; mt++)
            #pragma unroll
            for (int nt = 0; nt < 4; nt++) {
                uint32_t bf[2] = { bb[nt>>1][(nt&1)*2], bb[nt>>1][(nt&1)*2 + 1] };
                mma16n8k8(acc[mt][nt], a[mt], bf);
            }
    }

    const float scale = 0.125f;
    #pragma unroll
    for (int mt = 0; mt < 2; mt++) {
        #pragma unroll
        for (int nt = 0; nt < 4; nt++) {
            int j = j0 + wn*32 + nt*8 + t*2;
            #pragma unroll
            for (int half = 0; half < 2; half++) {
                int i = i0 + wm*32 + mt*16 + g + half*8;
                if (i < KS_) {
                    float* p = &g_logits[((size_t)bh*KS_ + i)*L_ + j];
                    p[0] = acc[mt][nt][half*2 + 0] * scale;
                    p[1] = acc[mt][nt][half*2 + 1] * scale;
                }
            }
        }
    }
}

// ---------------- softmax over keys ----------------
__global__ void softmax_kernel() {
    size_t row = blockIdx.x;
    float* p = g_logits + row * (size_t)L_;
    int t = threadIdx.x;   // 256
    __shared__ float sh[32];
    float v[8]; float mx = -1e30f;
    #pragma unroll
    for (int i = 0; i < 8; i++) { v[i] = p[t + 256*i]; mx = fmaxf(mx, v[i]); }
    mx = blockReduceMax(mx, sh);
    float s = 0.f;
    #pragma unroll
    for (int i = 0; i < 8; i++) { v[i] = expf(v[i] - mx); s += v[i]; }
    s = blockReduceSum(s, sh);
    float inv = 1.f / s;
    #pragma unroll
    for (int i = 0; i < 8; i++) p[t + 256*i] = v[i] * inv;
}

// ---------------- ctx = probs @ V via mma ----------------
__global__ __launch_bounds__(128) void ctx_tc() {
    int bh = blockIdx.y; int b = bh / H_, h = bh % H_;
    int i0 = blockIdx.x * 64;
    __shared__ __align__(128) float Ps[64][36];
    __shared__ __align__(128) float Vs[32][72];
    const int tid = threadIdx.x, lane = tid & 31, wid = tid >> 5;
    const int wm = wid & 1, wn = wid >> 1;
    const int g = lane >> 2, t = lane & 3;

    uint32_t sP = smem_u32(&Ps[0][0]);
    int a_row = wm*32 + (lane & 7) + ((lane >> 3) & 1) * 8;
    int a_kc  = ((lane >> 4) & 1) * 4;
    uint32_t a_ld = sP + (uint32_t)(a_row*36 + a_kc) * 4;

    float acc[2][4][4] = {};
    for (int l0 = 0; l0 < L_; l0 += 32) {
        #pragma unroll
        for (int q = 0; q < 4; q++) {
            int idx = q*128 + tid;
            int r = idx >> 3, c4 = (idx & 7) * 4;
            int i = i0 + r;
            float4 v = make_float4(0.f, 0.f, 0.f, 0.f);
            if (i < KS_) v = *(const float4*)&g_logits[((size_t)bh*KS_ + i)*L_ + l0 + c4];
            Ps[r][c4+0] = tf32r(v.x); Ps[r][c4+1] = tf32r(v.y);
            Ps[r][c4+2] = tf32r(v.z); Ps[r][c4+3] = tf32r(v.w);
        }
        #pragma unroll
        for (int q = 0; q < 4; q++) {
            int idx = q*128 + tid;
            int r = idx >> 4, c4 = (idx & 15) * 4;
            float4 w = *(const float4*)&g_vf[((size_t)(b*L_ + l0 + r))*D_ + h*DH_ + c4];
            Vs[r][c4+0] = tf32r(w.x); Vs[r][c4+1] = tf32r(w.y);
            Vs[r][c4+2] = tf32r(w.z); Vs[r][c4+3] = tf32r(w.w);
        }
        __syncthreads();
        #pragma unroll
        for (int kk = 0; kk < 32; kk += 8) {
            uint32_t a[2][4];
            #pragma unroll
            for (int mt = 0; mt < 2; mt++) ldsm4(a[mt], a_ld + mt*(16*36*4) + kk*4);
            uint32_t bv[4][2];
            #pragma unroll
            for (int nt = 0; nt < 4; nt++) {
                int nb = wn*32 + nt*8 + g;
                bv[nt][0] = __float_as_uint(Vs[kk + t][nb]);
                bv[nt][1] = __float_as_uint(Vs[kk + t + 4][nb]);
            }
            #pragma unroll
            for (int mt = 0; mt < 2; mt++)
                #pragma unroll
                for (int nt = 0; nt < 4; nt++)
                    mma16n8k8(acc[mt][nt], a[mt], bv[nt]);
        }
        __syncthreads();
    }

    #pragma unroll
    for (int mt = 0; mt < 2; mt++) {
        #pragma unroll
        for (int nt = 0; nt < 4; nt++) {
            int n = wn*32 + nt*8 + t*2;
            #pragma unroll
            for (int half = 0; half < 2; half++) {
                int i = i0 + wm*32 + mt*16 + g + half*8;
                if (i < KS_) {
                    float* p = &g_ctx[((size_t)(b*KS_ + i))*D_ + h*DH_ + n];
                    p[0] = tf32r(acc[mt][nt][half*2 + 0]);
                    p[1] = tf32r(acc[mt][nt][half*2 + 1]);
                }
            }
        }
    }
}

// ---------------- merge paths + residual + LN2 ----------------
__global__ void merge_ln2_kernel(const float* __restrict__ x, const float* __restrict__ g2,
                                 const float* __restrict__ b2) {
    int tok = blockIdx.x;
    int b = tok >> 11;
    int t = threadIdx.x;
    int pos = g_selpos[tok];
    float sc = g_scores[tok];
    __shared__ float sh[32];
    float hv[3]; float s = 0.f, sq = 0.f;
    #pragma unroll
    for (int i = 0; i < 3; i++) {
        int d = t + 256*i;
        float mg;
        if (pos >= 0) mg = g_attno[(size_t)pos*D_ + d];
        else          mg = g_mixb[(size_t)tok*D_ + d] + sc * g_pooledWm[b*D_ + d];
        float u = x[(size_t)tok*D_ + d] + mg;
        hv[i] = u;
        g_h[(size_t)tok*D_ + d] = u;
        s += u; sq += u*u;
    }
    s  = blockReduceSum(s,  sh);
    sq = blockReduceSum(sq, sh);
    float mean = s * (1.f/D_);
    float rstd = rsqrtf(sq*(1.f/D_) - mean*mean + 1e-5f);
    #pragma unroll
    for (int i = 0; i < 3; i++) {
        int d = t + 256*i;
        g_n2[(size_t)tok*D_ + d] = tf32r((hv[i] - mean) * rstd * g2[d] + b2[d]);
    }
}

// ---------------- host launch ----------------
extern "C" void kernel_launch(void* const* d_in, const int* in_sizes, int n_in,
                              void* d_out, int out_size) {
    (void)in_sizes; (void)n_in; (void)out_size;
    const float* x   = (const float*)d_in[0];
    const float* g1  = (const float*)d_in[1];
    const float* b1  = (const float*)d_in[2];
    const float* g2  = (const float*)d_in[3];
    const float* b2  = (const float*)d_in[4];
    const float* Wr  = (const float*)d_in[5];
    const float* br  = (const float*)d_in[6];
    const float* Wq  = (const float*)d_in[7];
    const float* bq  = (const float*)d_in[8];
    const float* Wk  = (const float*)d_in[9];
    const float* bk  = (const float*)d_in[10];
    const float* Wv  = (const float*)d_in[11];
    const float* bv  = (const float*)d_in[12];
    const float* Wo  = (const float*)d_in[13];
    const float* bo  = (const float*)d_in[14];
    const float* Wm  = (const float*)d_in[15];
    const float* bm  = (const float*)d_in[16];
    const float* W1  = (const float*)d_in[17];
    const float* bf1 = (const float*)d_in[18];
    const float* W2  = (const float*)d_in[19];
    const float* bf2 = (const float*)d_in[20];
    float* out = (float*)d_out;

    float *p_normedr, *p_kf, *p_vf, *p_mixb, *p_qsel, *p_ctx, *p_attno, *p_h, *p_n2, *p_t;
    float *p_wbuf;
    int* p_selidx;
    cudaGetSymbolAddress((void**)&p_normedr, g_normedr);
    cudaGetSymbolAddress((void**)&p_kf,     g_kf);
    cudaGetSymbolAddress((void**)&p_vf,     g_vf);
    cudaGetSymbolAddress((void**)&p_mixb,   g_mixb);
    cudaGetSymbolAddress((void**)&p_qsel,   g_qsel);
    cudaGetSymbolAddress((void**)&p_ctx,    g_ctx);
    cudaGetSymbolAddress((void**)&p_attno,  g_attno);
    cudaGetSymbolAddress((void**)&p_h,      g_h);
    cudaGetSymbolAddress((void**)&p_n2,     g_n2);
    cudaGetSymbolAddress((void**)&p_t,      g_t);
    cudaGetSymbolAddress((void**)&p_wbuf,   g_wbuf);
    cudaGetSymbolAddress((void**)&p_selidx, g_selidx);

    float* rWq = p_wbuf + 0*(size_t)WSZ_;
    float* rWk = p_wbuf + 1*(size_t)WSZ_;
    float* rWv = p_wbuf + 2*(size_t)WSZ_;
    float* rWo = p_wbuf + 3*(size_t)WSZ_;
    float* rWm = p_wbuf + 4*(size_t)WSZ_;
    float* rW1 = p_wbuf + 5*(size_t)WSZ_;
    float* rW2 = rW1 + (size_t)W1SZ_;

    // 0. round + transpose weights to tf32 [N][K]
    dim3 tb(32, 8);
    transpose_round_kernel<<<dim3(D_/32, D_/32), tb>>>(Wq, rWq, D_, D_);
    transpose_round_kernel<<<dim3(D_/32, D_/32), tb>>>(Wk, rWk, D_, D_);
    transpose_round_kernel<<<dim3(D_/32, D_/32), tb>>>(Wv, rWv, D_, D_);
    transpose_round_kernel<<<dim3(D_/32, D_/32), tb>>>(Wo, rWo, D_, D_);
    transpose_round_kernel<<<dim3(D_/32, D_/32), tb>>>(Wm, rWm, D_, D_);
    transpose_round_kernel<<<dim3(F_/32, D_/32), tb>>>(W1, rW1, D_, F_);
    transpose_round_kernel<<<dim3(D_/32, F_/32), tb>>>(W2, rW2, F_, D_);
    // 1. LN1 + router
    ln1_router_kernel<<<BL_, 256>>>(x, g1, b1, Wr, br);
    // 2. top-k
    topk_kernel<<<B_, 1024>>>();
    // 3. pooling path (exact fp32)
    pooled_part_kernel<<<dim3(16, B_), D_>>>();
    pooled_fin_kernel<<<B_, D_>>>();
    pooledwm_kernel<<<dim3(3, B_), 256>>>(Wm);
    // 4. dense projections K, V, mixbase (BM=256)
    gemm_tc<256,0,false,false,false><<<dim3(D_/128, BL_/256), 256>>>(p_normedr, nullptr, rWk, bk, nullptr, p_kf,   BL_,  D_, D_);
    gemm_tc<256,0,false,false,false><<<dim3(D_/128, BL_/256), 256>>>(p_normedr, nullptr, rWv, bv, nullptr, p_vf,   BL_,  D_, D_);
    gemm_tc<256,0,false,false,false><<<dim3(D_/128, BL_/256), 256>>>(p_normedr, nullptr, rWm, bm, nullptr, p_mixb, BL_,  D_, D_);
    // 5. Q for selected rows (BM=128, gather)
    gemm_tc<128,0,true ,false,false><<<dim3(D_/128, (MSEL_+127)/128), 256>>>(p_normedr, p_selidx, rWq, bq, nullptr, p_qsel, MSEL_, D_, D_);
    // 6. attention
    logits_tc<<<dim3(L_/64, (KS_+63)/64, B_*H_), 128>>>();
    softmax_kernel<<<B_*H_*KS_, 256>>>();
    ctx_tc<<<dim3((KS_+63)/64, B_*H_), 128>>>();
    gemm_tc<128,0,false,false,false><<<dim3(D_/128, (MSEL_+127)/128), 256>>>(p_ctx, nullptr, rWo, bo, nullptr, p_attno, MSEL_, D_, D_);
    // 7. merge + residual + LN2
    merge_ln2_kernel<<<BL_, 256>>>(x, g2, b2);
    // 8. FFN
    gemm_tc<256,1,false,false,true ><<<dim3(F_/128, BL_/256), 256>>>(p_n2, nullptr, rW1, bf1, nullptr, p_t, BL_, F_, D_);
    gemm_tc<256,0,false,true ,false><<<dim3(D_/128, BL_/256), 256>>>(p_t,  nullptr, rW2, bf2, p_h,    out, BL_, D_, F_);
}

// round 6
// speedup vs baseline: 1.2204x; 1.2204x over previous
#include <cuda_runtime.h>
#include <math.h>
#include <stdint.h>

// Problem constants
#define B_    4
#define L_    2048
#define D_    768
#define H_    12
#define DH_   64
#define F_    3072
#define KS_   307              // round(0.15 * 2048)
#define BL_   (B_*L_)          // 8192
#define MSEL_ (B_*KS_)         // 1228

#define WSZ_  589824           // 768*768
#define W1SZ_ 2359296          // 768*3072

// ---------------- scratch (static device globals; allocation-free) ----------
__device__ float g_normed [BL_*(size_t)D_];   // exact fp32 (router/pool path)
__device__ float g_normedr[BL_*(size_t)D_];   // tf32-rounded (GEMM A path)
__device__ float g_scores[BL_];
__device__ float g_ssum[B_];
__device__ int   g_selidx[MSEL_];
__device__ int   g_selpos[BL_];
__device__ float g_ppart[B_*16*D_];
__device__ float g_pooled[B_*D_];
__device__ float g_pooledWm[B_*D_];
__device__ float g_kf[BL_*(size_t)D_];
__device__ float g_vf[BL_*(size_t)D_];
__device__ float g_mixb[BL_*(size_t)D_];
__device__ float g_qsel[MSEL_*(size_t)D_];
__device__ float g_logits[(size_t)B_*H_*KS_*L_];
__device__ float g_ctx[MSEL_*(size_t)D_];
__device__ float g_attno[MSEL_*(size_t)D_];
__device__ float g_h[BL_*(size_t)D_];
__device__ float g_n2[BL_*(size_t)D_];
__device__ float g_t[BL_*(size_t)F_];
__device__ float g_wbuf[5*(size_t)WSZ_ + 2*(size_t)W1SZ_];  // rounded+transposed weights

// ---------------- small helpers ----------------
__device__ __forceinline__ uint32_t smem_u32(const void* p) {
    uint32_t a;
    asm("{ .reg .u64 t; cvta.to.shared.u64 t, %1; cvt.u32.u64 %0, t; }"
        : "=r"(a) : "l"(p));
    return a;
}
__device__ __forceinline__ uint32_t f2tf32(float x) {
    uint32_t u;
    asm("cvt.rna.tf32.f32 %0, %1;" : "=r"(u) : "f"(x));
    return u;
}
__device__ __forceinline__ float tf32r(float x) { return __uint_as_float(f2tf32(x)); }
__device__ __forceinline__ void mma16n8k8(float* c, const uint32_t* a, const uint32_t* b) {
    asm volatile(
        "mma.sync.aligned.m16n8k8.row.col.f32.tf32.tf32.f32 "
        "{%0,%1,%2,%3}, {%4,%5,%6,%7}, {%8,%9}, {%0,%1,%2,%3};"
        : "+f"(c[0]), "+f"(c[1]), "+f"(c[2]), "+f"(c[3])
        : "r"(a[0]), "r"(a[1]), "r"(a[2]), "r"(a[3]), "r"(b[0]), "r"(b[1]));
}
__device__ __forceinline__ void ldsm4(uint32_t* r, uint32_t addr) {
    asm volatile("ldmatrix.sync.aligned.m8n8.x4.shared.b16 {%0,%1,%2,%3}, [%4];"
        : "=r"(r[0]), "=r"(r[1]), "=r"(r[2]), "=r"(r[3]) : "r"(addr));
}
__device__ __forceinline__ void cpasync16(uint32_t dst, const void* src, unsigned sz) {
    asm volatile("cp.async.cg.shared.global [%0], [%1], 16, %2;"
        :: "r"(dst), "l"(src), "r"(sz));
}
__device__ __forceinline__ void cpcommit() { asm volatile("cp.async.commit_group;"); }
__device__ __forceinline__ void cpwait0()  { asm volatile("cp.async.wait_group 0;"); }
__device__ __forceinline__ void cpwait1()  { asm volatile("cp.async.wait_group 1;"); }

// ---------------- reductions ----------------
__device__ __forceinline__ float blockReduceSum(float v, float* sh) {
    __syncthreads();
    int lane = threadIdx.x & 31, w = threadIdx.x >> 5;
    #pragma unroll
    for (int o = 16; o > 0; o >>= 1) v += __shfl_xor_sync(0xffffffffu, v, o);
    if (lane == 0) sh[w] = v;
    __syncthreads();
    int nw = (blockDim.x + 31) >> 5;
    if (w == 0) {
        v = (lane < nw) ? sh[lane] : 0.f;
        #pragma unroll
        for (int o = 16; o > 0; o >>= 1) v += __shfl_xor_sync(0xffffffffu, v, o);
        if (lane == 0) sh[0] = v;
    }
    __syncthreads();
    return sh[0];
}
__device__ __forceinline__ float blockReduceMax(float v, float* sh) {
    __syncthreads();
    int lane = threadIdx.x & 31, w = threadIdx.x >> 5;
    #pragma unroll
    for (int o = 16; o > 0; o >>= 1) v = fmaxf(v, __shfl_xor_sync(0xffffffffu, v, o));
    if (lane == 0) sh[w] = v;
    __syncthreads();
    int nw = (blockDim.x + 31) >> 5;
    if (w == 0) {
        v = (lane < nw) ? sh[lane] : -1e30f;
        #pragma unroll
        for (int o = 16; o > 0; o >>= 1) v = fmaxf(v, __shfl_xor_sync(0xffffffffu, v, o));
        if (lane == 0) sh[0] = v;
    }
    __syncthreads();
    return sh[0];
}

// ---------------- W prep: round to tf32 AND transpose to [N][K] ------------
__global__ void transpose_round_kernel(const float* __restrict__ in, float* __restrict__ out,
                                       int K, int N) {
    __shared__ float tile[32][33];
    int k0 = blockIdx.y * 32, n0 = blockIdx.x * 32;
    int tx = threadIdx.x, ty = threadIdx.y;   // (32, 8)
    #pragma unroll
    for (int i = 0; i < 32; i += 8)
        tile[ty + i][tx] = in[(size_t)(k0 + ty + i) * N + n0 + tx];
    __syncthreads();
    #pragma unroll
    for (int i = 0; i < 32; i += 8)
        out[(size_t)(n0 + ty + i) * K + k0 + tx] = tf32r(tile[tx][ty + i]);
}

// ---------------- K1: LN1 + router score ----------------
__global__ void ln1_router_kernel(const float* __restrict__ x, const float* __restrict__ g1,
                                  const float* __restrict__ b1, const float* __restrict__ Wr,
                                  const float* __restrict__ br) {
    int tok = blockIdx.x;
    int t = threadIdx.x;   // 256
    const float* xr = x + (size_t)tok * D_;
    __shared__ float sh[32];
    float v[3]; float s = 0.f, sq = 0.f;
    #pragma unroll
    for (int i = 0; i < 3; i++) { float u = xr[t + 256*i]; v[i] = u; s += u; sq += u*u; }
    s  = blockReduceSum(s,  sh);
    sq = blockReduceSum(sq, sh);
    float mean = s * (1.f/D_);
    float var  = sq * (1.f/D_) - mean*mean;
    float rstd = rsqrtf(var + 1e-5f);
    float dot = 0.f;
    #pragma unroll
    for (int i = 0; i < 3; i++) {
        int d = t + 256*i;
        float nv = (v[i] - mean) * rstd * g1[d] + b1[d];
        g_normed [(size_t)tok*D_ + d] = nv;
        g_normedr[(size_t)tok*D_ + d] = tf32r(nv);
        dot += nv * Wr[d];
    }
    dot = blockReduceSum(dot, sh);
    if (t == 0) g_scores[tok] = 1.f / (1.f + expf(-(dot + br[0])));
}

// ---------------- K2: exact top-k via bitonic sort ----------
__global__ void topk_kernel() {
    int b = blockIdx.x, t = threadIdx.x;   // 1024 threads
    __shared__ unsigned long long keys[L_];
    __shared__ float sh[32];
    float s0 = g_scores[b*L_ + t];
    float s1 = g_scores[b*L_ + t + 1024];
    keys[t]        = ((unsigned long long)__float_as_uint(s0) << 32) | (unsigned)t;
    keys[t + 1024] = ((unsigned long long)__float_as_uint(s1) << 32) | (unsigned)(t + 1024);
    g_selpos[b*L_ + t] = -1;
    g_selpos[b*L_ + t + 1024] = -1;
    float tot = blockReduceSum(s0 + s1, sh);
    if (t == 0) g_ssum[b] = tot + 1e-6f;
    for (unsigned k = 2; k <= (unsigned)L_; k <<= 1) {
        for (unsigned j = k >> 1; j > 0; j >>= 1) {
            __syncthreads();
            for (unsigned i = t; i < (unsigned)L_; i += 1024) {
                unsigned ixj = i ^ j;
                if (ixj > i) {
                    unsigned long long a = keys[i], c = keys[ixj];
                    bool up = ((i & k) == 0);
                    if ((a > c) == up) { keys[i] = c; keys[ixj] = a; }
                }
            }
        }
    }
    __syncthreads();
    if (t < KS_) {
        int tok = (int)(unsigned)(keys[t] & 0xffffffffULL);
        g_selidx[b*KS_ + t] = b*L_ + tok;
        g_selpos[b*L_ + tok] = b*KS_ + t;
    }
}

// ---------------- K3: coherence-weighted pooling ----------------
__global__ void pooled_part_kernel() {
    int b = blockIdx.y, ch = blockIdx.x;
    int d = threadIdx.x;
    float acc = 0.f;
    int l0 = ch * (L_/16);
    for (int l = l0; l < l0 + L_/16; l++)
        acc += g_scores[b*L_ + l] * g_normed[((size_t)(b*L_ + l))*D_ + d];
    g_ppart[(b*16 + ch)*D_ + d] = acc;
}
__global__ void pooled_fin_kernel() {
    int b = blockIdx.x; int d = threadIdx.x;
    float acc = 0.f;
    #pragma unroll
    for (int c = 0; c < 16; c++) acc += g_ppart[(b*16 + c)*D_ + d];
    g_pooled[b*D_ + d] = acc / g_ssum[b];
}
__global__ void pooledwm_kernel(const float* __restrict__ Wm) {
    int b = blockIdx.y;
    int n = blockIdx.x*256 + threadIdx.x;
    float acc = 0.f;
    for (int d = 0; d < D_; d++) acc += g_pooled[b*D_ + d] * Wm[d*D_ + n];
    g_pooledWm[b*D_ + n] = acc;
}

// ---------------- GEMM v6: R4 shape + ldmatrix-B + 3-stage ------------------
// C[M,N] = act( A[M,K] @ Bt[N,K]^T + bias[N] ) (+ Rm[M,N])
// Bt PRE-TRANSPOSED [N][K], tf32-rounded. A tf32-rounded.
// 128 threads = 4 warps (2M x 2N), warp tile 64x64, block 128x128, k-tile 16.
// Both operands loaded n/m-major [row][20] and fed to mma via ldmatrix.x4.
#define STG_ (128*20*4)   // bytes per smem stage (same for A and B)
template<int ACT, bool GATHER, bool RESID, bool ROUND_OUT>
__global__ __launch_bounds__(128)
void gemm_tc(const float* __restrict__ A, const int* __restrict__ gidx,
             const float* __restrict__ Bt, const float* __restrict__ bias,
             const float* __restrict__ Rm, float* __restrict__ C,
             int M, int N, int K) {
    __shared__ __align__(128) float As[3][128][20];
    __shared__ __align__(128) float Bs[3][128][20];
    const int tid = threadIdx.x, lane = tid & 31, wid = tid >> 5;
    const int wm = wid & 1, wn = wid >> 1;
    const int g = lane >> 2, t = lane & 3;
    const int m0 = blockIdx.y * 128, n0 = blockIdx.x * 128;

    uint32_t sA = smem_u32(&As[0][0][0]);
    uint32_t sB = smem_u32(&Bs[0][0][0]);

    // loaders: 128 rows x 4 chunks of 16B each for A and for B -> 4 per thread each
    const float* asrc[4]; unsigned asz[4]; uint32_t a_dst[4];
    const float* bsrc[4]; uint32_t b_dst[4];
    #pragma unroll
    for (int j = 0; j < 4; j++) {
        int rl = j*32 + (tid >> 2);
        int ck = (tid & 3) * 4;
        int r = m0 + rl;
        bool v = r < M;
        int gr = v ? (GATHER ? gidx[r] : r) : 0;
        asrc[j]  = A + (size_t)gr*K + ck;
        asz[j]   = v ? 16u : 0u;
        a_dst[j] = sA + (uint32_t)(rl*20 + ck) * 4;
        bsrc[j]  = Bt + (size_t)(n0 + rl)*K + ck;
        b_dst[j] = sB + (uint32_t)(rl*20 + ck) * 4;
    }

    // ldmatrix addressing (A row-major fragment; B col-major fragment, logits-K pattern)
    uint32_t a_ld = sA + (uint32_t)((wm*64 + (lane & 7) + ((lane >> 3) & 1)*8)*20
                                    + ((lane >> 4) & 1)*4) * 4;
    uint32_t b_ld = sB + (uint32_t)((wn*64 + (lane & 7) + ((lane >> 4) & 1)*8)*20
                                    + ((lane >> 3) & 1)*4) * 4;

    float acc[4][8][4] = {};
    const int ntiles = K >> 4;

    auto issue = [&](int stage, int k0) {
        #pragma unroll
        for (int j = 0; j < 4; j++) cpasync16(a_dst[j] + stage*STG_, asrc[j] + k0, asz[j]);
        #pragma unroll
        for (int j = 0; j < 4; j++) cpasync16(b_dst[j] + stage*STG_, bsrc[j] + k0, 16u);
        cpcommit();
    };

    issue(0, 0);
    if (ntiles > 1) issue(1, 16);
    for (int it = 0; it < ntiles; it++) {
        int st = it % 3;
        if (it == ntiles - 1) cpwait0(); else cpwait1();
        __syncthreads();
        if (it + 2 < ntiles) issue((it + 2) % 3, (it + 2) << 4);
        #pragma unroll
        for (int kk = 0; kk < 16; kk += 8) {
            uint32_t a[4][4], bb[4][4];
            #pragma unroll
            for (int mt = 0; mt < 4; mt++)
                ldsm4(a[mt], a_ld + st*STG_ + mt*1280 + kk*4);
            #pragma unroll
            for (int np = 0; np < 4; np++)
                ldsm4(bb[np], b_ld + st*STG_ + np*1280 + kk*4);
            #pragma unroll
            for (int mt = 0; mt < 4; mt++)
                #pragma unroll
                for (int nt = 0; nt < 8; nt++) {
                    uint32_t bf[2] = { bb[nt >> 1][(nt & 1)*2], bb[nt >> 1][(nt & 1)*2 + 1] };
                    mma16n8k8(acc[mt][nt], a[mt], bf);
                }
        }
        __syncthreads();
    }

    // ---- epilogue ----
    #pragma unroll
    for (int mt = 0; mt < 4; mt++) {
        #pragma unroll
        for (int nt = 0; nt < 8; nt++) {
            int n = n0 + wn*64 + nt*8 + t*2;
            float bi0 = bias[n], bi1 = bias[n + 1];
            #pragma unroll
            for (int half = 0; half < 2; half++) {
                int m = m0 + wm*64 + mt*16 + g + half*8;
                if (m < M) {
                    float v0 = acc[mt][nt][half*2 + 0] + bi0;
                    float v1 = acc[mt][nt][half*2 + 1] + bi1;
                    if (ACT == 1) {
                        v0 = 0.5f * v0 * (1.f + erff(v0 * 0.70710678118654752f));
                        v1 = 0.5f * v1 * (1.f + erff(v1 * 0.70710678118654752f));
                    }
                    size_t off = (size_t)m * N + n;
                    if (RESID) { v0 += Rm[off]; v1 += Rm[off + 1]; }
                    if (ROUND_OUT) { v0 = tf32r(v0); v1 = tf32r(v1); }
                    float2 o; o.x = v0; o.y = v1;
                    *(float2*)&C[off] = o;
                }
            }
        }
    }
}

// ---------------- logits: Q @ K^T via mma (both operands LDSM) --------------
__global__ __launch_bounds__(128) void logits_tc() {
    int bh = blockIdx.z; int b = bh / H_, h = bh % H_;
    int i0 = blockIdx.y * 64, j0 = blockIdx.x * 64;
    __shared__ __align__(128) float Qs[64][68];
    __shared__ __align__(128) float Ks[64][68];
    const int tid = threadIdx.x, lane = tid & 31, wid = tid >> 5;
    const int wm = wid & 1, wn = wid >> 1;
    const int g = lane >> 2, t = lane & 3;

    #pragma unroll
    for (int q = 0; q < 8; q++) {
        int idx = q*128 + tid;
        int r = idx >> 4, c4 = (idx & 15) * 4;
        int i = i0 + r;
        float4 v = make_float4(0.f, 0.f, 0.f, 0.f);
        if (i < KS_) v = *(const float4*)&g_qsel[((size_t)(b*KS_ + i))*D_ + h*DH_ + c4];
        Qs[r][c4+0] = tf32r(v.x); Qs[r][c4+1] = tf32r(v.y);
        Qs[r][c4+2] = tf32r(v.z); Qs[r][c4+3] = tf32r(v.w);
        float4 w = *(const float4*)&g_kf[((size_t)(b*L_ + j0 + r))*D_ + h*DH_ + c4];
        Ks[r][c4+0] = tf32r(w.x); Ks[r][c4+1] = tf32r(w.y);
        Ks[r][c4+2] = tf32r(w.z); Ks[r][c4+3] = tf32r(w.w);
    }
    __syncthreads();

    uint32_t sQ = smem_u32(&Qs[0][0]);
    uint32_t sK = smem_u32(&Ks[0][0]);
    int a_row = wm*32 + (lane & 7) + ((lane >> 3) & 1) * 8;
    int a_kc  = ((lane >> 4) & 1) * 4;
    uint32_t a_ld = sQ + (uint32_t)(a_row*68 + a_kc) * 4;
    int b_row = wn*32 + (lane & 7) + ((lane >> 4) & 1) * 8;
    int b_kc  = ((lane >> 3) & 1) * 4;
    uint32_t b_ld = sK + (uint32_t)(b_row*68 + b_kc) * 4;

    float acc[2][4][4] = {};
    #pragma unroll
    for (int kk = 0; kk < 64; kk += 8) {
        uint32_t a[2][4], bb[2][4];
        #pragma unroll
        for (int mt = 0; mt < 2; mt++) ldsm4(a[mt], a_ld + mt*(16*68*4) + kk*4);
        #pragma unroll
        for (int nb = 0; nb < 2; nb++) ldsm4(bb[nb], b_ld + nb*(16*68*4) + kk*4);
        #pragma unroll
        for (int mt = 0; mt < 2; mt++)
            #pragma unroll
            for (int nt = 0; nt < 4; nt++) {
                uint32_t bf[2] = { bb[nt>>1][(nt&1)*2], bb[nt>>1][(nt&1)*2 + 1] };
                mma16n8k8(acc[mt][nt], a[mt], bf);
            }
    }

    const float scale = 0.125f;
    #pragma unroll
    for (int mt = 0; mt < 2; mt++) {
        #pragma unroll
        for (int nt = 0; nt < 4; nt++) {
            int j = j0 + wn*32 + nt*8 + t*2;
            #pragma unroll
            for (int half = 0; half < 2; half++) {
                int i = i0 + wm*32 + mt*16 + g + half*8;
                if (i < KS_) {
                    float* p = &g_logits[((size_t)bh*KS_ + i)*L_ + j];
                    p[0] = acc[mt][nt][half*2 + 0] * scale;
                    p[1] = acc[mt][nt][half*2 + 1] * scale;
                }
            }
        }
    }
}

// ---------------- softmax over keys ----------------
__global__ void softmax_kernel() {
    size_t row = blockIdx.x;
    float* p = g_logits + row * (size_t)L_;
    int t = threadIdx.x;   // 256
    __shared__ float sh[32];
    float v[8]; float mx = -1e30f;
    #pragma unroll
    for (int i = 0; i < 8; i++) { v[i] = p[t + 256*i]; mx = fmaxf(mx, v[i]); }
    mx = blockReduceMax(mx, sh);
    float s = 0.f;
    #pragma unroll
    for (int i = 0; i < 8; i++) { v[i] = expf(v[i] - mx); s += v[i]; }
    s = blockReduceSum(s, sh);
    float inv = 1.f / s;
    #pragma unroll
    for (int i = 0; i < 8; i++) p[t + 256*i] = v[i] * inv;
}

// ---------------- ctx = probs @ V via mma ----------------
__global__ __launch_bounds__(128) void ctx_tc() {
    int bh = blockIdx.y; int b = bh / H_, h = bh % H_;
    int i0 = blockIdx.x * 64;
    __shared__ __align__(128) float Ps[64][36];
    __shared__ __align__(128) float Vs[32][72];
    const int tid = threadIdx.x, lane = tid & 31, wid = tid >> 5;
    const int wm = wid & 1, wn = wid >> 1;
    const int g = lane >> 2, t = lane & 3;

    uint32_t sP = smem_u32(&Ps[0][0]);
    int a_row = wm*32 + (lane & 7) + ((lane >> 3) & 1) * 8;
    int a_kc  = ((lane >> 4) & 1) * 4;
    uint32_t a_ld = sP + (uint32_t)(a_row*36 + a_kc) * 4;

    float acc[2][4][4] = {};
    for (int l0 = 0; l0 < L_; l0 += 32) {
        #pragma unroll
        for (int q = 0; q < 4; q++) {
            int idx = q*128 + tid;
            int r = idx >> 3, c4 = (idx & 7) * 4;
            int i = i0 + r;
            float4 v = make_float4(0.f, 0.f, 0.f, 0.f);
            if (i < KS_) v = *(const float4*)&g_logits[((size_t)bh*KS_ + i)*L_ + l0 + c4];
            Ps[r][c4+0] = tf32r(v.x); Ps[r][c4+1] = tf32r(v.y);
            Ps[r][c4+2] = tf32r(v.z); Ps[r][c4+3] = tf32r(v.w);
        }
        #pragma unroll
        for (int q = 0; q < 4; q++) {
            int idx = q*128 + tid;
            int r = idx >> 4, c4 = (idx & 15) * 4;
            float4 w = *(const float4*)&g_vf[((size_t)(b*L_ + l0 + r))*D_ + h*DH_ + c4];
            Vs[r][c4+0] = tf32r(w.x); Vs[r][c4+1] = tf32r(w.y);
            Vs[r][c4+2] = tf32r(w.z); Vs[r][c4+3] = tf32r(w.w);
        }
        __syncthreads();
        #pragma unroll
        for (int kk = 0; kk < 32; kk += 8) {
            uint32_t a[2][4];
            #pragma unroll
            for (int mt = 0; mt < 2; mt++) ldsm4(a[mt], a_ld + mt*(16*36*4) + kk*4);
            uint32_t bv[4][2];
            #pragma unroll
            for (int nt = 0; nt < 4; nt++) {
                int nb = wn*32 + nt*8 + g;
                bv[nt][0] = __float_as_uint(Vs[kk + t][nb]);
                bv[nt][1] = __float_as_uint(Vs[kk + t + 4][nb]);
            }
            #pragma unroll
            for (int mt = 0; mt < 2; mt++)
                #pragma unroll
                for (int nt = 0; nt < 4; nt++)
                    mma16n8k8(acc[mt][nt], a[mt], bv[nt]);
        }
        __syncthreads();
    }

    #pragma unroll
    for (int mt = 0; mt < 2; mt++) {
        #pragma unroll
        for (int nt = 0; nt < 4; nt++) {
            int n = wn*32 + nt*8 + t*2;
            #pragma unroll
            for (int half = 0; half < 2; half++) {
                int i = i0 + wm*32 + mt*16 + g + half*8;
                if (i < KS_) {
                    float* p = &g_ctx[((size_t)(b*KS_ + i))*D_ + h*DH_ + n];
                    p[0] = tf32r(acc[mt][nt][half*2 + 0]);
                    p[1] = tf32r(acc[mt][nt][half*2 + 1]);
                }
            }
        }
    }
}

// ---------------- merge paths + residual + LN2 ----------------
__global__ void merge_ln2_kernel(const float* __restrict__ x, const float* __restrict__ g2,
                                 const float* __restrict__ b2) {
    int tok = blockIdx.x;
    int b = tok >> 11;
    int t = threadIdx.x;
    int pos = g_selpos[tok];
    float sc = g_scores[tok];
    __shared__ float sh[32];
    float hv[3]; float s = 0.f, sq = 0.f;
    #pragma unroll
    for (int i = 0; i < 3; i++) {
        int d = t + 256*i;
        float mg;
        if (pos >= 0) mg = g_attno[(size_t)pos*D_ + d];
        else          mg = g_mixb[(size_t)tok*D_ + d] + sc * g_pooledWm[b*D_ + d];
        float u = x[(size_t)tok*D_ + d] + mg;
        hv[i] = u;
        g_h[(size_t)tok*D_ + d] = u;
        s += u; sq += u*u;
    }
    s  = blockReduceSum(s,  sh);
    sq = blockReduceSum(sq, sh);
    float mean = s * (1.f/D_);
    float rstd = rsqrtf(sq*(1.f/D_) - mean*mean + 1e-5f);
    #pragma unroll
    for (int i = 0; i < 3; i++) {
        int d = t + 256*i;
        g_n2[(size_t)tok*D_ + d] = tf32r((hv[i] - mean) * rstd * g2[d] + b2[d]);
    }
}

// ---------------- host launch ----------------
extern "C" void kernel_launch(void* const* d_in, const int* in_sizes, int n_in,
                              void* d_out, int out_size) {
    (void)in_sizes; (void)n_in; (void)out_size;
    const float* x   = (const float*)d_in[0];
    const float* g1  = (const float*)d_in[1];
    const float* b1  = (const float*)d_in[2];
    const float* g2  = (const float*)d_in[3];
    const float* b2  = (const float*)d_in[4];
    const float* Wr  = (const float*)d_in[5];
    const float* br  = (const float*)d_in[6];
    const float* Wq  = (const float*)d_in[7];
    const float* bq  = (const float*)d_in[8];
    const float* Wk  = (const float*)d_in[9];
    const float* bk  = (const float*)d_in[10];
    const float* Wv  = (const float*)d_in[11];
    const float* bv  = (const float*)d_in[12];
    const float* Wo  = (const float*)d_in[13];
    const float* bo  = (const float*)d_in[14];
    const float* Wm  = (const float*)d_in[15];
    const float* bm  = (const float*)d_in[16];
    const float* W1  = (const float*)d_in[17];
    const float* bf1 = (const float*)d_in[18];
    const float* W2  = (const float*)d_in[19];
    const float* bf2 = (const float*)d_in[20];
    float* out = (float*)d_out;

    float *p_normedr, *p_kf, *p_vf, *p_mixb, *p_qsel, *p_ctx, *p_attno, *p_h, *p_n2, *p_t;
    float *p_wbuf;
    int* p_selidx;
    cudaGetSymbolAddress((void**)&p_normedr, g_normedr);
    cudaGetSymbolAddress((void**)&p_kf,     g_kf);
    cudaGetSymbolAddress((void**)&p_vf,     g_vf);
    cudaGetSymbolAddress((void**)&p_mixb,   g_mixb);
    cudaGetSymbolAddress((void**)&p_qsel,   g_qsel);
    cudaGetSymbolAddress((void**)&p_ctx,    g_ctx);
    cudaGetSymbolAddress((void**)&p_attno,  g_attno);
    cudaGetSymbolAddress((void**)&p_h,      g_h);
    cudaGetSymbolAddress((void**)&p_n2,     g_n2);
    cudaGetSymbolAddress((void**)&p_t,      g_t);
    cudaGetSymbolAddress((void**)&p_wbuf,   g_wbuf);
    cudaGetSymbolAddress((void**)&p_selidx, g_selidx);

    float* rWq = p_wbuf + 0*(size_t)WSZ_;
    float* rWk = p_wbuf + 1*(size_t)WSZ_;
    float* rWv = p_wbuf + 2*(size_t)WSZ_;
    float* rWo = p_wbuf + 3*(size_t)WSZ_;
    float* rWm = p_wbuf + 4*(size_t)WSZ_;
    float* rW1 = p_wbuf + 5*(size_t)WSZ_;
    float* rW2 = rW1 + (size_t)W1SZ_;

    // 0. round + transpose weights to tf32 [N][K]
    dim3 tb(32, 8);
    transpose_round_kernel<<<dim3(D_/32, D_/32), tb>>>(Wq, rWq, D_, D_);
    transpose_round_kernel<<<dim3(D_/32, D_/32), tb>>>(Wk, rWk, D_, D_);
    transpose_round_kernel<<<dim3(D_/32, D_/32), tb>>>(Wv, rWv, D_, D_);
    transpose_round_kernel<<<dim3(D_/32, D_/32), tb>>>(Wo, rWo, D_, D_);
    transpose_round_kernel<<<dim3(D_/32, D_/32), tb>>>(Wm, rWm, D_, D_);
    transpose_round_kernel<<<dim3(F_/32, D_/32), tb>>>(W1, rW1, D_, F_);
    transpose_round_kernel<<<dim3(D_/32, F_/32), tb>>>(W2, rW2, F_, D_);
    // 1. LN1 + router
    ln1_router_kernel<<<BL_, 256>>>(x, g1, b1, Wr, br);
    // 2. top-k
    topk_kernel<<<B_, 1024>>>();
    // 3. pooling path (exact fp32)
    pooled_part_kernel<<<dim3(16, B_), D_>>>();
    pooled_fin_kernel<<<B_, D_>>>();
    pooledwm_kernel<<<dim3(3, B_), 256>>>(Wm);
    // 4. dense projections K, V, mixbase
    gemm_tc<0,false,false,false><<<dim3(D_/128, BL_/128), 128>>>(p_normedr, nullptr, rWk, bk, nullptr, p_kf,   BL_,  D_, D_);
    gemm_tc<0,false,false,false><<<dim3(D_/128, BL_/128), 128>>>(p_normedr, nullptr, rWv, bv, nullptr, p_vf,   BL_,  D_, D_);
    gemm_tc<0,false,false,false><<<dim3(D_/128, BL_/128), 128>>>(p_normedr, nullptr, rWm, bm, nullptr, p_mixb, BL_,  D_, D_);
    // 5. Q for selected rows (gather)
    gemm_tc<0,true ,false,false><<<dim3(D_/128, (MSEL_+127)/128), 128>>>(p_normedr, p_selidx, rWq, bq, nullptr, p_qsel, MSEL_, D_, D_);
    // 6. attention
    logits_tc<<<dim3(L_/64, (KS_+63)/64, B_*H_), 128>>>();
    softmax_kernel<<<B_*H_*KS_, 256>>>();
    ctx_tc<<<dim3((KS_+63)/64, B_*H_), 128>>>();
    gemm_tc<0,false,false,false><<<dim3(D_/128, (MSEL_+127)/128), 128>>>(p_ctx, nullptr, rWo, bo, nullptr, p_attno, MSEL_, D_, D_);
    // 7. merge + residual + LN2
    merge_ln2_kernel<<<BL_, 256>>>(x, g2, b2);
    // 8. FFN
    gemm_tc<1,false,false,true ><<<dim3(F_/128, BL_/128), 128>>>(p_n2, nullptr, rW1, bf1, nullptr, p_t, BL_, F_, D_);
    gemm_tc<0,false,true ,false><<<dim3(D_/128, BL_/128), 128>>>(p_t,  nullptr, rW2, bf2, p_h,    out, BL_, D_, F_);
}

// round 8
// speedup vs baseline: 1.4621x; 1.1980x over previous
#include <cuda_runtime.h>
#include <math.h>
#include <stdint.h>

// Problem constants
#define B_    4
#define L_    2048
#define D_    768
#define H_    12
#define DH_   64
#define F_    3072
#define KS_   307              // round(0.15 * 2048)
#define BL_   (B_*L_)          // 8192
#define MSEL_ (B_*KS_)         // 1228
#define NKVM_ 2304             // 3*D concat (K,V,M)
#define NSPL_ 4                // KV splits in flash attention
#define JSEG_ (L_/NSPL_)       // 512

#define WSZ_  589824           // 768*768
#define W1SZ_ 2359296          // 768*3072

// ---------------- scratch (static device globals; allocation-free) ----------
__device__ float g_normed [BL_*(size_t)D_];   // exact fp32 (router/pool path)
__device__ float g_normedr[BL_*(size_t)D_];   // tf32-rounded (GEMM A path)
__device__ float g_scores[BL_];
__device__ float g_ssum[B_];
__device__ int   g_selidx[MSEL_];
__device__ int   g_selpos[BL_];
__device__ float g_ppart[B_*16*D_];
__device__ float g_pooled[B_*D_];
__device__ float g_pooledWm[B_*D_];
__device__ float g_kvm[BL_*(size_t)NKVM_];    // [tok][ K(768) | V(768) | mixb(768) ]
__device__ float g_bkvm[NKVM_];
__device__ float g_qsel[MSEL_*(size_t)D_];
__device__ float g_po[(size_t)B_*H_*NSPL_*320*64];   // attention partial O
__device__ float g_pm[B_*H_*NSPL_*320];
__device__ float g_pl[B_*H_*NSPL_*320];
__device__ float g_ctx[MSEL_*(size_t)D_];
__device__ float g_attno[MSEL_*(size_t)D_];
__device__ float g_h[BL_*(size_t)D_];
__device__ float g_n2[BL_*(size_t)D_];
__device__ float g_t[BL_*(size_t)F_];
__device__ float g_wbuf[5*(size_t)WSZ_ + 2*(size_t)W1SZ_];  // rounded+transposed weights

// ---------------- small helpers ----------------
__device__ __forceinline__ uint32_t smem_u32(const void* p) {
    uint32_t a;
    asm("{ .reg .u64 t; cvta.to.shared.u64 t, %1; cvt.u32.u64 %0, t; }"
        : "=r"(a) : "l"(p));
    return a;
}
__device__ __forceinline__ uint32_t f2tf32(float x) {
    uint32_t u;
    asm("cvt.rna.tf32.f32 %0, %1;" : "=r"(u) : "f"(x));
    return u;
}
__device__ __forceinline__ float tf32r(float x) { return __uint_as_float(f2tf32(x)); }
__device__ __forceinline__ void mma16n8k8(float* c, const uint32_t* a, const uint32_t* b) {
    asm volatile(
        "mma.sync.aligned.m16n8k8.row.col.f32.tf32.tf32.f32 "
        "{%0,%1,%2,%3}, {%4,%5,%6,%7}, {%8,%9}, {%0,%1,%2,%3};"
        : "+f"(c[0]), "+f"(c[1]), "+f"(c[2]), "+f"(c[3])
        : "r"(a[0]), "r"(a[1]), "r"(a[2]), "r"(a[3]), "r"(b[0]), "r"(b[1]));
}
__device__ __forceinline__ void ldsm4(uint32_t* r, uint32_t addr) {
    asm volatile("ldmatrix.sync.aligned.m8n8.x4.shared.b16 {%0,%1,%2,%3}, [%4];"
        : "=r"(r[0]), "=r"(r[1]), "=r"(r[2]), "=r"(r[3]) : "r"(addr));
}
__device__ __forceinline__ void cpasync16(uint32_t dst, const void* src, unsigned sz) {
    asm volatile("cp.async.cg.shared.global [%0], [%1], 16, %2;"
        :: "r"(dst), "l"(src), "r"(sz));
}
__device__ __forceinline__ void cpcommit() { asm volatile("cp.async.commit_group;"); }
__device__ __forceinline__ void cpwait0()  { asm volatile("cp.async.wait_group 0;"); }
__device__ __forceinline__ void cpwait1()  { asm volatile("cp.async.wait_group 1;"); }

// ---------------- reductions ----------------
__device__ __forceinline__ float blockReduceSum(float v, float* sh) {
    __syncthreads();
    int lane = threadIdx.x & 31, w = threadIdx.x >> 5;
    #pragma unroll
    for (int o = 16; o > 0; o >>= 1) v += __shfl_xor_sync(0xffffffffu, v, o);
    if (lane == 0) sh[w] = v;
    __syncthreads();
    int nw = (blockDim.x + 31) >> 5;
    if (w == 0) {
        v = (lane < nw) ? sh[lane] : 0.f;
        #pragma unroll
        for (int o = 16; o > 0; o >>= 1) v += __shfl_xor_sync(0xffffffffu, v, o);
        if (lane == 0) sh[0] = v;
    }
    __syncthreads();
    return sh[0];
}
__device__ __forceinline__ float blockReduceMax(float v, float* sh) {
    __syncthreads();
    int lane = threadIdx.x & 31, w = threadIdx.x >> 5;
    #pragma unroll
    for (int o = 16; o > 0; o >>= 1) v = fmaxf(v, __shfl_xor_sync(0xffffffffu, v, o));
    if (lane == 0) sh[w] = v;
    __syncthreads();
    int nw = (blockDim.x + 31) >> 5;
    if (w == 0) {
        v = (lane < nw) ? sh[lane] : -1e30f;
        #pragma unroll
        for (int o = 16; o > 0; o >>= 1) v = fmaxf(v, __shfl_xor_sync(0xffffffffu, v, o));
        if (lane == 0) sh[0] = v;
    }
    __syncthreads();
    return sh[0];
}

// ---------------- W prep: round to tf32 AND transpose to [N][K] ------------
__global__ void transpose_round_kernel(const float* __restrict__ in, float* __restrict__ out,
                                       int K, int N) {
    __shared__ float tile[32][33];
    int k0 = blockIdx.y * 32, n0 = blockIdx.x * 32;
    int tx = threadIdx.x, ty = threadIdx.y;   // (32, 8)
    #pragma unroll
    for (int i = 0; i < 32; i += 8)
        tile[ty + i][tx] = in[(size_t)(k0 + ty + i) * N + n0 + tx];
    __syncthreads();
    #pragma unroll
    for (int i = 0; i < 32; i += 8)
        out[(size_t)(n0 + ty + i) * K + k0 + tx] = tf32r(tile[tx][ty + i]);
}

__global__ void bias_concat_kernel(const float* __restrict__ bk, const float* __restrict__ bv,
                                   const float* __restrict__ bm) {
    int d = blockIdx.x * 256 + threadIdx.x;   // 9 blocks * 256 = 2304
    float v = (d < 768) ? bk[d] : ((d < 1536) ? bv[d - 768] : bm[d - 1536]);
    g_bkvm[d] = v;
}

// ---------------- K1: LN1 + router score ----------------
__global__ void ln1_router_kernel(const float* __restrict__ x, const float* __restrict__ g1,
                                  const float* __restrict__ b1, const float* __restrict__ Wr,
                                  const float* __restrict__ br) {
    int tok = blockIdx.x;
    int t = threadIdx.x;   // 256
    const float* xr = x + (size_t)tok * D_;
    __shared__ float sh[32];
    float v[3]; float s = 0.f, sq = 0.f;
    #pragma unroll
    for (int i = 0; i < 3; i++) { float u = xr[t + 256*i]; v[i] = u; s += u; sq += u*u; }
    s  = blockReduceSum(s,  sh);
    sq = blockReduceSum(sq, sh);
    float mean = s * (1.f/D_);
    float var  = sq * (1.f/D_) - mean*mean;
    float rstd = rsqrtf(var + 1e-5f);
    float dot = 0.f;
    #pragma unroll
    for (int i = 0; i < 3; i++) {
        int d = t + 256*i;
        float nv = (v[i] - mean) * rstd * g1[d] + b1[d];
        g_normed [(size_t)tok*D_ + d] = nv;
        g_normedr[(size_t)tok*D_ + d] = tf32r(nv);
        dot += nv * Wr[d];
    }
    dot = blockReduceSum(dot, sh);
    if (t == 0) g_scores[tok] = 1.f / (1.f + expf(-(dot + br[0])));
}

// ---------------- K2: exact top-k via bitonic sort ----------
__global__ void topk_kernel() {
    int b = blockIdx.x, t = threadIdx.x;   // 1024 threads
    __shared__ unsigned long long keys[L_];
    __shared__ float sh[32];
    float s0 = g_scores[b*L_ + t];
    float s1 = g_scores[b*L_ + t + 1024];
    keys[t]        = ((unsigned long long)__float_as_uint(s0) << 32) | (unsigned)t;
    keys[t + 1024] = ((unsigned long long)__float_as_uint(s1) << 32) | (unsigned)(t + 1024);
    g_selpos[b*L_ + t] = -1;
    g_selpos[b*L_ + t + 1024] = -1;
    float tot = blockReduceSum(s0 + s1, sh);
    if (t == 0) g_ssum[b] = tot + 1e-6f;
    for (unsigned k = 2; k <= (unsigned)L_; k <<= 1) {
        for (unsigned j = k >> 1; j > 0; j >>= 1) {
            __syncthreads();
            for (unsigned i = t; i < (unsigned)L_; i += 1024) {
                unsigned ixj = i ^ j;
                if (ixj > i) {
                    unsigned long long a = keys[i], c = keys[ixj];
                    bool up = ((i & k) == 0);
                    if ((a > c) == up) { keys[i] = c; keys[ixj] = a; }
                }
            }
        }
    }
    __syncthreads();
    if (t < KS_) {
        int tok = (int)(unsigned)(keys[t] & 0xffffffffULL);
        g_selidx[b*KS_ + t] = b*L_ + tok;
        g_selpos[b*L_ + tok] = b*KS_ + t;
    }
}

// ---------------- K3: coherence-weighted pooling ----------------
__global__ void pooled_part_kernel() {
    int b = blockIdx.y, ch = blockIdx.x;
    int d = threadIdx.x;
    float acc = 0.f;
    int l0 = ch * (L_/16);
    for (int l = l0; l < l0 + L_/16; l++)
        acc += g_scores[b*L_ + l] * g_normed[((size_t)(b*L_ + l))*D_ + d];
    g_ppart[(b*16 + ch)*D_ + d] = acc;
}
__global__ void pooled_fin_kernel() {
    int b = blockIdx.x; int d = threadIdx.x;
    float acc = 0.f;
    #pragma unroll
    for (int c = 0; c < 16; c++) acc += g_ppart[(b*16 + c)*D_ + d];
    g_pooled[b*D_ + d] = acc / g_ssum[b];
}
__global__ void pooledwm_kernel(const float* __restrict__ Wm) {
    int b = blockIdx.y;
    int n = blockIdx.x*256 + threadIdx.x;
    float acc = 0.f;
    for (int d = 0; d < D_; d++) acc += g_pooled[b*D_ + d] * Wm[d*D_ + n];
    g_pooledWm[b*D_ + n] = acc;
}

// ---------------- GEMM (R6, validated): tf32 mma, dual ldmatrix, 3-stage ----
#define STG_ (128*20*4)
template<int ACT, bool GATHER, bool RESID, bool ROUND_OUT>
__global__ __launch_bounds__(128)
void gemm_tc(const float* __restrict__ A, const int* __restrict__ gidx,
             const float* __restrict__ Bt, const float* __restrict__ bias,
             const float* __restrict__ Rm, float* __restrict__ C,
             int M, int N, int K) {
    __shared__ __align__(128) float As[3][128][20];
    __shared__ __align__(128) float Bs[3][128][20];
    const int tid = threadIdx.x, lane = tid & 31, wid = tid >> 5;
    const int wm = wid & 1, wn = wid >> 1;
    const int g = lane >> 2, t = lane & 3;
    const int m0 = blockIdx.y * 128, n0 = blockIdx.x * 128;

    uint32_t sA = smem_u32(&As[0][0][0]);
    uint32_t sB = smem_u32(&Bs[0][0][0]);

    const float* asrc[4]; unsigned asz[4]; uint32_t a_dst[4];
    const float* bsrc[4]; uint32_t b_dst[4];
    #pragma unroll
    for (int j = 0; j < 4; j++) {
        int rl = j*32 + (tid >> 2);
        int ck = (tid & 3) * 4;
        int r = m0 + rl;
        bool v = r < M;
        int gr = v ? (GATHER ? gidx[r] : r) : 0;
        asrc[j]  = A + (size_t)gr*K + ck;
        asz[j]   = v ? 16u : 0u;
        a_dst[j] = sA + (uint32_t)(rl*20 + ck) * 4;
        bsrc[j]  = Bt + (size_t)(n0 + rl)*K + ck;
        b_dst[j] = sB + (uint32_t)(rl*20 + ck) * 4;
    }

    uint32_t a_ld = sA + (uint32_t)((wm*64 + (lane & 7) + ((lane >> 3) & 1)*8)*20
                                    + ((lane >> 4) & 1)*4) * 4;
    uint32_t b_ld = sB + (uint32_t)((wn*64 + (lane & 7) + ((lane >> 4) & 1)*8)*20
                                    + ((lane >> 3) & 1)*4) * 4;

    float acc[4][8][4] = {};
    const int ntiles = K >> 4;

    auto issue = [&](int stage, int k0) {
        #pragma unroll
        for (int j = 0; j < 4; j++) cpasync16(a_dst[j] + stage*STG_, asrc[j] + k0, asz[j]);
        #pragma unroll
        for (int j = 0; j < 4; j++) cpasync16(b_dst[j] + stage*STG_, bsrc[j] + k0, 16u);
        cpcommit();
    };

    issue(0, 0);
    if (ntiles > 1) issue(1, 16);
    for (int it = 0; it < ntiles; it++) {
        int st = it % 3;
        if (it == ntiles - 1) cpwait0(); else cpwait1();
        __syncthreads();
        if (it + 2 < ntiles) issue((it + 2) % 3, (it + 2) << 4);
        #pragma unroll
        for (int kk = 0; kk < 16; kk += 8) {
            uint32_t a[4][4], bb[4][4];
            #pragma unroll
            for (int mt = 0; mt < 4; mt++)
                ldsm4(a[mt], a_ld + st*STG_ + mt*1280 + kk*4);
            #pragma unroll
            for (int np = 0; np < 4; np++)
                ldsm4(bb[np], b_ld + st*STG_ + np*1280 + kk*4);
            #pragma unroll
            for (int mt = 0; mt < 4; mt++)
                #pragma unroll
                for (int nt = 0; nt < 8; nt++) {
                    uint32_t bf[2] = { bb[nt >> 1][(nt & 1)*2], bb[nt >> 1][(nt & 1)*2 + 1] };
                    mma16n8k8(acc[mt][nt], a[mt], bf);
                }
        }
        __syncthreads();
    }

    #pragma unroll
    for (int mt = 0; mt < 4; mt++) {
        #pragma unroll
        for (int nt = 0; nt < 8; nt++) {
            int n = n0 + wn*64 + nt*8 + t*2;
            float bi0 = bias[n], bi1 = bias[n + 1];
            #pragma unroll
            for (int half = 0; half < 2; half++) {
                int m = m0 + wm*64 + mt*16 + g + half*8;
                if (m < M) {
                    float v0 = acc[mt][nt][half*2 + 0] + bi0;
                    float v1 = acc[mt][nt][half*2 + 1] + bi1;
                    if (ACT == 1) {
                        v0 = 0.5f * v0 * (1.f + erff(v0 * 0.70710678118654752f));
                        v1 = 0.5f * v1 * (1.f + erff(v1 * 0.70710678118654752f));
                    }
                    size_t off = (size_t)m * N + n;
                    if (RESID) { v0 += Rm[off]; v1 += Rm[off + 1]; }
                    if (ROUND_OUT) { v0 = tf32r(v0); v1 = tf32r(v1); }
                    float2 o; o.x = v0; o.y = v1;
                    *(float2*)&C[off] = o;
                }
            }
        }
    }
}

// ---------------- flash attention, split-KV -------------------------------
// grid (5 i-tiles, 48 bh, NSPL_ splits), 128 threads = 4 warps.
// Warp w owns rows [w*16, w*16+16) of the 64-row i-tile.
// Per split: online softmax over JSEG_=512 keys in 32-key chunks.
__global__ __launch_bounds__(128) void flash_attn() {
    const int it = blockIdx.x, bh = blockIdx.y, sp = blockIdx.z;
    const int b = bh / H_, h = bh % H_;
    const int i0 = it * 64;
    __shared__ __align__(128) float Qs[64][68];
    __shared__ __align__(128) float Ks[32][68];
    __shared__ __align__(128) float Vs[32][68];
    __shared__ __align__(128) float Ps[4][16][40];
    const int tid = threadIdx.x, lane = tid & 31, w = tid >> 5;
    const int g = lane >> 2, t = lane & 3;

    // load Q tile once (tf32-rounded)
    #pragma unroll
    for (int q = 0; q < 8; q++) {
        int idx = q*128 + tid;
        int r = idx >> 4, c4 = (idx & 15) * 4;
        int i = i0 + r;
        float4 v = make_float4(0.f, 0.f, 0.f, 0.f);
        if (i < KS_) v = *(const float4*)&g_qsel[((size_t)(b*KS_ + i))*D_ + h*DH_ + c4];
        Qs[r][c4+0] = tf32r(v.x); Qs[r][c4+1] = tf32r(v.y);
        Qs[r][c4+2] = tf32r(v.z); Qs[r][c4+3] = tf32r(v.w);
    }

    const uint32_t a_ldQ = smem_u32(&Qs[0][0])
        + (uint32_t)((w*16 + (lane & 7) + ((lane >> 3) & 1)*8)*68 + ((lane >> 4) & 1)*4) * 4;
    const uint32_t b_ldK = smem_u32(&Ks[0][0])
        + (uint32_t)(((lane & 7) + ((lane >> 4) & 1)*8)*68 + ((lane >> 3) & 1)*4) * 4;
    const uint32_t a_ldP = smem_u32(&Ps[w][0][0])
        + (uint32_t)(((lane & 7) + ((lane >> 3) & 1)*8)*40 + ((lane >> 4) & 1)*4) * 4;

    float accO[8][4] = {};
    float m0r = -1e30f, m1r = -1e30f, l0r = 0.f, l1r = 0.f;
    __syncthreads();

    for (int j0 = sp * JSEG_; j0 < (sp + 1) * JSEG_; j0 += 32) {
        // load K,V chunk (32 x 64 each) from g_kvm, tf32-rounded
        #pragma unroll
        for (int q = 0; q < 4; q++) {
            int idx = q*128 + tid;
            int r = idx >> 4, c4 = (idx & 15) * 4;
            size_t base = ((size_t)(b*L_ + j0 + r))*NKVM_ + h*DH_ + c4;
            float4 kv = *(const float4*)&g_kvm[base];
            Ks[r][c4+0] = tf32r(kv.x); Ks[r][c4+1] = tf32r(kv.y);
            Ks[r][c4+2] = tf32r(kv.z); Ks[r][c4+3] = tf32r(kv.w);
            float4 vv = *(const float4*)&g_kvm[base + 768];
            Vs[r][c4+0] = tf32r(vv.x); Vs[r][c4+1] = tf32r(vv.y);
            Vs[r][c4+2] = tf32r(vv.z); Vs[r][c4+3] = tf32r(vv.w);
        }
        __syncthreads();

        // S = (Q K^T) * 0.125 ; warp m16 x 32 cols
        float sacc[4][4] = {};
        #pragma unroll
        for (int kk = 0; kk < 64; kk += 8) {
            uint32_t a[4], bb[2][4];
            ldsm4(a, a_ldQ + kk*4);
            ldsm4(bb[0], b_ldK + kk*4);
            ldsm4(bb[1], b_ldK + 16*68*4 + kk*4);
            #pragma unroll
            for (int nt = 0; nt < 4; nt++) {
                uint32_t bf[2] = { bb[nt >> 1][(nt & 1)*2], bb[nt >> 1][(nt & 1)*2 + 1] };
                mma16n8k8(sacc[nt], a, bf);
            }
        }
        float cm0 = -1e30f, cm1 = -1e30f;
        #pragma unroll
        for (int nt = 0; nt < 4; nt++) {
            sacc[nt][0] *= 0.125f; sacc[nt][1] *= 0.125f;
            sacc[nt][2] *= 0.125f; sacc[nt][3] *= 0.125f;
            cm0 = fmaxf(cm0, fmaxf(sacc[nt][0], sacc[nt][1]));
            cm1 = fmaxf(cm1, fmaxf(sacc[nt][2], sacc[nt][3]));
        }
        cm0 = fmaxf(cm0, __shfl_xor_sync(0xffffffffu, cm0, 1));
        cm0 = fmaxf(cm0, __shfl_xor_sync(0xffffffffu, cm0, 2));
        cm1 = fmaxf(cm1, __shfl_xor_sync(0xffffffffu, cm1, 1));
        cm1 = fmaxf(cm1, __shfl_xor_sync(0xffffffffu, cm1, 2));
        float mn0 = fmaxf(m0r, cm0), mn1 = fmaxf(m1r, cm1);
        float al0 = expf(m0r - mn0), al1 = expf(m1r - mn1);
        m0r = mn0; m1r = mn1;
        float s0 = 0.f, s1 = 0.f;
        #pragma unroll
        for (int nt = 0; nt < 4; nt++) {
            float p0 = expf(sacc[nt][0] - mn0);
            float p1 = expf(sacc[nt][1] - mn0);
            float p2 = expf(sacc[nt][2] - mn1);
            float p3 = expf(sacc[nt][3] - mn1);
            s0 += p0 + p1; s1 += p2 + p3;
            int c = nt*8 + t*2;
            Ps[w][g][c]     = tf32r(p0);
            Ps[w][g][c+1]   = tf32r(p1);
            Ps[w][g+8][c]   = tf32r(p2);
            Ps[w][g+8][c+1] = tf32r(p3);
        }
        s0 += __shfl_xor_sync(0xffffffffu, s0, 1);
        s0 += __shfl_xor_sync(0xffffffffu, s0, 2);
        s1 += __shfl_xor_sync(0xffffffffu, s1, 1);
        s1 += __shfl_xor_sync(0xffffffffu, s1, 2);
        l0r = l0r*al0 + s0; l1r = l1r*al1 + s1;
        #pragma unroll
        for (int nt = 0; nt < 8; nt++) {
            accO[nt][0] *= al0; accO[nt][1] *= al0;
            accO[nt][2] *= al1; accO[nt][3] *= al1;
        }
        __syncwarp();
        // O += P V
        #pragma unroll
        for (int kk = 0; kk < 32; kk += 8) {
            uint32_t a[4];
            ldsm4(a, a_ldP + kk*4);
            #pragma unroll
            for (int nt = 0; nt < 8; nt++) {
                int nb = nt*8 + g;
                uint32_t bv[2];
                bv[0] = __float_as_uint(Vs[kk + t][nb]);
                bv[1] = __float_as_uint(Vs[kk + t + 4][nb]);
                mma16n8k8(accO[nt], a, bv);
            }
        }
        __syncthreads();
    }

    // store partial O, m, l (un-normalized)
    const size_t slot0 = (size_t)(bh*NSPL_ + sp)*320 + it*64 + w*16 + g;
    const size_t slot1 = slot0 + 8;
    if (t == 0) {
        g_pm[slot0] = m0r; g_pl[slot0] = l0r;
        g_pm[slot1] = m1r; g_pl[slot1] = l1r;
    }
    #pragma unroll
    for (int nt = 0; nt < 8; nt++) {
        int c = nt*8 + t*2;
        g_po[slot0*64 + c]     = accO[nt][0];
        g_po[slot0*64 + c + 1] = accO[nt][1];
        g_po[slot1*64 + c]     = accO[nt][2];
        g_po[slot1*64 + c + 1] = accO[nt][3];
    }
}

// combine split-KV partials -> g_ctx (tf32-rounded)
__global__ __launch_bounds__(256) void attn_combine() {
    const int it = blockIdx.x, bh = blockIdx.y;
    const int b = bh / H_, h = bh % H_;
    __shared__ float ws[64][NSPL_];
    __shared__ float linv[64];
    const int tid = threadIdx.x;
    if (tid < 64) {
        size_t base = (size_t)(bh*NSPL_)*320 + it*64 + tid;
        float mv[NSPL_]; float m = -1e30f;
        #pragma unroll
        for (int s = 0; s < NSPL_; s++) { mv[s] = g_pm[base + (size_t)s*320]; m = fmaxf(m, mv[s]); }
        float l = 0.f;
        #pragma unroll
        for (int s = 0; s < NSPL_; s++) {
            float wv = expf(mv[s] - m);
            ws[tid][s] = wv;
            l += g_pl[base + (size_t)s*320] * wv;
        }
        linv[tid] = 1.f / l;
    }
    __syncthreads();
    #pragma unroll
    for (int q = 0; q < 16; q++) {
        int idx = q*256 + tid;
        int r = idx >> 6, c = idx & 63;
        int i = it*64 + r;
        if (i < KS_) {
            size_t slot = (size_t)(bh*NSPL_)*320 + it*64 + r;
            float acc = 0.f;
            #pragma unroll
            for (int s = 0; s < NSPL_; s++)
                acc += g_po[(slot + (size_t)s*320)*64 + c] * ws[r][s];
            g_ctx[((size_t)(b*KS_ + i))*D_ + h*DH_ + c] = tf32r(acc * linv[r]);
        }
    }
}

// ---------------- merge paths + residual + LN2 ----------------
__global__ void merge_ln2_kernel(const float* __restrict__ x, const float* __restrict__ g2,
                                 const float* __restrict__ b2) {
    int tok = blockIdx.x;
    int b = tok >> 11;
    int t = threadIdx.x;
    int pos = g_selpos[tok];
    float sc = g_scores[tok];
    __shared__ float sh[32];
    float hv[3]; float s = 0.f, sq = 0.f;
    #pragma unroll
    for (int i = 0; i < 3; i++) {
        int d = t + 256*i;
        float mg;
        if (pos >= 0) mg = g_attno[(size_t)pos*D_ + d];
        else          mg = g_kvm[(size_t)tok*NKVM_ + 1536 + d] + sc * g_pooledWm[b*D_ + d];
        float u = x[(size_t)tok*D_ + d] + mg;
        hv[i] = u;
        g_h[(size_t)tok*D_ + d] = u;
        s += u; sq += u*u;
    }
    s  = blockReduceSum(s,  sh);
    sq = blockReduceSum(sq, sh);
    float mean = s * (1.f/D_);
    float rstd = rsqrtf(sq*(1.f/D_) - mean*mean + 1e-5f);
    #pragma unroll
    for (int i = 0; i < 3; i++) {
        int d = t + 256*i;
        g_n2[(size_t)tok*D_ + d] = tf32r((hv[i] - mean) * rstd * g2[d] + b2[d]);
    }
}

// ---------------- host launch ----------------
extern "C" void kernel_launch(void* const* d_in, const int* in_sizes, int n_in,
                              void* d_out, int out_size) {
    (void)in_sizes; (void)n_in; (void)out_size;
    const float* x   = (const float*)d_in[0];
    const float* g1  = (const float*)d_in[1];
    const float* b1  = (const float*)d_in[2];
    const float* g2  = (const float*)d_in[3];
    const float* b2  = (const float*)d_in[4];
    const float* Wr  = (const float*)d_in[5];
    const float* br  = (const float*)d_in[6];
    const float* Wq  = (const float*)d_in[7];
    const float* bq  = (const float*)d_in[8];
    const float* Wk  = (const float*)d_in[9];
    const float* bk  = (const float*)d_in[10];
    const float* Wv  = (const float*)d_in[11];
    const float* bv  = (const float*)d_in[12];
    const float* Wo  = (const float*)d_in[13];
    const float* bo  = (const float*)d_in[14];
    const float* Wm  = (const float*)d_in[15];
    const float* bm  = (const float*)d_in[16];
    const float* W1  = (const float*)d_in[17];
    const float* bf1 = (const float*)d_in[18];
    const float* W2  = (const float*)d_in[19];
    const float* bf2 = (const float*)d_in[20];
    float* out = (float*)d_out;

    float *p_normedr, *p_kvm, *p_bkvm, *p_qsel, *p_ctx, *p_attno, *p_h, *p_n2, *p_t;
    float *p_wbuf;
    int* p_selidx;
    cudaGetSymbolAddress((void**)&p_normedr, g_normedr);
    cudaGetSymbolAddress((void**)&p_kvm,    g_kvm);
    cudaGetSymbolAddress((void**)&p_bkvm,   g_bkvm);
    cudaGetSymbolAddress((void**)&p_qsel,   g_qsel);
    cudaGetSymbolAddress((void**)&p_ctx,    g_ctx);
    cudaGetSymbolAddress((void**)&p_attno,  g_attno);
    cudaGetSymbolAddress((void**)&p_h,      g_h);
    cudaGetSymbolAddress((void**)&p_n2,     g_n2);
    cudaGetSymbolAddress((void**)&p_t,      g_t);
    cudaGetSymbolAddress((void**)&p_wbuf,   g_wbuf);
    cudaGetSymbolAddress((void**)&p_selidx, g_selidx);

    float* rKVM = p_wbuf;                          // [2304][768]: K rows, V rows, M rows
    float* rWq  = p_wbuf + 3*(size_t)WSZ_;
    float* rWo  = p_wbuf + 4*(size_t)WSZ_;
    float* rW1  = p_wbuf + 5*(size_t)WSZ_;
    float* rW2  = rW1 + (size_t)W1SZ_;

    // 0. round + transpose weights to tf32 [N][K]; K/V/M concatenated along N
    dim3 tb(32, 8);
    transpose_round_kernel<<<dim3(D_/32, D_/32), tb>>>(Wk, rKVM + 0*(size_t)WSZ_, D_, D_);
    transpose_round_kernel<<<dim3(D_/32, D_/32), tb>>>(Wv, rKVM + 1*(size_t)WSZ_, D_, D_);
    transpose_round_kernel<<<dim3(D_/32, D_/32), tb>>>(Wm, rKVM + 2*(size_t)WSZ_, D_, D_);
    transpose_round_kernel<<<dim3(D_/32, D_/32), tb>>>(Wq, rWq, D_, D_);
    transpose_round_kernel<<<dim3(D_/32, D_/32), tb>>>(Wo, rWo, D_, D_);
    transpose_round_kernel<<<dim3(F_/32, D_/32), tb>>>(W1, rW1, D_, F_);
    transpose_round_kernel<<<dim3(D_/32, F_/32), tb>>>(W2, rW2, F_, D_);
    bias_concat_kernel<<<9, 256>>>(bk, bv, bm);
    // 1. LN1 + router
    ln1_router_kernel<<<BL_, 256>>>(x, g1, b1, Wr, br);
    // 2. top-k
    topk_kernel<<<B_, 1024>>>();
    // 3. pooling path (exact fp32)
    pooled_part_kernel<<<dim3(16, B_), D_>>>();
    pooled_fin_kernel<<<B_, D_>>>();
    pooledwm_kernel<<<dim3(3, B_), 256>>>(Wm);
    // 4. fused K|V|mix projection (N=2304)
    gemm_tc<0,false,false,false><<<dim3(NKVM_/128, BL_/128), 128>>>(p_normedr, nullptr, rKVM, p_bkvm, nullptr, p_kvm, BL_, NKVM_, D_);
    // 5. Q for selected rows (gather)
    gemm_tc<0,true ,false,false><<<dim3(D_/128, (MSEL_+127)/128), 128>>>(p_normedr, p_selidx, rWq, bq, nullptr, p_qsel, MSEL_, D_, D_);
    // 6. flash attention (split-KV) + combine
    flash_attn<<<dim3(5, B_*H_, NSPL_), 128>>>();
    attn_combine<<<dim3(5, B_*H_), 256>>>();
    gemm_tc<0,false,false,false><<<dim3(D_/128, (MSEL_+127)/128), 128>>>(p_ctx, nullptr, rWo, bo, nullptr, p_attno, MSEL_, D_, D_);
    // 7. merge + residual + LN2
    merge_ln2_kernel<<<BL_, 256>>>(x, g2, b2);
    // 8. FFN
    gemm_tc<1,false,false,true ><<<dim3(F_/128, BL_/128), 128>>>(p_n2, nullptr, rW1, bf1, nullptr, p_t, BL_, F_, D_);
    gemm_tc<0,false,true ,false><<<dim3(D_/128, BL_/128), 128>>>(p_t,  nullptr, rW2, bf2, p_h,    out, BL_, D_, F_);
}

// round 9
// speedup vs baseline: 2.1976x; 1.5030x over previous
#include <cuda_runtime.h>
#include <cuda_fp16.h>
#include <math.h>
#include <stdint.h>

// Problem constants
#define B_    4
#define L_    2048
#define D_    768
#define H_    12
#define DH_   64
#define F_    3072
#define KS_   307              // round(0.15 * 2048)
#define BL_   (B_*L_)          // 8192
#define MSEL_ (B_*KS_)         // 1228
#define NKVM_ 2304             // 3*D concat (K,V,M)
#define NSPL_ 4                // KV splits in flash attention
#define JSEG_ (L_/NSPL_)       // 512

#define WSZ_  589824           // 768*768
#define W1SZ_ 2359296          // 768*3072

// ---------------- scratch (static device globals; allocation-free) ----------
__device__ float g_normed[BL_*(size_t)D_];    // exact fp32 (router/pool path)
__device__ __align__(16) __half g_nh[BL_*(size_t)D_];   // fp16 (GEMM A path)
__device__ float g_scores[BL_];
__device__ float g_ssum[B_];
__device__ int   g_selidx[MSEL_];
__device__ int   g_selpos[BL_];
__device__ float g_ppart[B_*16*D_];
__device__ float g_pooled[B_*D_];
__device__ float g_pooledWm[B_*D_];
__device__ float g_kvm[BL_*(size_t)NKVM_];    // [tok][ K(768) | V(768) | mixb(768) ]
__device__ float g_bkvm[NKVM_];
__device__ float g_qsel[MSEL_*(size_t)D_];
__device__ float g_po[(size_t)B_*H_*NSPL_*320*64];   // attention partial O
__device__ float g_pm[B_*H_*NSPL_*320];
__device__ float g_pl[B_*H_*NSPL_*320];
__device__ __align__(16) __half g_ctxh[MSEL_*(size_t)D_];
__device__ float g_attno[MSEL_*(size_t)D_];
__device__ float g_h[BL_*(size_t)D_];
__device__ __align__(16) __half g_n2h[BL_*(size_t)D_];
__device__ __align__(16) __half g_th[BL_*(size_t)F_];
__device__ __align__(16) __half g_whuf[5*(size_t)WSZ_ + 2*(size_t)W1SZ_];  // fp16 [N][K] weights

// ---------------- small helpers ----------------
__device__ __forceinline__ uint32_t smem_u32(const void* p) {
    uint32_t a;
    asm("{ .reg .u64 t; cvta.to.shared.u64 t, %1; cvt.u32.u64 %0, t; }"
        : "=r"(a) : "l"(p));
    return a;
}
__device__ __forceinline__ uint32_t f2tf32(float x) {
    uint32_t u;
    asm("cvt.rna.tf32.f32 %0, %1;" : "=r"(u) : "f"(x));
    return u;
}
__device__ __forceinline__ float tf32r(float x) { return __uint_as_float(f2tf32(x)); }
__device__ __forceinline__ void mma16n8k8(float* c, const uint32_t* a, const uint32_t* b) {
    asm volatile(
        "mma.sync.aligned.m16n8k8.row.col.f32.tf32.tf32.f32 "
        "{%0,%1,%2,%3}, {%4,%5,%6,%7}, {%8,%9}, {%0,%1,%2,%3};"
        : "+f"(c[0]), "+f"(c[1]), "+f"(c[2]), "+f"(c[3])
        : "r"(a[0]), "r"(a[1]), "r"(a[2]), "r"(a[3]), "r"(b[0]), "r"(b[1]));
}
__device__ __forceinline__ void mma16n8k16h(float* c, const uint32_t* a, const uint32_t* b) {
    asm volatile(
        "mma.sync.aligned.m16n8k16.row.col.f32.f16.f16.f32 "
        "{%0,%1,%2,%3}, {%4,%5,%6,%7}, {%8,%9}, {%0,%1,%2,%3};"
        : "+f"(c[0]), "+f"(c[1]), "+f"(c[2]), "+f"(c[3])
        : "r"(a[0]), "r"(a[1]), "r"(a[2]), "r"(a[3]), "r"(b[0]), "r"(b[1]));
}
__device__ __forceinline__ void ldsm4(uint32_t* r, uint32_t addr) {
    asm volatile("ldmatrix.sync.aligned.m8n8.x4.shared.b16 {%0,%1,%2,%3}, [%4];"
        : "=r"(r[0]), "=r"(r[1]), "=r"(r[2]), "=r"(r[3]) : "r"(addr));
}
__device__ __forceinline__ void cpasync16(uint32_t dst, const void* src, unsigned sz) {
    asm volatile("cp.async.cg.shared.global [%0], [%1], 16, %2;"
        :: "r"(dst), "l"(src), "r"(sz));
}
__device__ __forceinline__ void cpcommit() { asm volatile("cp.async.commit_group;"); }
__device__ __forceinline__ void cpwait0()  { asm volatile("cp.async.wait_group 0;"); }
__device__ __forceinline__ void cpwait1()  { asm volatile("cp.async.wait_group 1;"); }

// ---------------- reductions ----------------
__device__ __forceinline__ float blockReduceSum(float v, float* sh) {
    __syncthreads();
    int lane = threadIdx.x & 31, w = threadIdx.x >> 5;
    #pragma unroll
    for (int o = 16; o > 0; o >>= 1) v += __shfl_xor_sync(0xffffffffu, v, o);
    if (lane == 0) sh[w] = v;
    __syncthreads();
    int nw = (blockDim.x + 31) >> 5;
    if (w == 0) {
        v = (lane < nw) ? sh[lane] : 0.f;
        #pragma unroll
        for (int o = 16; o > 0; o >>= 1) v += __shfl_xor_sync(0xffffffffu, v, o);
        if (lane == 0) sh[0] = v;
    }
    __syncthreads();
    return sh[0];
}
__device__ __forceinline__ float blockReduceMax(float v, float* sh) {
    __syncthreads();
    int lane = threadIdx.x & 31, w = threadIdx.x >> 5;
    #pragma unroll
    for (int o = 16; o > 0; o >>= 1) v = fmaxf(v, __shfl_xor_sync(0xffffffffu, v, o));
    if (lane == 0) sh[w] = v;
    __syncthreads();
    int nw = (blockDim.x + 31) >> 5;
    if (w == 0) {
        v = (lane < nw) ? sh[lane] : -1e30f;
        #pragma unroll
        for (int o = 16; o > 0; o >>= 1) v = fmaxf(v, __shfl_xor_sync(0xffffffffu, v, o));
        if (lane == 0) sh[0] = v;
    }
    __syncthreads();
    return sh[0];
}

// ---------------- W prep: transpose to [N][K] + fp16 -----------------------
__global__ void transpose_half_kernel(const float* __restrict__ in, __half* __restrict__ out,
                                      int K, int N) {
    __shared__ float tile[32][33];
    int k0 = blockIdx.y * 32, n0 = blockIdx.x * 32;
    int tx = threadIdx.x, ty = threadIdx.y;   // (32, 8)
    #pragma unroll
    for (int i = 0; i < 32; i += 8)
        tile[ty + i][tx] = in[(size_t)(k0 + ty + i) * N + n0 + tx];
    __syncthreads();
    #pragma unroll
    for (int i = 0; i < 32; i += 8)
        out[(size_t)(n0 + ty + i) * K + k0 + tx] = __float2half_rn(tile[tx][ty + i]);
}

__global__ void bias_concat_kernel(const float* __restrict__ bk, const float* __restrict__ bv,
                                   const float* __restrict__ bm) {
    int d = blockIdx.x * 256 + threadIdx.x;   // 9 blocks * 256 = 2304
    float v = (d < 768) ? bk[d] : ((d < 1536) ? bv[d - 768] : bm[d - 1536]);
    g_bkvm[d] = v;
}

// ---------------- K1: LN1 + router score ----------------
__global__ void ln1_router_kernel(const float* __restrict__ x, const float* __restrict__ g1,
                                  const float* __restrict__ b1, const float* __restrict__ Wr,
                                  const float* __restrict__ br) {
    int tok = blockIdx.x;
    int t = threadIdx.x;   // 256
    const float* xr = x + (size_t)tok * D_;
    __shared__ float sh[32];
    float v[3]; float s = 0.f, sq = 0.f;
    #pragma unroll
    for (int i = 0; i < 3; i++) { float u = xr[t + 256*i]; v[i] = u; s += u; sq += u*u; }
    s  = blockReduceSum(s,  sh);
    sq = blockReduceSum(sq, sh);
    float mean = s * (1.f/D_);
    float var  = sq * (1.f/D_) - mean*mean;
    float rstd = rsqrtf(var + 1e-5f);
    float dot = 0.f;
    #pragma unroll
    for (int i = 0; i < 3; i++) {
        int d = t + 256*i;
        float nv = (v[i] - mean) * rstd * g1[d] + b1[d];
        g_normed[(size_t)tok*D_ + d] = nv;
        g_nh[(size_t)tok*D_ + d] = __float2half_rn(nv);
        dot += nv * Wr[d];
    }
    dot = blockReduceSum(dot, sh);
    if (t == 0) g_scores[tok] = 1.f / (1.f + expf(-(dot + br[0])));
}

// ---------------- K2: exact top-k via bitonic sort ----------
__global__ void topk_kernel() {
    int b = blockIdx.x, t = threadIdx.x;   // 1024 threads
    __shared__ unsigned long long keys[L_];
    __shared__ float sh[32];
    float s0 = g_scores[b*L_ + t];
    float s1 = g_scores[b*L_ + t + 1024];
    keys[t]        = ((unsigned long long)__float_as_uint(s0) << 32) | (unsigned)t;
    keys[t + 1024] = ((unsigned long long)__float_as_uint(s1) << 32) | (unsigned)(t + 1024);
    g_selpos[b*L_ + t] = -1;
    g_selpos[b*L_ + t + 1024] = -1;
    float tot = blockReduceSum(s0 + s1, sh);
    if (t == 0) g_ssum[b] = tot + 1e-6f;
    for (unsigned k = 2; k <= (unsigned)L_; k <<= 1) {
        for (unsigned j = k >> 1; j > 0; j >>= 1) {
            __syncthreads();
            for (unsigned i = t; i < (unsigned)L_; i += 1024) {
                unsigned ixj = i ^ j;
                if (ixj > i) {
                    unsigned long long a = keys[i], c = keys[ixj];
                    bool up = ((i & k) == 0);
                    if ((a > c) == up) { keys[i] = c; keys[ixj] = a; }
                }
            }
        }
    }
    __syncthreads();
    if (t < KS_) {
        int tok = (int)(unsigned)(keys[t] & 0xffffffffULL);
        g_selidx[b*KS_ + t] = b*L_ + tok;
        g_selpos[b*L_ + tok] = b*KS_ + t;
    }
}

// ---------------- K3: coherence-weighted pooling ----------------
__global__ void pooled_part_kernel() {
    int b = blockIdx.y, ch = blockIdx.x;
    int d = threadIdx.x;
    float acc = 0.f;
    int l0 = ch * (L_/16);
    for (int l = l0; l < l0 + L_/16; l++)
        acc += g_scores[b*L_ + l] * g_normed[((size_t)(b*L_ + l))*D_ + d];
    g_ppart[(b*16 + ch)*D_ + d] = acc;
}
__global__ void pooled_fin_kernel() {
    int b = blockIdx.x; int d = threadIdx.x;
    float acc = 0.f;
    #pragma unroll
    for (int c = 0; c < 16; c++) acc += g_ppart[(b*16 + c)*D_ + d];
    g_pooled[b*D_ + d] = acc / g_ssum[b];
}
__global__ void pooledwm_kernel(const float* __restrict__ Wm) {
    int b = blockIdx.y;
    int n = blockIdx.x*256 + threadIdx.x;
    float acc = 0.f;
    for (int d = 0; d < D_; d++) acc += g_pooled[b*D_ + d] * Wm[d*D_ + n];
    g_pooledWm[b*D_ + n] = acc;
}

// ---------------- fp16 GEMM: mma m16n8k16, dual ldmatrix, 3-stage ----------
// C[M,N] = epi( A[M,K] @ Bt[N,K]^T + bias[N] )
// OUT: 0 = f32 C; 1 = GELU -> fp16 Ch; 2 = + Rm -> f32 C.
// 128 thr = 4 warps (2M x 2N), warp 64x64, block 128x128, k-tile 32 halves.
#define RS_  40                   // smem row stride in halves (80 B)
#define HSTG_ (128*RS_*2)         // bytes per stage per operand = 10240
template<int OUT, bool GATHER>
__global__ __launch_bounds__(128)
void gemm_h(const __half* __restrict__ A, const int* __restrict__ gidx,
            const __half* __restrict__ Bt, const float* __restrict__ bias,
            const float* __restrict__ Rm, float* __restrict__ C,
            __half* __restrict__ Ch, int M, int N, int K) {
    __shared__ __align__(128) __half As[3][128][RS_];
    __shared__ __align__(128) __half Bs[3][128][RS_];
    const int tid = threadIdx.x, lane = tid & 31, wid = tid >> 5;
    const int wm = wid & 1, wn = wid >> 1;
    const int g = lane >> 2, t = lane & 3;
    const int m0 = blockIdx.y * 128, n0 = blockIdx.x * 128;

    uint32_t sA = smem_u32(&As[0][0][0]);
    uint32_t sB = smem_u32(&Bs[0][0][0]);

    // loaders: 128 rows x 4 chunks of 16B (8 halves) each operand -> 4/thread
    const __half* asrc[4]; unsigned asz[4]; uint32_t a_dst[4];
    const __half* bsrc[4]; uint32_t b_dst[4];
    #pragma unroll
    for (int j = 0; j < 4; j++) {
        int rl = j*32 + (tid >> 2);
        int ck = (tid & 3) * 8;            // halves within 32-half k-tile
        int r = m0 + rl;
        bool v = r < M;
        int gr = v ? (GATHER ? gidx[r] : r) : 0;
        asrc[j]  = A + (size_t)gr*K + ck;
        asz[j]   = v ? 16u : 0u;
        a_dst[j] = sA + (uint32_t)(rl*RS_ + ck) * 2;
        bsrc[j]  = Bt + (size_t)(n0 + rl)*K + ck;
        b_dst[j] = sB + (uint32_t)(rl*RS_ + ck) * 2;
    }

    // ldmatrix addressing (m16n8k16): same quadrant pattern as validated R6 paths
    uint32_t a_ld = sA + (uint32_t)((wm*64 + (lane & 7) + ((lane >> 3) & 1)*8)*RS_
                                    + ((lane >> 4) & 1)*8) * 2;
    uint32_t b_ld = sB + (uint32_t)((wn*64 + (lane & 7) + ((lane >> 4) & 1)*8)*RS_
                                    + ((lane >> 3) & 1)*8) * 2;

    float acc[4][8][4] = {};
    const int ntiles = K >> 5;     // k-tile = 32 halves

    auto issue = [&](int stage, int k0) {
        #pragma unroll
        for (int j = 0; j < 4; j++) cpasync16(a_dst[j] + stage*HSTG_, asrc[j] + k0, asz[j]);
        #pragma unroll
        for (int j = 0; j < 4; j++) cpasync16(b_dst[j] + stage*HSTG_, bsrc[j] + k0, 16u);
        cpcommit();
    };

    issue(0, 0);
    if (ntiles > 1) issue(1, 32);
    for (int it = 0; it < ntiles; it++) {
        int st = it % 3;
        if (it == ntiles - 1) cpwait0(); else cpwait1();
        __syncthreads();
        if (it + 2 < ntiles) issue((it + 2) % 3, (it + 2) << 5);
        #pragma unroll
        for (int kk = 0; kk < 32; kk += 16) {
            uint32_t a[4][4], bb[4][4];
            #pragma unroll
            for (int mt = 0; mt < 4; mt++)
                ldsm4(a[mt], a_ld + st*HSTG_ + mt*(16*RS_*2) + kk*2);
            #pragma unroll
            for (int np = 0; np < 4; np++)
                ldsm4(bb[np], b_ld + st*HSTG_ + np*(16*RS_*2) + kk*2);
            #pragma unroll
            for (int mt = 0; mt < 4; mt++)
                #pragma unroll
                for (int nt = 0; nt < 8; nt++) {
                    uint32_t bf[2] = { bb[nt >> 1][(nt & 1)*2], bb[nt >> 1][(nt & 1)*2 + 1] };
                    mma16n8k16h(acc[mt][nt], a[mt], bf);
                }
        }
        __syncthreads();
    }

    // ---- epilogue ----
    #pragma unroll
    for (int mt = 0; mt < 4; mt++) {
        #pragma unroll
        for (int nt = 0; nt < 8; nt++) {
            int n = n0 + wn*64 + nt*8 + t*2;
            float bi0 = bias[n], bi1 = bias[n + 1];
            #pragma unroll
            for (int half = 0; half < 2; half++) {
                int m = m0 + wm*64 + mt*16 + g + half*8;
                if (m < M) {
                    float v0 = acc[mt][nt][half*2 + 0] + bi0;
                    float v1 = acc[mt][nt][half*2 + 1] + bi1;
                    size_t off = (size_t)m * N + n;
                    if (OUT == 1) {
                        v0 = 0.5f * v0 * (1.f + erff(v0 * 0.70710678118654752f));
                        v1 = 0.5f * v1 * (1.f + erff(v1 * 0.70710678118654752f));
                        *reinterpret_cast<__half2*>(Ch + off) = __floats2half2_rn(v0, v1);
                    } else {
                        if (OUT == 2) { v0 += Rm[off]; v1 += Rm[off + 1]; }
                        float2 o; o.x = v0; o.y = v1;
                        *(float2*)&C[off] = o;
                    }
                }
            }
        }
    }
}

// ---------------- flash attention, split-KV (R8, validated) ----------------
__global__ __launch_bounds__(128) void flash_attn() {
    const int it = blockIdx.x, bh = blockIdx.y, sp = blockIdx.z;
    const int b = bh / H_, h = bh % H_;
    const int i0 = it * 64;
    __shared__ __align__(128) float Qs[64][68];
    __shared__ __align__(128) float Ks[32][68];
    __shared__ __align__(128) float Vs[32][68];
    __shared__ __align__(128) float Ps[4][16][40];
    const int tid = threadIdx.x, lane = tid & 31, w = tid >> 5;
    const int g = lane >> 2, t = lane & 3;

    #pragma unroll
    for (int q = 0; q < 8; q++) {
        int idx = q*128 + tid;
        int r = idx >> 4, c4 = (idx & 15) * 4;
        int i = i0 + r;
        float4 v = make_float4(0.f, 0.f, 0.f, 0.f);
        if (i < KS_) v = *(const float4*)&g_qsel[((size_t)(b*KS_ + i))*D_ + h*DH_ + c4];
        Qs[r][c4+0] = tf32r(v.x); Qs[r][c4+1] = tf32r(v.y);
        Qs[r][c4+2] = tf32r(v.z); Qs[r][c4+3] = tf32r(v.w);
    }

    const uint32_t a_ldQ = smem_u32(&Qs[0][0])
        + (uint32_t)((w*16 + (lane & 7) + ((lane >> 3) & 1)*8)*68 + ((lane >> 4) & 1)*4) * 4;
    const uint32_t b_ldK = smem_u32(&Ks[0][0])
        + (uint32_t)(((lane & 7) + ((lane >> 4) & 1)*8)*68 + ((lane >> 3) & 1)*4) * 4;
    const uint32_t a_ldP = smem_u32(&Ps[w][0][0])
        + (uint32_t)(((lane & 7) + ((lane >> 3) & 1)*8)*40 + ((lane >> 4) & 1)*4) * 4;

    float accO[8][4] = {};
    float m0r = -1e30f, m1r = -1e30f, l0r = 0.f, l1r = 0.f;
    __syncthreads();

    for (int j0 = sp * JSEG_; j0 < (sp + 1) * JSEG_; j0 += 32) {
        #pragma unroll
        for (int q = 0; q < 4; q++) {
            int idx = q*128 + tid;
            int r = idx >> 4, c4 = (idx & 15) * 4;
            size_t base = ((size_t)(b*L_ + j0 + r))*NKVM_ + h*DH_ + c4;
            float4 kv = *(const float4*)&g_kvm[base];
            Ks[r][c4+0] = tf32r(kv.x); Ks[r][c4+1] = tf32r(kv.y);
            Ks[r][c4+2] = tf32r(kv.z); Ks[r][c4+3] = tf32r(kv.w);
            float4 vv = *(const float4*)&g_kvm[base + 768];
            Vs[r][c4+0] = tf32r(vv.x); Vs[r][c4+1] = tf32r(vv.y);
            Vs[r][c4+2] = tf32r(vv.z); Vs[r][c4+3] = tf32r(vv.w);
        }
        __syncthreads();

        float sacc[4][4] = {};
        #pragma unroll
        for (int kk = 0; kk < 64; kk += 8) {
            uint32_t a[4], bb[2][4];
            ldsm4(a, a_ldQ + kk*4);
            ldsm4(bb[0], b_ldK + kk*4);
            ldsm4(bb[1], b_ldK + 16*68*4 + kk*4);
            #pragma unroll
            for (int nt = 0; nt < 4; nt++) {
                uint32_t bf[2] = { bb[nt >> 1][(nt & 1)*2], bb[nt >> 1][(nt & 1)*2 + 1] };
                mma16n8k8(sacc[nt], a, bf);
            }
        }
        float cm0 = -1e30f, cm1 = -1e30f;
        #pragma unroll
        for (int nt = 0; nt < 4; nt++) {
            sacc[nt][0] *= 0.125f; sacc[nt][1] *= 0.125f;
            sacc[nt][2] *= 0.125f; sacc[nt][3] *= 0.125f;
            cm0 = fmaxf(cm0, fmaxf(sacc[nt][0], sacc[nt][1]));
            cm1 = fmaxf(cm1, fmaxf(sacc[nt][2], sacc[nt][3]));
        }
        cm0 = fmaxf(cm0, __shfl_xor_sync(0xffffffffu, cm0, 1));
        cm0 = fmaxf(cm0, __shfl_xor_sync(0xffffffffu, cm0, 2));
        cm1 = fmaxf(cm1, __shfl_xor_sync(0xffffffffu, cm1, 1));
        cm1 = fmaxf(cm1, __shfl_xor_sync(0xffffffffu, cm1, 2));
        float mn0 = fmaxf(m0r, cm0), mn1 = fmaxf(m1r, cm1);
        float al0 = expf(m0r - mn0), al1 = expf(m1r - mn1);
        m0r = mn0; m1r = mn1;
        float s0 = 0.f, s1 = 0.f;
        #pragma unroll
        for (int nt = 0; nt < 4; nt++) {
            float p0 = expf(sacc[nt][0] - mn0);
            float p1 = expf(sacc[nt][1] - mn0);
            float p2 = expf(sacc[nt][2] - mn1);
            float p3 = expf(sacc[nt][3] - mn1);
            s0 += p0 + p1; s1 += p2 + p3;
            int c = nt*8 + t*2;
            Ps[w][g][c]     = tf32r(p0);
            Ps[w][g][c+1]   = tf32r(p1);
            Ps[w][g+8][c]   = tf32r(p2);
            Ps[w][g+8][c+1] = tf32r(p3);
        }
        s0 += __shfl_xor_sync(0xffffffffu, s0, 1);
        s0 += __shfl_xor_sync(0xffffffffu, s0, 2);
        s1 += __shfl_xor_sync(0xffffffffu, s1, 1);
        s1 += __shfl_xor_sync(0xffffffffu, s1, 2);
        l0r = l0r*al0 + s0; l1r = l1r*al1 + s1;
        #pragma unroll
        for (int nt = 0; nt < 8; nt++) {
            accO[nt][0] *= al0; accO[nt][1] *= al0;
            accO[nt][2] *= al1; accO[nt][3] *= al1;
        }
        __syncwarp();
        #pragma unroll
        for (int kk = 0; kk < 32; kk += 8) {
            uint32_t a[4];
            ldsm4(a, a_ldP + kk*4);
            #pragma unroll
            for (int nt = 0; nt < 8; nt++) {
                int nb = nt*8 + g;
                uint32_t bv[2];
                bv[0] = __float_as_uint(Vs[kk + t][nb]);
                bv[1] = __float_as_uint(Vs[kk + t + 4][nb]);
                mma16n8k8(accO[nt], a, bv);
            }
        }
        __syncthreads();
    }

    const size_t slot0 = (size_t)(bh*NSPL_ + sp)*320 + it*64 + w*16 + g;
    const size_t slot1 = slot0 + 8;
    if (t == 0) {
        g_pm[slot0] = m0r; g_pl[slot0] = l0r;
        g_pm[slot1] = m1r; g_pl[slot1] = l1r;
    }
    #pragma unroll
    for (int nt = 0; nt < 8; nt++) {
        int c = nt*8 + t*2;
        g_po[slot0*64 + c]     = accO[nt][0];
        g_po[slot0*64 + c + 1] = accO[nt][1];
        g_po[slot1*64 + c]     = accO[nt][2];
        g_po[slot1*64 + c + 1] = accO[nt][3];
    }
}

// combine split-KV partials -> g_ctxh (fp16, feeds Wo GEMM)
__global__ __launch_bounds__(256) void attn_combine() {
    const int it = blockIdx.x, bh = blockIdx.y;
    const int b = bh / H_, h = bh % H_;
    __shared__ float ws[64][NSPL_];
    __shared__ float linv[64];
    const int tid = threadIdx.x;
    if (tid < 64) {
        size_t base = (size_t)(bh*NSPL_)*320 + it*64 + tid;
        float mv[NSPL_]; float m = -1e30f;
        #pragma unroll
        for (int s = 0; s < NSPL_; s++) { mv[s] = g_pm[base + (size_t)s*320]; m = fmaxf(m, mv[s]); }
        float l = 0.f;
        #pragma unroll
        for (int s = 0; s < NSPL_; s++) {
            float wv = expf(mv[s] - m);
            ws[tid][s] = wv;
            l += g_pl[base + (size_t)s*320] * wv;
        }
        linv[tid] = 1.f / l;
    }
    __syncthreads();
    #pragma unroll
    for (int q = 0; q < 16; q++) {
        int idx = q*256 + tid;
        int r = idx >> 6, c = idx & 63;
        int i = it*64 + r;
        if (i < KS_) {
            size_t slot = (size_t)(bh*NSPL_)*320 + it*64 + r;
            float acc = 0.f;
            #pragma unroll
            for (int s = 0; s < NSPL_; s++)
                acc += g_po[(slot + (size_t)s*320)*64 + c] * ws[r][s];
            g_ctxh[((size_t)(b*KS_ + i))*D_ + h*DH_ + c] = __float2half_rn(acc * linv[r]);
        }
    }
}

// ---------------- merge paths + residual + LN2 ----------------
__global__ void merge_ln2_kernel(const float* __restrict__ x, const float* __restrict__ g2,
                                 const float* __restrict__ b2) {
    int tok = blockIdx.x;
    int b = tok >> 11;
    int t = threadIdx.x;
    int pos = g_selpos[tok];
    float sc = g_scores[tok];
    __shared__ float sh[32];
    float hv[3]; float s = 0.f, sq = 0.f;
    #pragma unroll
    for (int i = 0; i < 3; i++) {
        int d = t + 256*i;
        float mg;
        if (pos >= 0) mg = g_attno[(size_t)pos*D_ + d];
        else          mg = g_kvm[(size_t)tok*NKVM_ + 1536 + d] + sc * g_pooledWm[b*D_ + d];
        float u = x[(size_t)tok*D_ + d] + mg;
        hv[i] = u;
        g_h[(size_t)tok*D_ + d] = u;
        s += u; sq += u*u;
    }
    s  = blockReduceSum(s,  sh);
    sq = blockReduceSum(sq, sh);
    float mean = s * (1.f/D_);
    float rstd = rsqrtf(sq*(1.f/D_) - mean*mean + 1e-5f);
    #pragma unroll
    for (int i = 0; i < 3; i++) {
        int d = t + 256*i;
        g_n2h[(size_t)tok*D_ + d] = __float2half_rn((hv[i] - mean) * rstd * g2[d] + b2[d]);
    }
}

// ---------------- host launch ----------------
extern "C" void kernel_launch(void* const* d_in, const int* in_sizes, int n_in,
                              void* d_out, int out_size) {
    (void)in_sizes; (void)n_in; (void)out_size;
    const float* x   = (const float*)d_in[0];
    const float* g1  = (const float*)d_in[1];
    const float* b1  = (const float*)d_in[2];
    const float* g2  = (const float*)d_in[3];
    const float* b2  = (const float*)d_in[4];
    const float* Wr  = (const float*)d_in[5];
    const float* br  = (const float*)d_in[6];
    const float* Wq  = (const float*)d_in[7];
    const float* bq  = (const float*)d_in[8];
    const float* Wk  = (const float*)d_in[9];
    const float* bk  = (const float*)d_in[10];
    const float* Wv  = (const float*)d_in[11];
    const float* bv  = (const float*)d_in[12];
    const float* Wo  = (const float*)d_in[13];
    const float* bo  = (const float*)d_in[14];
    const float* Wm  = (const float*)d_in[15];
    const float* bm  = (const float*)d_in[16];
    const float* W1  = (const float*)d_in[17];
    const float* bf1 = (const float*)d_in[18];
    const float* W2  = (const float*)d_in[19];
    const float* bf2 = (const float*)d_in[20];
    float* out = (float*)d_out;

    float *p_kvm, *p_bkvm, *p_qsel, *p_attno, *p_h;
    __half *p_nh, *p_ctxh, *p_n2h, *p_th, *p_whuf;
    int* p_selidx;
    cudaGetSymbolAddress((void**)&p_nh,     g_nh);
    cudaGetSymbolAddress((void**)&p_kvm,    g_kvm);
    cudaGetSymbolAddress((void**)&p_bkvm,   g_bkvm);
    cudaGetSymbolAddress((void**)&p_qsel,   g_qsel);
    cudaGetSymbolAddress((void**)&p_ctxh,   g_ctxh);
    cudaGetSymbolAddress((void**)&p_attno,  g_attno);
    cudaGetSymbolAddress((void**)&p_h,      g_h);
    cudaGetSymbolAddress((void**)&p_n2h,    g_n2h);
    cudaGetSymbolAddress((void**)&p_th,     g_th);
    cudaGetSymbolAddress((void**)&p_whuf,   g_whuf);
    cudaGetSymbolAddress((void**)&p_selidx, g_selidx);

    __half* rKVM = p_whuf;                         // [2304][768]
    __half* rWq  = p_whuf + 3*(size_t)WSZ_;
    __half* rWo  = p_whuf + 4*(size_t)WSZ_;
    __half* rW1  = p_whuf + 5*(size_t)WSZ_;
    __half* rW2  = rW1 + (size_t)W1SZ_;

    // 0. transpose weights to fp16 [N][K]; K/V/M concatenated along N
    dim3 tb(32, 8);
    transpose_half_kernel<<<dim3(D_/32, D_/32), tb>>>(Wk, rKVM + 0*(size_t)WSZ_, D_, D_);
    transpose_half_kernel<<<dim3(D_/32, D_/32), tb>>>(Wv, rKVM + 1*(size_t)WSZ_, D_, D_);
    transpose_half_kernel<<<dim3(D_/32, D_/32), tb>>>(Wm, rKVM + 2*(size_t)WSZ_, D_, D_);
    transpose_half_kernel<<<dim3(D_/32, D_/32), tb>>>(Wq, rWq, D_, D_);
    transpose_half_kernel<<<dim3(D_/32, D_/32), tb>>>(Wo, rWo, D_, D_);
    transpose_half_kernel<<<dim3(F_/32, D_/32), tb>>>(W1, rW1, D_, F_);
    transpose_half_kernel<<<dim3(D_/32, F_/32), tb>>>(W2, rW2, F_, D_);
    bias_concat_kernel<<<9, 256>>>(bk, bv, bm);
    // 1. LN1 + router
    ln1_router_kernel<<<BL_, 256>>>(x, g1, b1, Wr, br);
    // 2. top-k
    topk_kernel<<<B_, 1024>>>();
    // 3. pooling path (exact fp32)
    pooled_part_kernel<<<dim3(16, B_), D_>>>();
    pooled_fin_kernel<<<B_, D_>>>();
    pooledwm_kernel<<<dim3(3, B_), 256>>>(Wm);
    // 4. fused K|V|mix projection (N=2304), fp16 mma
    gemm_h<0,false><<<dim3(NKVM_/128, BL_/128), 128>>>(p_nh, nullptr, rKVM, p_bkvm, nullptr, p_kvm, nullptr, BL_, NKVM_, D_);
    // 5. Q for selected rows (gather)
    gemm_h<0,true ><<<dim3(D_/128, (MSEL_+127)/128), 128>>>(p_nh, p_selidx, rWq, bq, nullptr, p_qsel, nullptr, MSEL_, D_, D_);
    // 6. flash attention (split-KV) + combine
    flash_attn<<<dim3(5, B_*H_, NSPL_), 128>>>();
    attn_combine<<<dim3(5, B_*H_), 256>>>();
    gemm_h<0,false><<<dim3(D_/128, (MSEL_+127)/128), 128>>>(p_ctxh, nullptr, rWo, bo, nullptr, p_attno, nullptr, MSEL_, D_, D_);
    // 7. merge + residual + LN2
    merge_ln2_kernel<<<BL_, 256>>>(x, g2, b2);
    // 8. FFN (fp16 mma; FFN1 GELU -> fp16; FFN2 + residual -> out)
    gemm_h<1,false><<<dim3(F_/128, BL_/128), 128>>>(p_n2h, nullptr, rW1, bf1, nullptr, nullptr, p_th, BL_, F_, D_);
    gemm_h<2,false><<<dim3(D_/128, BL_/128), 128>>>(p_th,  nullptr, rW2, bf2, p_h,    out,    nullptr, BL_, D_, F_);
}

// round 10
// speedup vs baseline: 2.2588x; 1.0278x over previous
#include <cuda_runtime.h>
#include <cuda_fp16.h>
#include <math.h>
#include <stdint.h>

// Problem constants
#define B_    4
#define L_    2048
#define D_    768
#define H_    12
#define DH_   64
#define F_    3072
#define KS_   307              // round(0.15 * 2048)
#define BL_   (B_*L_)          // 8192
#define MSEL_ (B_*KS_)         // 1228
#define NKVM_ 2304             // 3*D concat (K,V,M)
#define NSPL_ 4                // KV splits in flash attention
#define JSEG_ (L_/NSPL_)       // 512

#define WSZ_  589824           // 768*768
#define W1SZ_ 2359296          // 768*3072

// ---------------- scratch (static device globals; allocation-free) ----------
__device__ float g_normed[BL_*(size_t)D_];    // exact fp32 (router/pool path)
__device__ __align__(16) __half g_nh[BL_*(size_t)D_];   // fp16 (GEMM A path)
__device__ float g_scores[BL_];
__device__ float g_ssum[B_];
__device__ int   g_selidx[MSEL_];
__device__ int   g_selpos[BL_];
__device__ float g_ppart[B_*16*D_];
__device__ float g_pooled[B_*D_];
__device__ float g_pooledWm[B_*D_];
__device__ float g_kvm[BL_*(size_t)NKVM_];    // [tok][ K(768) | V(768) | mixb(768) ]
__device__ float g_bkvm[NKVM_];
__device__ __align__(16) __half g_qselh[MSEL_*(size_t)D_];
__device__ float g_po[(size_t)B_*H_*NSPL_*320*64];   // attention partial O
__device__ float g_pm[B_*H_*NSPL_*320];
__device__ float g_pl[B_*H_*NSPL_*320];
__device__ __align__(16) __half g_ctxh[MSEL_*(size_t)D_];
__device__ float g_attno[MSEL_*(size_t)D_];
__device__ float g_h[BL_*(size_t)D_];
__device__ __align__(16) __half g_n2h[BL_*(size_t)D_];
__device__ __align__(16) __half g_th[BL_*(size_t)F_];
__device__ __align__(16) __half g_whuf[5*(size_t)WSZ_ + 2*(size_t)W1SZ_];  // fp16 [N][K] weights

// ---------------- small helpers ----------------
__device__ __forceinline__ uint32_t smem_u32(const void* p) {
    uint32_t a;
    asm("{ .reg .u64 t; cvta.to.shared.u64 t, %1; cvt.u32.u64 %0, t; }"
        : "=r"(a) : "l"(p));
    return a;
}
__device__ __forceinline__ void mma16n8k16h(float* c, const uint32_t* a, const uint32_t* b) {
    asm volatile(
        "mma.sync.aligned.m16n8k16.row.col.f32.f16.f16.f32 "
        "{%0,%1,%2,%3}, {%4,%5,%6,%7}, {%8,%9}, {%0,%1,%2,%3};"
        : "+f"(c[0]), "+f"(c[1]), "+f"(c[2]), "+f"(c[3])
        : "r"(a[0]), "r"(a[1]), "r"(a[2]), "r"(a[3]), "r"(b[0]), "r"(b[1]));
}
__device__ __forceinline__ void ldsm4(uint32_t* r, uint32_t addr) {
    asm volatile("ldmatrix.sync.aligned.m8n8.x4.shared.b16 {%0,%1,%2,%3}, [%4];"
        : "=r"(r[0]), "=r"(r[1]), "=r"(r[2]), "=r"(r[3]) : "r"(addr));
}
__device__ __forceinline__ void cpasync16(uint32_t dst, const void* src, unsigned sz) {
    asm volatile("cp.async.cg.shared.global [%0], [%1], 16, %2;"
        :: "r"(dst), "l"(src), "r"(sz));
}
__device__ __forceinline__ void cpcommit() { asm volatile("cp.async.commit_group;"); }
__device__ __forceinline__ void cpwait0()  { asm volatile("cp.async.wait_group 0;"); }
__device__ __forceinline__ void cpwait1()  { asm volatile("cp.async.wait_group 1;"); }

// ---------------- reductions ----------------
__device__ __forceinline__ float blockReduceSum(float v, float* sh) {
    __syncthreads();
    int lane = threadIdx.x & 31, w = threadIdx.x >> 5;
    #pragma unroll
    for (int o = 16; o > 0; o >>= 1) v += __shfl_xor_sync(0xffffffffu, v, o);
    if (lane == 0) sh[w] = v;
    __syncthreads();
    int nw = (blockDim.x + 31) >> 5;
    if (w == 0) {
        v = (lane < nw) ? sh[lane] : 0.f;
        #pragma unroll
        for (int o = 16; o > 0; o >>= 1) v += __shfl_xor_sync(0xffffffffu, v, o);
        if (lane == 0) sh[0] = v;
    }
    __syncthreads();
    return sh[0];
}

// ---------------- W prep: transpose [K][N] fp32 -> [N][K] fp16, wide stores -
__global__ void transpose_half_kernel(const float* __restrict__ in, __half* __restrict__ out,
                                      int K, int N) {
    __shared__ float tile[64][33];
    int k0 = blockIdx.y * 64, n0 = blockIdx.x * 32;
    int tx = threadIdx.x, ty = threadIdx.y;   // (32, 8)
    #pragma unroll
    for (int i = 0; i < 64; i += 8)
        tile[ty + i][tx] = in[(size_t)(k0 + ty + i) * N + n0 + tx];
    __syncthreads();
    #pragma unroll
    for (int i = 0; i < 32; i += 8) {
        int n = n0 + ty + i;
        __half2 v = __floats2half2_rn(tile[tx*2][ty + i], tile[tx*2 + 1][ty + i]);
        *reinterpret_cast<__half2*>(&out[(size_t)n * K + k0 + tx*2]) = v;
    }
}

__global__ void bias_concat_kernel(const float* __restrict__ bk, const float* __restrict__ bv,
                                   const float* __restrict__ bm) {
    int d = blockIdx.x * 256 + threadIdx.x;   // 9 blocks * 256 = 2304
    float v = (d < 768) ? bk[d] : ((d < 1536) ? bv[d - 768] : bm[d - 1536]);
    g_bkvm[d] = v;
}

// ---------------- K1: LN1 + router score ----------------
__global__ void ln1_router_kernel(const float* __restrict__ x, const float* __restrict__ g1,
                                  const float* __restrict__ b1, const float* __restrict__ Wr,
                                  const float* __restrict__ br) {
    int tok = blockIdx.x;
    int t = threadIdx.x;   // 256
    const float* xr = x + (size_t)tok * D_;
    __shared__ float sh[32];
    float v[3]; float s = 0.f, sq = 0.f;
    #pragma unroll
    for (int i = 0; i < 3; i++) { float u = xr[t + 256*i]; v[i] = u; s += u; sq += u*u; }
    s  = blockReduceSum(s,  sh);
    sq = blockReduceSum(sq, sh);
    float mean = s * (1.f/D_);
    float var  = sq * (1.f/D_) - mean*mean;
    float rstd = rsqrtf(var + 1e-5f);
    float dot = 0.f;
    #pragma unroll
    for (int i = 0; i < 3; i++) {
        int d = t + 256*i;
        float nv = (v[i] - mean) * rstd * g1[d] + b1[d];
        g_normed[(size_t)tok*D_ + d] = nv;
        g_nh[(size_t)tok*D_ + d] = __float2half_rn(nv);
        dot += nv * Wr[d];
    }
    dot = blockReduceSum(dot, sh);
    if (t == 0) g_scores[tok] = 1.f / (1.f + expf(-(dot + br[0])));
}

// ---------------- K2: exact top-k via bitonic sort ----------
__global__ void topk_kernel() {
    int b = blockIdx.x, t = threadIdx.x;   // 1024 threads
    __shared__ unsigned long long keys[L_];
    __shared__ float sh[32];
    float s0 = g_scores[b*L_ + t];
    float s1 = g_scores[b*L_ + t + 1024];
    keys[t]        = ((unsigned long long)__float_as_uint(s0) << 32) | (unsigned)t;
    keys[t + 1024] = ((unsigned long long)__float_as_uint(s1) << 32) | (unsigned)(t + 1024);
    g_selpos[b*L_ + t] = -1;
    g_selpos[b*L_ + t + 1024] = -1;
    float tot = blockReduceSum(s0 + s1, sh);
    if (t == 0) g_ssum[b] = tot + 1e-6f;
    for (unsigned k = 2; k <= (unsigned)L_; k <<= 1) {
        for (unsigned j = k >> 1; j > 0; j >>= 1) {
            __syncthreads();
            for (unsigned i = t; i < (unsigned)L_; i += 1024) {
                unsigned ixj = i ^ j;
                if (ixj > i) {
                    unsigned long long a = keys[i], c = keys[ixj];
                    bool up = ((i & k) == 0);
                    if ((a > c) == up) { keys[i] = c; keys[ixj] = a; }
                }
            }
        }
    }
    __syncthreads();
    if (t < KS_) {
        int tok = (int)(unsigned)(keys[t] & 0xffffffffULL);
        g_selidx[b*KS_ + t] = b*L_ + tok;
        g_selpos[b*L_ + tok] = b*KS_ + t;
    }
}

// ---------------- K3: coherence-weighted pooling ----------------
__global__ void pooled_part_kernel() {
    int b = blockIdx.y, ch = blockIdx.x;
    int d = threadIdx.x;
    float acc = 0.f;
    int l0 = ch * (L_/16);
    for (int l = l0; l < l0 + L_/16; l++)
        acc += g_scores[b*L_ + l] * g_normed[((size_t)(b*L_ + l))*D_ + d];
    g_ppart[(b*16 + ch)*D_ + d] = acc;
}
__global__ void pooled_fin_kernel() {
    int b = blockIdx.x; int d = threadIdx.x;
    float acc = 0.f;
    #pragma unroll
    for (int c = 0; c < 16; c++) acc += g_ppart[(b*16 + c)*D_ + d];
    g_pooled[b*D_ + d] = acc / g_ssum[b];
}
__global__ void pooledwm_kernel(const float* __restrict__ Wm) {
    int b = blockIdx.y;
    int n = blockIdx.x*256 + threadIdx.x;
    float acc = 0.f;
    for (int d = 0; d < D_; d++) acc += g_pooled[b*D_ + d] * Wm[d*D_ + n];
    g_pooledWm[b*D_ + n] = acc;
}

// ---------------- fp16 GEMM: mma m16n8k16, dual ldmatrix, 3-stage ----------
// C[M,N] = epi( A[M,K] @ Bt[N,K]^T + bias[N] )
// OUT: 0 = f32 C; 1 = GELU -> fp16 Ch; 2 = + Rm -> f32 C; 3 = fp16 Ch.
#define RS_  40                   // smem row stride in halves (80 B)
#define HSTG_ (128*RS_*2)         // bytes per stage per operand = 10240
template<int OUT, bool GATHER>
__global__ __launch_bounds__(128)
void gemm_h(const __half* __restrict__ A, const int* __restrict__ gidx,
            const __half* __restrict__ Bt, const float* __restrict__ bias,
            const float* __restrict__ Rm, float* __restrict__ C,
            __half* __restrict__ Ch, int M, int N, int K) {
    __shared__ __align__(128) __half As[3][128][RS_];
    __shared__ __align__(128) __half Bs[3][128][RS_];
    const int tid = threadIdx.x, lane = tid & 31, wid = tid >> 5;
    const int wm = wid & 1, wn = wid >> 1;
    const int g = lane >> 2, t = lane & 3;
    const int m0 = blockIdx.y * 128, n0 = blockIdx.x * 128;

    uint32_t sA = smem_u32(&As[0][0][0]);
    uint32_t sB = smem_u32(&Bs[0][0][0]);

    const __half* asrc[4]; unsigned asz[4]; uint32_t a_dst[4];
    const __half* bsrc[4]; uint32_t b_dst[4];
    #pragma unroll
    for (int j = 0; j < 4; j++) {
        int rl = j*32 + (tid >> 2);
        int ck = (tid & 3) * 8;            // halves within 32-half k-tile
        int r = m0 + rl;
        bool v = r < M;
        int gr = v ? (GATHER ? gidx[r] : r) : 0;
        asrc[j]  = A + (size_t)gr*K + ck;
        asz[j]   = v ? 16u : 0u;
        a_dst[j] = sA + (uint32_t)(rl*RS_ + ck) * 2;
        bsrc[j]  = Bt + (size_t)(n0 + rl)*K + ck;
        b_dst[j] = sB + (uint32_t)(rl*RS_ + ck) * 2;
    }

    uint32_t a_ld = sA + (uint32_t)((wm*64 + (lane & 7) + ((lane >> 3) & 1)*8)*RS_
                                    + ((lane >> 4) & 1)*8) * 2;
    uint32_t b_ld = sB + (uint32_t)((wn*64 + (lane & 7) + ((lane >> 4) & 1)*8)*RS_
                                    + ((lane >> 3) & 1)*8) * 2;

    float acc[4][8][4] = {};
    const int ntiles = K >> 5;     // k-tile = 32 halves

    auto issue = [&](int stage, int k0) {
        #pragma unroll
        for (int j = 0; j < 4; j++) cpasync16(a_dst[j] + stage*HSTG_, asrc[j] + k0, asz[j]);
        #pragma unroll
        for (int j = 0; j < 4; j++) cpasync16(b_dst[j] + stage*HSTG_, bsrc[j] + k0, 16u);
        cpcommit();
    };

    issue(0, 0);
    if (ntiles > 1) issue(1, 32);
    for (int it = 0; it < ntiles; it++) {
        int st = it % 3;
        if (it == ntiles - 1) cpwait0(); else cpwait1();
        __syncthreads();
        if (it + 2 < ntiles) issue((it + 2) % 3, (it + 2) << 5);
        #pragma unroll
        for (int kk = 0; kk < 32; kk += 16) {
            uint32_t a[4][4], bb[4][4];
            #pragma unroll
            for (int mt = 0; mt < 4; mt++)
                ldsm4(a[mt], a_ld + st*HSTG_ + mt*(16*RS_*2) + kk*2);
            #pragma unroll
            for (int np = 0; np < 4; np++)
                ldsm4(bb[np], b_ld + st*HSTG_ + np*(16*RS_*2) + kk*2);
            #pragma unroll
            for (int mt = 0; mt < 4; mt++)
                #pragma unroll
                for (int nt = 0; nt < 8; nt++) {
                    uint32_t bf[2] = { bb[nt >> 1][(nt & 1)*2], bb[nt >> 1][(nt & 1)*2 + 1] };
                    mma16n8k16h(acc[mt][nt], a[mt], bf);
                }
        }
        __syncthreads();
    }

    // ---- epilogue ----
    #pragma unroll
    for (int mt = 0; mt < 4; mt++) {
        #pragma unroll
        for (int nt = 0; nt < 8; nt++) {
            int n = n0 + wn*64 + nt*8 + t*2;
            float bi0 = bias[n], bi1 = bias[n + 1];
            #pragma unroll
            for (int half = 0; half < 2; half++) {
                int m = m0 + wm*64 + mt*16 + g + half*8;
                if (m < M) {
                    float v0 = acc[mt][nt][half*2 + 0] + bi0;
                    float v1 = acc[mt][nt][half*2 + 1] + bi1;
                    size_t off = (size_t)m * N + n;
                    if (OUT == 1 || OUT == 3) {
                        if (OUT == 1) {
                            v0 = 0.5f * v0 * (1.f + erff(v0 * 0.70710678118654752f));
                            v1 = 0.5f * v1 * (1.f + erff(v1 * 0.70710678118654752f));
                        }
                        *reinterpret_cast<__half2*>(Ch + off) = __floats2half2_rn(v0, v1);
                    } else {
                        if (OUT == 2) { v0 += Rm[off]; v1 += Rm[off + 1]; }
                        float2 o; o.x = v0; o.y = v1;
                        *(float2*)&C[off] = o;
                    }
                }
            }
        }
    }
}

// ---------------- flash attention, split-KV, fp16 mma ----------------------
// grid (5 i-tiles, 48 bh, NSPL_). 128 thr = 4 warps; warp w: rows [w*16,w*16+16).
#define QST_ 72   // Qh/Kh row stride (halves)
#define VST_ 40   // Vt/Ph row stride (halves)
__global__ __launch_bounds__(128) void flash_attn() {
    const int it = blockIdx.x, bh = blockIdx.y, sp = blockIdx.z;
    const int b = bh / H_, h = bh % H_;
    const int i0 = it * 64;
    __shared__ __align__(128) __half Qh[64][QST_];
    __shared__ __align__(128) __half Kh[32][QST_];
    __shared__ __align__(128) __half Vt[64][VST_];   // dh-major (transposed)
    __shared__ __align__(128) __half Ph[4][16][VST_];
    const int tid = threadIdx.x, lane = tid & 31, w = tid >> 5;
    const int g = lane >> 2, t = lane & 3;

    // load Q tile once (fp16 direct)
    #pragma unroll
    for (int q = 0; q < 4; q++) {
        int idx = q*128 + tid;
        int r = idx >> 3, c8 = (idx & 7) * 8;
        int i = i0 + r;
        uint4 v = make_uint4(0u, 0u, 0u, 0u);
        if (i < KS_) v = *(const uint4*)&g_qselh[((size_t)(b*KS_ + i))*D_ + h*DH_ + c8];
        *(uint4*)&Qh[r][c8] = v;
    }

    const uint32_t a_ldQ = smem_u32(&Qh[0][0])
        + (uint32_t)((w*16 + (lane & 7) + ((lane >> 3) & 1)*8)*QST_ + ((lane >> 4) & 1)*8) * 2;
    const uint32_t b_ldK = smem_u32(&Kh[0][0])
        + (uint32_t)(((lane & 7) + ((lane >> 4) & 1)*8)*QST_ + ((lane >> 3) & 1)*8) * 2;
    const uint32_t b_ldV = smem_u32(&Vt[0][0])
        + (uint32_t)(((lane & 7) + ((lane >> 4) & 1)*8)*VST_ + ((lane >> 3) & 1)*8) * 2;
    const uint32_t a_ldP = smem_u32(&Ph[w][0][0])
        + (uint32_t)(((lane & 7) + ((lane >> 3) & 1)*8)*VST_ + ((lane >> 4) & 1)*8) * 2;

    float accO[8][4] = {};
    float m0r = -1e30f, m1r = -1e30f, l0r = 0.f, l1r = 0.f;
    __syncthreads();

    for (int j0 = sp * JSEG_; j0 < (sp + 1) * JSEG_; j0 += 32) {
        // K chunk: 32 j-rows x 64 dh halves (j-major)
        #pragma unroll
        for (int q = 0; q < 4; q++) {
            int idx = q*128 + tid;
            int r = idx >> 4, c4 = (idx & 15) * 4;
            float4 kv = *(const float4*)&g_kvm[((size_t)(b*L_ + j0 + r))*NKVM_ + h*DH_ + c4];
            *reinterpret_cast<__half2*>(&Kh[r][c4])     = __floats2half2_rn(kv.x, kv.y);
            *reinterpret_cast<__half2*>(&Kh[r][c4 + 2]) = __floats2half2_rn(kv.z, kv.w);
        }
        // V chunk transposed: Vt[dh][j]
        #pragma unroll
        for (int q = 0; q < 4; q++) {
            int r = tid & 31;                       // j
            int c0 = (q*4 + (tid >> 5)) * 4;        // dh
            float4 vv = *(const float4*)&g_kvm[((size_t)(b*L_ + j0 + r))*NKVM_ + 768 + h*DH_ + c0];
            Vt[c0+0][r] = __float2half_rn(vv.x);
            Vt[c0+1][r] = __float2half_rn(vv.y);
            Vt[c0+2][r] = __float2half_rn(vv.z);
            Vt[c0+3][r] = __float2half_rn(vv.w);
        }
        __syncthreads();

        // S = (Q K^T) * 0.125 ; warp m16 x 32 cols, fp16 k16 mma
        float sacc[4][4] = {};
        #pragma unroll
        for (int ks = 0; ks < 4; ks++) {
            uint32_t a[4], bb[2][4];
            ldsm4(a, a_ldQ + ks*32);
            ldsm4(bb[0], b_ldK + ks*32);
            ldsm4(bb[1], b_ldK + 16*QST_*2 + ks*32);
            #pragma unroll
            for (int nt = 0; nt < 4; nt++) {
                uint32_t bf[2] = { bb[nt >> 1][(nt & 1)*2], bb[nt >> 1][(nt & 1)*2 + 1] };
                mma16n8k16h(sacc[nt], a, bf);
            }
        }
        float cm0 = -1e30f, cm1 = -1e30f;
        #pragma unroll
        for (int nt = 0; nt < 4; nt++) {
            sacc[nt][0] *= 0.125f; sacc[nt][1] *= 0.125f;
            sacc[nt][2] *= 0.125f; sacc[nt][3] *= 0.125f;
            cm0 = fmaxf(cm0, fmaxf(sacc[nt][0], sacc[nt][1]));
            cm1 = fmaxf(cm1, fmaxf(sacc[nt][2], sacc[nt][3]));
        }
        cm0 = fmaxf(cm0, __shfl_xor_sync(0xffffffffu, cm0, 1));
        cm0 = fmaxf(cm0, __shfl_xor_sync(0xffffffffu, cm0, 2));
        cm1 = fmaxf(cm1, __shfl_xor_sync(0xffffffffu, cm1, 1));
        cm1 = fmaxf(cm1, __shfl_xor_sync(0xffffffffu, cm1, 2));
        float mn0 = fmaxf(m0r, cm0), mn1 = fmaxf(m1r, cm1);
        float al0 = expf(m0r - mn0), al1 = expf(m1r - mn1);
        m0r = mn0; m1r = mn1;
        float s0 = 0.f, s1 = 0.f;
        #pragma unroll
        for (int nt = 0; nt < 4; nt++) {
            float p0 = expf(sacc[nt][0] - mn0);
            float p1 = expf(sacc[nt][1] - mn0);
            float p2 = expf(sacc[nt][2] - mn1);
            float p3 = expf(sacc[nt][3] - mn1);
            s0 += p0 + p1; s1 += p2 + p3;
            int c = nt*8 + t*2;
            *reinterpret_cast<__half2*>(&Ph[w][g][c])     = __floats2half2_rn(p0, p1);
            *reinterpret_cast<__half2*>(&Ph[w][g + 8][c]) = __floats2half2_rn(p2, p3);
        }
        s0 += __shfl_xor_sync(0xffffffffu, s0, 1);
        s0 += __shfl_xor_sync(0xffffffffu, s0, 2);
        s1 += __shfl_xor_sync(0xffffffffu, s1, 1);
        s1 += __shfl_xor_sync(0xffffffffu, s1, 2);
        l0r = l0r*al0 + s0; l1r = l1r*al1 + s1;
        #pragma unroll
        for (int nt = 0; nt < 8; nt++) {
            accO[nt][0] *= al0; accO[nt][1] *= al0;
            accO[nt][2] *= al1; accO[nt][3] *= al1;
        }
        __syncwarp();
        // O += P V   (fp16 k16 mma; V dh-major B fragments)
        #pragma unroll
        for (int ks = 0; ks < 2; ks++) {
            uint32_t a[4];
            ldsm4(a, a_ldP + ks*32);
            uint32_t bb[4][4];
            #pragma unroll
            for (int np = 0; np < 4; np++)
                ldsm4(bb[np], b_ldV + np*(16*VST_*2) + ks*32);
            #pragma unroll
            for (int nt = 0; nt < 8; nt++) {
                uint32_t bf[2] = { bb[nt >> 1][(nt & 1)*2], bb[nt >> 1][(nt & 1)*2 + 1] };
                mma16n8k16h(accO[nt], a, bf);
            }
        }
        __syncthreads();
    }

    const size_t slot0 = (size_t)(bh*NSPL_ + sp)*320 + it*64 + w*16 + g;
    const size_t slot1 = slot0 + 8;
    if (t == 0) {
        g_pm[slot0] = m0r; g_pl[slot0] = l0r;
        g_pm[slot1] = m1r; g_pl[slot1] = l1r;
    }
    #pragma unroll
    for (int nt = 0; nt < 8; nt++) {
        int c = nt*8 + t*2;
        g_po[slot0*64 + c]     = accO[nt][0];
        g_po[slot0*64 + c + 1] = accO[nt][1];
        g_po[slot1*64 + c]     = accO[nt][2];
        g_po[slot1*64 + c + 1] = accO[nt][3];
    }
}

// combine split-KV partials -> g_ctxh (fp16, feeds Wo GEMM)
__global__ __launch_bounds__(256) void attn_combine() {
    const int it = blockIdx.x, bh = blockIdx.y;
    const int b = bh / H_, h = bh % H_;
    __shared__ float ws[64][NSPL_];
    __shared__ float linv[64];
    const int tid = threadIdx.x;
    if (tid < 64) {
        size_t base = (size_t)(bh*NSPL_)*320 + it*64 + tid;
        float mv[NSPL_]; float m = -1e30f;
        #pragma unroll
        for (int s = 0; s < NSPL_; s++) { mv[s] = g_pm[base + (size_t)s*320]; m = fmaxf(m, mv[s]); }
        float l = 0.f;
        #pragma unroll
        for (int s = 0; s < NSPL_; s++) {
            float wv = expf(mv[s] - m);
            ws[tid][s] = wv;
            l += g_pl[base + (size_t)s*320] * wv;
        }
        linv[tid] = 1.f / l;
    }
    __syncthreads();
    #pragma unroll
    for (int q = 0; q < 16; q++) {
        int idx = q*256 + tid;
        int r = idx >> 6, c = idx & 63;
        int i = it*64 + r;
        if (i < KS_) {
            size_t slot = (size_t)(bh*NSPL_)*320 + it*64 + r;
            float acc = 0.f;
            #pragma unroll
            for (int s = 0; s < NSPL_; s++)
                acc += g_po[(slot + (size_t)s*320)*64 + c] * ws[r][s];
            g_ctxh[((size_t)(b*KS_ + i))*D_ + h*DH_ + c] = __float2half_rn(acc * linv[r]);
        }
    }
}

// ---------------- merge paths + residual + LN2 ----------------
__global__ void merge_ln2_kernel(const float* __restrict__ x, const float* __restrict__ g2,
                                 const float* __restrict__ b2) {
    int tok = blockIdx.x;
    int b = tok >> 11;
    int t = threadIdx.x;
    int pos = g_selpos[tok];
    float sc = g_scores[tok];
    __shared__ float sh[32];
    float hv[3]; float s = 0.f, sq = 0.f;
    #pragma unroll
    for (int i = 0; i < 3; i++) {
        int d = t + 256*i;
        float mg;
        if (pos >= 0) mg = g_attno[(size_t)pos*D_ + d];
        else          mg = g_kvm[(size_t)tok*NKVM_ + 1536 + d] + sc * g_pooledWm[b*D_ + d];
        float u = x[(size_t)tok*D_ + d] + mg;
        hv[i] = u;
        g_h[(size_t)tok*D_ + d] = u;
        s += u; sq += u*u;
    }
    s  = blockReduceSum(s,  sh);
    sq = blockReduceSum(sq, sh);
    float mean = s * (1.f/D_);
    float rstd = rsqrtf(sq*(1.f/D_) - mean*mean + 1e-5f);
    #pragma unroll
    for (int i = 0; i < 3; i++) {
        int d = t + 256*i;
        g_n2h[(size_t)tok*D_ + d] = __float2half_rn((hv[i] - mean) * rstd * g2[d] + b2[d]);
    }
}

// ---------------- host launch ----------------
extern "C" void kernel_launch(void* const* d_in, const int* in_sizes, int n_in,
                              void* d_out, int out_size) {
    (void)in_sizes; (void)n_in; (void)out_size;
    const float* x   = (const float*)d_in[0];
    const float* g1  = (const float*)d_in[1];
    const float* b1  = (const float*)d_in[2];
    const float* g2  = (const float*)d_in[3];
    const float* b2  = (const float*)d_in[4];
    const float* Wr  = (const float*)d_in[5];
    const float* br  = (const float*)d_in[6];
    const float* Wq  = (const float*)d_in[7];
    const float* bq  = (const float*)d_in[8];
    const float* Wk  = (const float*)d_in[9];
    const float* bk  = (const float*)d_in[10];
    const float* Wv  = (const float*)d_in[11];
    const float* bv  = (const float*)d_in[12];
    const float* Wo  = (const float*)d_in[13];
    const float* bo  = (const float*)d_in[14];
    const float* Wm  = (const float*)d_in[15];
    const float* bm  = (const float*)d_in[16];
    const float* W1  = (const float*)d_in[17];
    const float* bf1 = (const float*)d_in[18];
    const float* W2  = (const float*)d_in[19];
    const float* bf2 = (const float*)d_in[20];
    float* out = (float*)d_out;

    float *p_kvm, *p_bkvm, *p_attno, *p_h;
    __half *p_nh, *p_qselh, *p_ctxh, *p_n2h, *p_th, *p_whuf;
    int* p_selidx;
    cudaGetSymbolAddress((void**)&p_nh,     g_nh);
    cudaGetSymbolAddress((void**)&p_kvm,    g_kvm);
    cudaGetSymbolAddress((void**)&p_bkvm,   g_bkvm);
    cudaGetSymbolAddress((void**)&p_qselh,  g_qselh);
    cudaGetSymbolAddress((void**)&p_ctxh,   g_ctxh);
    cudaGetSymbolAddress((void**)&p_attno,  g_attno);
    cudaGetSymbolAddress((void**)&p_h,      g_h);
    cudaGetSymbolAddress((void**)&p_n2h,    g_n2h);
    cudaGetSymbolAddress((void**)&p_th,     g_th);
    cudaGetSymbolAddress((void**)&p_whuf,   g_whuf);
    cudaGetSymbolAddress((void**)&p_selidx, g_selidx);

    __half* rKVM = p_whuf;                         // [2304][768]
    __half* rWq  = p_whuf + 3*(size_t)WSZ_;
    __half* rWo  = p_whuf + 4*(size_t)WSZ_;
    __half* rW1  = p_whuf + 5*(size_t)WSZ_;
    __half* rW2  = rW1 + (size_t)W1SZ_;

    // 0. transpose weights to fp16 [N][K]; K/V/M concatenated along N
    dim3 tb(32, 8);
    transpose_half_kernel<<<dim3(D_/32, D_/64), tb>>>(Wk, rKVM + 0*(size_t)WSZ_, D_, D_);
    transpose_half_kernel<<<dim3(D_/32, D_/64), tb>>>(Wv, rKVM + 1*(size_t)WSZ_, D_, D_);
    transpose_half_kernel<<<dim3(D_/32, D_/64), tb>>>(Wm, rKVM + 2*(size_t)WSZ_, D_, D_);
    transpose_half_kernel<<<dim3(D_/32, D_/64), tb>>>(Wq, rWq, D_, D_);
    transpose_half_kernel<<<dim3(D_/32, D_/64), tb>>>(Wo, rWo, D_, D_);
    transpose_half_kernel<<<dim3(F_/32, D_/64), tb>>>(W1, rW1, D_, F_);
    transpose_half_kernel<<<dim3(D_/32, F_/64), tb>>>(W2, rW2, F_, D_);
    bias_concat_kernel<<<9, 256>>>(bk, bv, bm);
    // 1. LN1 + router
    ln1_router_kernel<<<BL_, 256>>>(x, g1, b1, Wr, br);
    // 2. top-k
    topk_kernel<<<B_, 1024>>>();
    // 3. pooling path (exact fp32)
    pooled_part_kernel<<<dim3(16, B_), D_>>>();
    pooled_fin_kernel<<<B_, D_>>>();
    pooledwm_kernel<<<dim3(3, B_), 256>>>(Wm);
    // 4. fused K|V|mix projection (N=2304), fp16 mma
    gemm_h<0,false><<<dim3(NKVM_/128, BL_/128), 128>>>(p_nh, nullptr, rKVM, p_bkvm, nullptr, p_kvm, nullptr, BL_, NKVM_, D_);
    // 5. Q for selected rows (gather) -> fp16
    gemm_h<3,true ><<<dim3(D_/128, (MSEL_+127)/128), 128>>>(p_nh, p_selidx, rWq, bq, nullptr, nullptr, p_qselh, MSEL_, D_, D_);
    // 6. flash attention (split-KV, fp16 mma) + combine
    flash_attn<<<dim3(5, B_*H_, NSPL_), 128>>>();
    attn_combine<<<dim3(5, B_*H_), 256>>>();
    gemm_h<0,false><<<dim3(D_/128, (MSEL_+127)/128), 128>>>(p_ctxh, nullptr, rWo, bo, nullptr, p_attno, nullptr, MSEL_, D_, D_);
    // 7. merge + residual + LN2
    merge_ln2_kernel<<<BL_, 256>>>(x, g2, b2);
    // 8. FFN (fp16 mma; FFN1 GELU -> fp16; FFN2 + residual -> out)
    gemm_h<1,false><<<dim3(F_/128, BL_/128), 128>>>(p_n2h, nullptr, rW1, bf1, nullptr, nullptr, p_th, BL_, F_, D_);
    gemm_h<2,false><<<dim3(D_/128, BL_/128), 128>>>(p_th,  nullptr, rW2, bf2, p_h,    out,    nullptr, BL_, D_, F_);
}

// round 11
// speedup vs baseline: 2.3928x; 1.0593x over previous
#include <cuda_runtime.h>
#include <cuda_fp16.h>
#include <math.h>
#include <stdint.h>

// Problem constants
#define B_    4
#define L_    2048
#define D_    768
#define H_    12
#define DH_   64
#define F_    3072
#define KS_   307              // round(0.15 * 2048)
#define BL_   (B_*L_)          // 8192
#define MSEL_ (B_*KS_)         // 1228
#define NKVM_ 2304             // 3*D concat (K,V,M)
#define NSPL_ 4                // KV splits in flash attention
#define JSEG_ (L_/NSPL_)       // 512

#define WSZ_  589824           // 768*768
#define W1SZ_ 2359296          // 768*3072

// ---------------- scratch (static device globals; allocation-free) ----------
__device__ __align__(16) __half g_nh[BL_*(size_t)D_];   // fp16 LN1 output
__device__ float g_scores[BL_];
__device__ float g_ssum[B_];
__device__ int   g_selidx[MSEL_];
__device__ int   g_selpos[BL_];
__device__ float g_ppart[B_*16*D_];
__device__ float g_pooled[B_*D_];
__device__ float g_pooledWm[B_*D_];
__device__ float g_kvm[BL_*(size_t)NKVM_];    // [tok][ K(768) | V(768) | mixb(768) ]
__device__ float g_bkvm[NKVM_];
__device__ __align__(16) __half g_qselh[MSEL_*(size_t)D_];
__device__ float g_po[(size_t)B_*H_*NSPL_*320*64];   // attention partial O
__device__ float g_pm[B_*H_*NSPL_*320];
__device__ float g_pl[B_*H_*NSPL_*320];
__device__ __align__(16) __half g_ctxh[MSEL_*(size_t)D_];
__device__ float g_attno[MSEL_*(size_t)D_];
__device__ float g_h[BL_*(size_t)D_];
__device__ __align__(16) __half g_n2h[BL_*(size_t)D_];
__device__ __align__(16) __half g_th[BL_*(size_t)F_];
__device__ float g_fp2[2*(size_t)BL_*D_];     // FFN2 split-K partials (50 MB)
__device__ __align__(16) __half g_whuf[5*(size_t)WSZ_ + 2*(size_t)W1SZ_];  // fp16 [N][K] weights

// ---------------- small helpers ----------------
__device__ __forceinline__ uint32_t smem_u32(const void* p) {
    uint32_t a;
    asm("{ .reg .u64 t; cvta.to.shared.u64 t, %1; cvt.u32.u64 %0, t; }"
        : "=r"(a) : "l"(p));
    return a;
}
__device__ __forceinline__ void mma16n8k16h(float* c, const uint32_t* a, const uint32_t* b) {
    asm volatile(
        "mma.sync.aligned.m16n8k16.row.col.f32.f16.f16.f32 "
        "{%0,%1,%2,%3}, {%4,%5,%6,%7}, {%8,%9}, {%0,%1,%2,%3};"
        : "+f"(c[0]), "+f"(c[1]), "+f"(c[2]), "+f"(c[3])
        : "r"(a[0]), "r"(a[1]), "r"(a[2]), "r"(a[3]), "r"(b[0]), "r"(b[1]));
}
__device__ __forceinline__ void ldsm4(uint32_t* r, uint32_t addr) {
    asm volatile("ldmatrix.sync.aligned.m8n8.x4.shared.b16 {%0,%1,%2,%3}, [%4];"
        : "=r"(r[0]), "=r"(r[1]), "=r"(r[2]), "=r"(r[3]) : "r"(addr));
}
__device__ __forceinline__ void cpasync16(uint32_t dst, const void* src, unsigned sz) {
    asm volatile("cp.async.cg.shared.global [%0], [%1], 16, %2;"
        :: "r"(dst), "l"(src), "r"(sz));
}
__device__ __forceinline__ void cpcommit() { asm volatile("cp.async.commit_group;"); }
__device__ __forceinline__ void cpwait0()  { asm volatile("cp.async.wait_group 0;"); }
__device__ __forceinline__ void cpwait1()  { asm volatile("cp.async.wait_group 1;"); }

// ---------------- reductions ----------------
__device__ __forceinline__ float blockReduceSum(float v, float* sh) {
    __syncthreads();
    int lane = threadIdx.x & 31, w = threadIdx.x >> 5;
    #pragma unroll
    for (int o = 16; o > 0; o >>= 1) v += __shfl_xor_sync(0xffffffffu, v, o);
    if (lane == 0) sh[w] = v;
    __syncthreads();
    int nw = (blockDim.x + 31) >> 5;
    if (w == 0) {
        v = (lane < nw) ? sh[lane] : 0.f;
        #pragma unroll
        for (int o = 16; o > 0; o >>= 1) v += __shfl_xor_sync(0xffffffffu, v, o);
        if (lane == 0) sh[0] = v;
    }
    __syncthreads();
    return sh[0];
}

// ---------------- W prep: fused 7-way transpose [K][N] fp32 -> [N][K] fp16 --
struct TP7 {
    const float* in[7];
    __half* out[7];
    int K[7], N[7];
    int cum[8];
};
__global__ void transpose_all_kernel(TP7 p) {
    __shared__ float tile[64][33];
    int flat = blockIdx.x;
    int s = 0;
    #pragma unroll
    for (int i = 1; i < 7; i++) s += (flat >= p.cum[i]);
    int id = flat - p.cum[s];
    int K = p.K[s], N = p.N[s];
    int ntl = N >> 5;
    int k0 = (id / ntl) * 64, n0 = (id % ntl) * 32;
    const float* in = p.in[s];
    __half* out = p.out[s];
    int tx = threadIdx.x, ty = threadIdx.y;   // (32, 8)
    #pragma unroll
    for (int i = 0; i < 64; i += 8)
        tile[ty + i][tx] = in[(size_t)(k0 + ty + i) * N + n0 + tx];
    __syncthreads();
    #pragma unroll
    for (int i = 0; i < 32; i += 8) {
        int n = n0 + ty + i;
        __half2 v = __floats2half2_rn(tile[tx*2][ty + i], tile[tx*2 + 1][ty + i]);
        *reinterpret_cast<__half2*>(&out[(size_t)n * K + k0 + tx*2]) = v;
    }
}

__global__ void bias_concat_kernel(const float* __restrict__ bk, const float* __restrict__ bv,
                                   const float* __restrict__ bm) {
    int d = blockIdx.x * 256 + threadIdx.x;
    float v = (d < 768) ? bk[d] : ((d < 1536) ? bv[d - 768] : bm[d - 1536]);
    g_bkvm[d] = v;
}

// ---------------- K1: LN1 + router score ----------------
__global__ void ln1_router_kernel(const float* __restrict__ x, const float* __restrict__ g1,
                                  const float* __restrict__ b1, const float* __restrict__ Wr,
                                  const float* __restrict__ br) {
    int tok = blockIdx.x;
    int t = threadIdx.x;   // 256
    const float* xr = x + (size_t)tok * D_;
    __shared__ float sh[32];
    float v[3]; float s = 0.f, sq = 0.f;
    #pragma unroll
    for (int i = 0; i < 3; i++) { float u = xr[t + 256*i]; v[i] = u; s += u; sq += u*u; }
    s  = blockReduceSum(s,  sh);
    sq = blockReduceSum(sq, sh);
    float mean = s * (1.f/D_);
    float var  = sq * (1.f/D_) - mean*mean;
    float rstd = rsqrtf(var + 1e-5f);
    float dot = 0.f;
    #pragma unroll
    for (int i = 0; i < 3; i++) {
        int d = t + 256*i;
        float nv = (v[i] - mean) * rstd * g1[d] + b1[d];
        g_nh[(size_t)tok*D_ + d] = __float2half_rn(nv);
        dot += nv * Wr[d];
    }
    dot = blockReduceSum(dot, sh);
    if (t == 0) g_scores[tok] = 1.f / (1.f + expf(-(dot + br[0])));
}

// ---------------- K2: exact top-k via bitonic sort ----------
__global__ void topk_kernel() {
    int b = blockIdx.x, t = threadIdx.x;   // 1024 threads
    __shared__ unsigned long long keys[L_];
    __shared__ float sh[32];
    float s0 = g_scores[b*L_ + t];
    float s1 = g_scores[b*L_ + t + 1024];
    keys[t]        = ((unsigned long long)__float_as_uint(s0) << 32) | (unsigned)t;
    keys[t + 1024] = ((unsigned long long)__float_as_uint(s1) << 32) | (unsigned)(t + 1024);
    g_selpos[b*L_ + t] = -1;
    g_selpos[b*L_ + t + 1024] = -1;
    float tot = blockReduceSum(s0 + s1, sh);
    if (t == 0) g_ssum[b] = tot + 1e-6f;
    for (unsigned k = 2; k <= (unsigned)L_; k <<= 1) {
        for (unsigned j = k >> 1; j > 0; j >>= 1) {
            __syncthreads();
            for (unsigned i = t; i < (unsigned)L_; i += 1024) {
                unsigned ixj = i ^ j;
                if (ixj > i) {
                    unsigned long long a = keys[i], c = keys[ixj];
                    bool up = ((i & k) == 0);
                    if ((a > c) == up) { keys[i] = c; keys[ixj] = a; }
                }
            }
        }
    }
    __syncthreads();
    if (t < KS_) {
        int tok = (int)(unsigned)(keys[t] & 0xffffffffULL);
        g_selidx[b*KS_ + t] = b*L_ + tok;
        g_selpos[b*L_ + tok] = b*KS_ + t;
    }
}

// ---------------- K3: coherence-weighted pooling (reads fp16 normed) -------
__global__ void pooled_part_kernel() {
    int b = blockIdx.y, ch = blockIdx.x;
    int d = threadIdx.x;
    float acc = 0.f;
    int l0 = ch * (L_/16);
    for (int l = l0; l < l0 + L_/16; l++)
        acc += g_scores[b*L_ + l] * __half2float(g_nh[((size_t)(b*L_ + l))*D_ + d]);
    g_ppart[(b*16 + ch)*D_ + d] = acc;
}
__global__ void pooled_fin_kernel() {
    int b = blockIdx.x; int d = threadIdx.x;
    float acc = 0.f;
    #pragma unroll
    for (int c = 0; c < 16; c++) acc += g_ppart[(b*16 + c)*D_ + d];
    g_pooled[b*D_ + d] = acc / g_ssum[b];
}
__global__ void pooledwm_kernel(const float* __restrict__ Wm) {
    int b = blockIdx.y;
    int n = blockIdx.x*256 + threadIdx.x;
    float acc = 0.f;
    for (int d = 0; d < D_; d++) acc += g_pooled[b*D_ + d] * Wm[d*D_ + n];
    g_pooledWm[b*D_ + n] = acc;
}

// ---------------- fp16 GEMM: mma m16n8k16, dual ldmatrix, 3-stage ----------
// C[M,N] = epi( A[M,K] @ Bt[N,K]^T + bias[N] )
// OUT: 0 = f32 C; 1 = GELU -> fp16 Ch; 3 = fp16 Ch; 4 = raw f32 partial (split-K via gridDim.z).
#define RS_  40                   // smem row stride in halves (80 B)
#define HSTG_ (128*RS_*2)         // bytes per stage per operand = 10240
template<int OUT, bool GATHER>
__global__ __launch_bounds__(128)
void gemm_h(const __half* __restrict__ A, const int* __restrict__ gidx,
            const __half* __restrict__ Bt, const float* __restrict__ bias,
            float* __restrict__ C, __half* __restrict__ Ch, int M, int N, int K) {
    __shared__ __align__(128) __half As[3][128][RS_];
    __shared__ __align__(128) __half Bs[3][128][RS_];
    const int tid = threadIdx.x, lane = tid & 31, wid = tid >> 5;
    const int wm = wid & 1, wn = wid >> 1;
    const int g = lane >> 2, t = lane & 3;
    const int m0 = blockIdx.y * 128, n0 = blockIdx.x * 128;
    const int zk = K / (int)gridDim.z;           // K span for this z-slice
    const int z0 = blockIdx.z * zk;

    uint32_t sA = smem_u32(&As[0][0][0]);
    uint32_t sB = smem_u32(&Bs[0][0][0]);

    const __half* asrc[4]; unsigned asz[4]; uint32_t a_dst[4];
    const __half* bsrc[4]; uint32_t b_dst[4];
    #pragma unroll
    for (int j = 0; j < 4; j++) {
        int rl = j*32 + (tid >> 2);
        int ck = (tid & 3) * 8;
        int r = m0 + rl;
        bool v = r < M;
        int gr = v ? (GATHER ? gidx[r] : r) : 0;
        asrc[j]  = A + (size_t)gr*K + z0 + ck;
        asz[j]   = v ? 16u : 0u;
        a_dst[j] = sA + (uint32_t)(rl*RS_ + ck) * 2;
        bsrc[j]  = Bt + (size_t)(n0 + rl)*K + z0 + ck;
        b_dst[j] = sB + (uint32_t)(rl*RS_ + ck) * 2;
    }

    uint32_t a_ld = sA + (uint32_t)((wm*64 + (lane & 7) + ((lane >> 3) & 1)*8)*RS_
                                    + ((lane >> 4) & 1)*8) * 2;
    uint32_t b_ld = sB + (uint32_t)((wn*64 + (lane & 7) + ((lane >> 4) & 1)*8)*RS_
                                    + ((lane >> 3) & 1)*8) * 2;

    float acc[4][8][4] = {};
    const int ntiles = zk >> 5;     // k-tile = 32 halves

    auto issue = [&](int stage, int k0) {
        #pragma unroll
        for (int j = 0; j < 4; j++) cpasync16(a_dst[j] + stage*HSTG_, asrc[j] + k0, asz[j]);
        #pragma unroll
        for (int j = 0; j < 4; j++) cpasync16(b_dst[j] + stage*HSTG_, bsrc[j] + k0, 16u);
        cpcommit();
    };

    issue(0, 0);
    if (ntiles > 1) issue(1, 32);
    for (int it = 0; it < ntiles; it++) {
        int st = it % 3;
        if (it == ntiles - 1) cpwait0(); else cpwait1();
        __syncthreads();
        if (it + 2 < ntiles) issue((it + 2) % 3, (it + 2) << 5);
        #pragma unroll
        for (int kk = 0; kk < 32; kk += 16) {
            uint32_t a[4][4], bb[4][4];
            #pragma unroll
            for (int mt = 0; mt < 4; mt++)
                ldsm4(a[mt], a_ld + st*HSTG_ + mt*(16*RS_*2) + kk*2);
            #pragma unroll
            for (int np = 0; np < 4; np++)
                ldsm4(bb[np], b_ld + st*HSTG_ + np*(16*RS_*2) + kk*2);
            #pragma unroll
            for (int mt = 0; mt < 4; mt++)
                #pragma unroll
                for (int nt = 0; nt < 8; nt++) {
                    uint32_t bf[2] = { bb[nt >> 1][(nt & 1)*2], bb[nt >> 1][(nt & 1)*2 + 1] };
                    mma16n8k16h(acc[mt][nt], a[mt], bf);
                }
        }
        __syncthreads();
    }

    // ---- epilogue ----
    const size_t zout = (OUT == 4) ? (size_t)blockIdx.z * M * N : 0;
    #pragma unroll
    for (int mt = 0; mt < 4; mt++) {
        #pragma unroll
        for (int nt = 0; nt < 8; nt++) {
            int n = n0 + wn*64 + nt*8 + t*2;
            float bi0 = (OUT == 4) ? 0.f : bias[n];
            float bi1 = (OUT == 4) ? 0.f : bias[n + 1];
            #pragma unroll
            for (int half = 0; half < 2; half++) {
                int m = m0 + wm*64 + mt*16 + g + half*8;
                if (m < M) {
                    float v0 = acc[mt][nt][half*2 + 0] + bi0;
                    float v1 = acc[mt][nt][half*2 + 1] + bi1;
                    size_t off = (size_t)m * N + n;
                    if (OUT == 1 || OUT == 3) {
                        if (OUT == 1) {
                            v0 = 0.5f * v0 * (1.f + erff(v0 * 0.70710678118654752f));
                            v1 = 0.5f * v1 * (1.f + erff(v1 * 0.70710678118654752f));
                        }
                        *reinterpret_cast<__half2*>(Ch + off) = __floats2half2_rn(v0, v1);
                    } else {
                        float2 o; o.x = v0; o.y = v1;
                        *(float2*)&C[zout + off] = o;
                    }
                }
            }
        }
    }
}

// FFN2 finish: out = part0 + part1 + bias + h  (float4 over 8192x768)
__global__ __launch_bounds__(256) void ffn2_fin(const float* __restrict__ bf2,
                                                float* __restrict__ out) {
    int i = blockIdx.x * 256 + threadIdx.x;       // float4 index; total 1572864
    const float4* p0 = (const float4*)g_fp2;
    const float4* p1 = (const float4*)(g_fp2 + (size_t)BL_*D_);
    const float4* ph = (const float4*)g_h;
    float4 a = p0[i], b = p1[i], hh = ph[i];
    float4 bi = ((const float4*)bf2)[i % (D_/4)];
    float4 o;
    o.x = a.x + b.x + hh.x + bi.x;
    o.y = a.y + b.y + hh.y + bi.y;
    o.z = a.z + b.z + hh.z + bi.z;
    o.w = a.w + b.w + hh.w + bi.w;
    ((float4*)out)[i] = o;
}

// ---------------- flash attention, split-KV, fp16 mma (R10, validated) -----
#define QST_ 72
#define VST_ 40
__global__ __launch_bounds__(128) void flash_attn() {
    const int it = blockIdx.x, bh = blockIdx.y, sp = blockIdx.z;
    const int b = bh / H_, h = bh % H_;
    const int i0 = it * 64;
    __shared__ __align__(128) __half Qh[64][QST_];
    __shared__ __align__(128) __half Kh[32][QST_];
    __shared__ __align__(128) __half Vt[64][VST_];
    __shared__ __align__(128) __half Ph[4][16][VST_];
    const int tid = threadIdx.x, lane = tid & 31, w = tid >> 5;
    const int g = lane >> 2, t = lane & 3;

    #pragma unroll
    for (int q = 0; q < 4; q++) {
        int idx = q*128 + tid;
        int r = idx >> 3, c8 = (idx & 7) * 8;
        int i = i0 + r;
        uint4 v = make_uint4(0u, 0u, 0u, 0u);
        if (i < KS_) v = *(const uint4*)&g_qselh[((size_t)(b*KS_ + i))*D_ + h*DH_ + c8];
        *(uint4*)&Qh[r][c8] = v;
    }

    const uint32_t a_ldQ = smem_u32(&Qh[0][0])
        + (uint32_t)((w*16 + (lane & 7) + ((lane >> 3) & 1)*8)*QST_ + ((lane >> 4) & 1)*8) * 2;
    const uint32_t b_ldK = smem_u32(&Kh[0][0])
        + (uint32_t)(((lane & 7) + ((lane >> 4) & 1)*8)*QST_ + ((lane >> 3) & 1)*8) * 2;
    const uint32_t b_ldV = smem_u32(&Vt[0][0])
        + (uint32_t)(((lane & 7) + ((lane >> 4) & 1)*8)*VST_ + ((lane >> 3) & 1)*8) * 2;
    const uint32_t a_ldP = smem_u32(&Ph[w][0][0])
        + (uint32_t)(((lane & 7) + ((lane >> 3) & 1)*8)*VST_ + ((lane >> 4) & 1)*8) * 2;

    float accO[8][4] = {};
    float m0r = -1e30f, m1r = -1e30f, l0r = 0.f, l1r = 0.f;
    __syncthreads();

    for (int j0 = sp * JSEG_; j0 < (sp + 1) * JSEG_; j0 += 32) {
        #pragma unroll
        for (int q = 0; q < 4; q++) {
            int idx = q*128 + tid;
            int r = idx >> 4, c4 = (idx & 15) * 4;
            float4 kv = *(const float4*)&g_kvm[((size_t)(b*L_ + j0 + r))*NKVM_ + h*DH_ + c4];
            *reinterpret_cast<__half2*>(&Kh[r][c4])     = __floats2half2_rn(kv.x, kv.y);
            *reinterpret_cast<__half2*>(&Kh[r][c4 + 2]) = __floats2half2_rn(kv.z, kv.w);
        }
        #pragma unroll
        for (int q = 0; q < 4; q++) {
            int r = tid & 31;
            int c0 = (q*4 + (tid >> 5)) * 4;
            float4 vv = *(const float4*)&g_kvm[((size_t)(b*L_ + j0 + r))*NKVM_ + 768 + h*DH_ + c0];
            Vt[c0+0][r] = __float2half_rn(vv.x);
            Vt[c0+1][r] = __float2half_rn(vv.y);
            Vt[c0+2][r] = __float2half_rn(vv.z);
            Vt[c0+3][r] = __float2half_rn(vv.w);
        }
        __syncthreads();

        float sacc[4][4] = {};
        #pragma unroll
        for (int ks = 0; ks < 4; ks++) {
            uint32_t a[4], bb[2][4];
            ldsm4(a, a_ldQ + ks*32);
            ldsm4(bb[0], b_ldK + ks*32);
            ldsm4(bb[1], b_ldK + 16*QST_*2 + ks*32);
            #pragma unroll
            for (int nt = 0; nt < 4; nt++) {
                uint32_t bf[2] = { bb[nt >> 1][(nt & 1)*2], bb[nt >> 1][(nt & 1)*2 + 1] };
                mma16n8k16h(sacc[nt], a, bf);
            }
        }
        float cm0 = -1e30f, cm1 = -1e30f;
        #pragma unroll
        for (int nt = 0; nt < 4; nt++) {
            sacc[nt][0] *= 0.125f; sacc[nt][1] *= 0.125f;
            sacc[nt][2] *= 0.125f; sacc[nt][3] *= 0.125f;
            cm0 = fmaxf(cm0, fmaxf(sacc[nt][0], sacc[nt][1]));
            cm1 = fmaxf(cm1, fmaxf(sacc[nt][2], sacc[nt][3]));
        }
        cm0 = fmaxf(cm0, __shfl_xor_sync(0xffffffffu, cm0, 1));
        cm0 = fmaxf(cm0, __shfl_xor_sync(0xffffffffu, cm0, 2));
        cm1 = fmaxf(cm1, __shfl_xor_sync(0xffffffffu, cm1, 1));
        cm1 = fmaxf(cm1, __shfl_xor_sync(0xffffffffu, cm1, 2));
        float mn0 = fmaxf(m0r, cm0), mn1 = fmaxf(m1r, cm1);
        float al0 = expf(m0r - mn0), al1 = expf(m1r - mn1);
        m0r = mn0; m1r = mn1;
        float s0 = 0.f, s1 = 0.f;
        #pragma unroll
        for (int nt = 0; nt < 4; nt++) {
            float p0 = expf(sacc[nt][0] - mn0);
            float p1 = expf(sacc[nt][1] - mn0);
            float p2 = expf(sacc[nt][2] - mn1);
            float p3 = expf(sacc[nt][3] - mn1);
            s0 += p0 + p1; s1 += p2 + p3;
            int c = nt*8 + t*2;
            *reinterpret_cast<__half2*>(&Ph[w][g][c])     = __floats2half2_rn(p0, p1);
            *reinterpret_cast<__half2*>(&Ph[w][g + 8][c]) = __floats2half2_rn(p2, p3);
        }
        s0 += __shfl_xor_sync(0xffffffffu, s0, 1);
        s0 += __shfl_xor_sync(0xffffffffu, s0, 2);
        s1 += __shfl_xor_sync(0xffffffffu, s1, 1);
        s1 += __shfl_xor_sync(0xffffffffu, s1, 2);
        l0r = l0r*al0 + s0; l1r = l1r*al1 + s1;
        #pragma unroll
        for (int nt = 0; nt < 8; nt++) {
            accO[nt][0] *= al0; accO[nt][1] *= al0;
            accO[nt][2] *= al1; accO[nt][3] *= al1;
        }
        __syncwarp();
        #pragma unroll
        for (int ks = 0; ks < 2; ks++) {
            uint32_t a[4];
            ldsm4(a, a_ldP + ks*32);
            uint32_t bb[4][4];
            #pragma unroll
            for (int np = 0; np < 4; np++)
                ldsm4(bb[np], b_ldV + np*(16*VST_*2) + ks*32);
            #pragma unroll
            for (int nt = 0; nt < 8; nt++) {
                uint32_t bf[2] = { bb[nt >> 1][(nt & 1)*2], bb[nt >> 1][(nt & 1)*2 + 1] };
                mma16n8k16h(accO[nt], a, bf);
            }
        }
        __syncthreads();
    }

    const size_t slot0 = (size_t)(bh*NSPL_ + sp)*320 + it*64 + w*16 + g;
    const size_t slot1 = slot0 + 8;
    if (t == 0) {
        g_pm[slot0] = m0r; g_pl[slot0] = l0r;
        g_pm[slot1] = m1r; g_pl[slot1] = l1r;
    }
    #pragma unroll
    for (int nt = 0; nt < 8; nt++) {
        int c = nt*8 + t*2;
        g_po[slot0*64 + c]     = accO[nt][0];
        g_po[slot0*64 + c + 1] = accO[nt][1];
        g_po[slot1*64 + c]     = accO[nt][2];
        g_po[slot1*64 + c + 1] = accO[nt][3];
    }
}

// combine split-KV partials -> g_ctxh (fp16, feeds Wo GEMM)
__global__ __launch_bounds__(256) void attn_combine() {
    const int it = blockIdx.x, bh = blockIdx.y;
    const int b = bh / H_, h = bh % H_;
    __shared__ float ws[64][NSPL_];
    __shared__ float linv[64];
    const int tid = threadIdx.x;
    if (tid < 64) {
        size_t base = (size_t)(bh*NSPL_)*320 + it*64 + tid;
        float mv[NSPL_]; float m = -1e30f;
        #pragma unroll
        for (int s = 0; s < NSPL_; s++) { mv[s] = g_pm[base + (size_t)s*320]; m = fmaxf(m, mv[s]); }
        float l = 0.f;
        #pragma unroll
        for (int s = 0; s < NSPL_; s++) {
            float wv = expf(mv[s] - m);
            ws[tid][s] = wv;
            l += g_pl[base + (size_t)s*320] * wv;
        }
        linv[tid] = 1.f / l;
    }
    __syncthreads();
    #pragma unroll
    for (int q = 0; q < 16; q++) {
        int idx = q*256 + tid;
        int r = idx >> 6, c = idx & 63;
        int i = it*64 + r;
        if (i < KS_) {
            size_t slot = (size_t)(bh*NSPL_)*320 + it*64 + r;
            float acc = 0.f;
            #pragma unroll
            for (int s = 0; s < NSPL_; s++)
                acc += g_po[(slot + (size_t)s*320)*64 + c] * ws[r][s];
            g_ctxh[((size_t)(b*KS_ + i))*D_ + h*DH_ + c] = __float2half_rn(acc * linv[r]);
        }
    }
}

// ---------------- merge paths + residual + LN2 ----------------
__global__ void merge_ln2_kernel(const float* __restrict__ x, const float* __restrict__ g2,
                                 const float* __restrict__ b2) {
    int tok = blockIdx.x;
    int b = tok >> 11;
    int t = threadIdx.x;
    int pos = g_selpos[tok];
    float sc = g_scores[tok];
    __shared__ float sh[32];
    float hv[3]; float s = 0.f, sq = 0.f;
    #pragma unroll
    for (int i = 0; i < 3; i++) {
        int d = t + 256*i;
        float mg;
        if (pos >= 0) mg = g_attno[(size_t)pos*D_ + d];
        else          mg = g_kvm[(size_t)tok*NKVM_ + 1536 + d] + sc * g_pooledWm[b*D_ + d];
        float u = x[(size_t)tok*D_ + d] + mg;
        hv[i] = u;
        g_h[(size_t)tok*D_ + d] = u;
        s += u; sq += u*u;
    }
    s  = blockReduceSum(s,  sh);
    sq = blockReduceSum(sq, sh);
    float mean = s * (1.f/D_);
    float rstd = rsqrtf(sq*(1.f/D_) - mean*mean + 1e-5f);
    #pragma unroll
    for (int i = 0; i < 3; i++) {
        int d = t + 256*i;
        g_n2h[(size_t)tok*D_ + d] = __float2half_rn((hv[i] - mean) * rstd * g2[d] + b2[d]);
    }
}

// ---------------- host launch ----------------
extern "C" void kernel_launch(void* const* d_in, const int* in_sizes, int n_in,
                              void* d_out, int out_size) {
    (void)in_sizes; (void)n_in; (void)out_size;
    const float* x   = (const float*)d_in[0];
    const float* g1  = (const float*)d_in[1];
    const float* b1  = (const float*)d_in[2];
    const float* g2  = (const float*)d_in[3];
    const float* b2  = (const float*)d_in[4];
    const float* Wr  = (const float*)d_in[5];
    const float* br  = (const float*)d_in[6];
    const float* Wq  = (const float*)d_in[7];
    const float* bq  = (const float*)d_in[8];
    const float* Wk  = (const float*)d_in[9];
    const float* bk  = (const float*)d_in[10];
    const float* Wv  = (const float*)d_in[11];
    const float* bv  = (const float*)d_in[12];
    const float* Wo  = (const float*)d_in[13];
    const float* bo  = (const float*)d_in[14];
    const float* Wm  = (const float*)d_in[15];
    const float* bm  = (const float*)d_in[16];
    const float* W1  = (const float*)d_in[17];
    const float* bf1 = (const float*)d_in[18];
    const float* W2  = (const float*)d_in[19];
    const float* bf2 = (const float*)d_in[20];
    float* out = (float*)d_out;

    float *p_kvm, *p_bkvm, *p_attno;
    __half *p_nh, *p_qselh, *p_ctxh, *p_n2h, *p_th, *p_whuf;
    int* p_selidx;
    cudaGetSymbolAddress((void**)&p_nh,     g_nh);
    cudaGetSymbolAddress((void**)&p_kvm,    g_kvm);
    cudaGetSymbolAddress((void**)&p_bkvm,   g_bkvm);
    cudaGetSymbolAddress((void**)&p_qselh,  g_qselh);
    cudaGetSymbolAddress((void**)&p_ctxh,   g_ctxh);
    cudaGetSymbolAddress((void**)&p_attno,  g_attno);
    cudaGetSymbolAddress((void**)&p_n2h,    g_n2h);
    cudaGetSymbolAddress((void**)&p_th,     g_th);
    cudaGetSymbolAddress((void**)&p_whuf,   g_whuf);
    cudaGetSymbolAddress((void**)&p_selidx, g_selidx);
    float* p_fp2;
    cudaGetSymbolAddress((void**)&p_fp2,    g_fp2);

    __half* rKVM = p_whuf;                         // [2304][768]
    __half* rWq  = p_whuf + 3*(size_t)WSZ_;
    __half* rWo  = p_whuf + 4*(size_t)WSZ_;
    __half* rW1  = p_whuf + 5*(size_t)WSZ_;
    __half* rW2  = rW1 + (size_t)W1SZ_;

    // 0. fused weight prep (single launch)
    TP7 tp;
    tp.in[0]=Wk; tp.out[0]=rKVM + 0*(size_t)WSZ_; tp.K[0]=D_; tp.N[0]=D_;
    tp.in[1]=Wv; tp.out[1]=rKVM + 1*(size_t)WSZ_; tp.K[1]=D_; tp.N[1]=D_;
    tp.in[2]=Wm; tp.out[2]=rKVM + 2*(size_t)WSZ_; tp.K[2]=D_; tp.N[2]=D_;
    tp.in[3]=Wq; tp.out[3]=rWq;                   tp.K[3]=D_; tp.N[3]=D_;
    tp.in[4]=Wo; tp.out[4]=rWo;                   tp.K[4]=D_; tp.N[4]=D_;
    tp.in[5]=W1; tp.out[5]=rW1;                   tp.K[5]=D_; tp.N[5]=F_;
    tp.in[6]=W2; tp.out[6]=rW2;                   tp.K[6]=F_; tp.N[6]=D_;
    int total = 0;
    for (int s = 0; s < 7; s++) {
        tp.cum[s] = total;
        total += (tp.K[s]/64) * (tp.N[s]/32);
    }
    tp.cum[7] = total;   // 3744
    transpose_all_kernel<<<total, dim3(32, 8)>>>(tp);
    bias_concat_kernel<<<9, 256>>>(bk, bv, bm);
    // 1. LN1 + router
    ln1_router_kernel<<<BL_, 256>>>(x, g1, b1, Wr, br);
    // 2. top-k
    topk_kernel<<<B_, 1024>>>();
    // 3. pooling path
    pooled_part_kernel<<<dim3(16, B_), D_>>>();
    pooled_fin_kernel<<<B_, D_>>>();
    pooledwm_kernel<<<dim3(3, B_), 256>>>(Wm);
    // 4. fused K|V|mix projection (N=2304), fp16 mma
    gemm_h<0,false><<<dim3(NKVM_/128, BL_/128), 128>>>(p_nh, nullptr, rKVM, p_bkvm, p_kvm, nullptr, BL_, NKVM_, D_);
    // 5. Q for selected rows (gather) -> fp16
    gemm_h<3,true ><<<dim3(D_/128, (MSEL_+127)/128), 128>>>(p_nh, p_selidx, rWq, bq, nullptr, p_qselh, MSEL_, D_, D_);
    // 6. flash attention (split-KV, fp16 mma) + combine
    flash_attn<<<dim3(5, B_*H_, NSPL_), 128>>>();
    attn_combine<<<dim3(5, B_*H_), 256>>>();
    gemm_h<0,false><<<dim3(D_/128, (MSEL_+127)/128), 128>>>(p_ctxh, nullptr, rWo, bo, p_attno, nullptr, MSEL_, D_, D_);
    // 7. merge + residual + LN2
    merge_ln2_kernel<<<BL_, 256>>>(x, g2, b2);
    // 8. FFN: FFN1 GELU -> fp16; FFN2 split-K=2 -> partials -> fin(out)
    gemm_h<1,false><<<dim3(F_/128, BL_/128), 128>>>(p_n2h, nullptr, rW1, bf1, nullptr, p_th, BL_, F_, D_);
    gemm_h<4,false><<<dim3(D_/128, BL_/128, 2), 128>>>(p_th, nullptr, rW2, nullptr, p_fp2, nullptr, BL_, D_, F_);
    ffn2_fin<<<(BL_*D_/4)/256, 256>>>(bf2, out);
}

// round 12
// speedup vs baseline: 2.4483x; 1.0232x over previous
#include <cuda_runtime.h>
#include <cuda_fp16.h>
#include <math.h>
#include <stdint.h>

// Problem constants
#define B_    4
#define L_    2048
#define D_    768
#define H_    12
#define DH_   64
#define F_    3072
#define KS_   307              // round(0.15 * 2048)
#define BL_   (B_*L_)          // 8192
#define MSEL_ (B_*KS_)         // 1228
#define NKVM_ 2304             // 3*D concat (K,V,M)
#define NSPL_ 4                // KV splits in flash attention
#define JSEG_ (L_/NSPL_)       // 512
#define QZ_   4                // split-K for Q/Wo GEMMs

#define WSZ_  589824           // 768*768
#define W1SZ_ 2359296          // 768*3072

// ---------------- scratch (static device globals; allocation-free) ----------
__device__ __align__(16) __half g_nh[BL_*(size_t)D_];   // fp16 LN1 output
__device__ float g_scores[BL_];
__device__ float g_ssum[B_];
__device__ int   g_selidx[MSEL_];
__device__ int   g_selpos[BL_];
__device__ float g_ppart[B_*16*D_];
__device__ float g_pooled[B_*D_];
__device__ float g_pooledWm[B_*D_];
__device__ float g_kvm[BL_*(size_t)NKVM_];    // [tok][ K(768) | V(768) | mixb(768) ]
__device__ float g_bkvm[NKVM_];
__device__ __align__(16) __half g_qselh[MSEL_*(size_t)D_];
__device__ float g_po[(size_t)B_*H_*NSPL_*320*64];   // attention partial O
__device__ float g_pm[B_*H_*NSPL_*320];
__device__ float g_pl[B_*H_*NSPL_*320];
__device__ __align__(16) __half g_ctxh[MSEL_*(size_t)D_];
__device__ float g_attno[MSEL_*(size_t)D_];
__device__ float g_h[BL_*(size_t)D_];
__device__ __align__(16) __half g_n2h[BL_*(size_t)D_];
__device__ __align__(16) __half g_th[BL_*(size_t)F_];
__device__ float g_fp2[2*(size_t)BL_*D_];     // split-K partials (reused: Q, Wo, FFN2)
__device__ __align__(16) __half g_whuf[5*(size_t)WSZ_ + 2*(size_t)W1SZ_];  // fp16 [N][K] weights

// ---------------- small helpers ----------------
__device__ __forceinline__ uint32_t smem_u32(const void* p) {
    uint32_t a;
    asm("{ .reg .u64 t; cvta.to.shared.u64 t, %1; cvt.u32.u64 %0, t; }"
        : "=r"(a) : "l"(p));
    return a;
}
__device__ __forceinline__ void mma16n8k16h(float* c, const uint32_t* a, const uint32_t* b) {
    asm volatile(
        "mma.sync.aligned.m16n8k16.row.col.f32.f16.f16.f32 "
        "{%0,%1,%2,%3}, {%4,%5,%6,%7}, {%8,%9}, {%0,%1,%2,%3};"
        : "+f"(c[0]), "+f"(c[1]), "+f"(c[2]), "+f"(c[3])
        : "r"(a[0]), "r"(a[1]), "r"(a[2]), "r"(a[3]), "r"(b[0]), "r"(b[1]));
}
__device__ __forceinline__ void ldsm4(uint32_t* r, uint32_t addr) {
    asm volatile("ldmatrix.sync.aligned.m8n8.x4.shared.b16 {%0,%1,%2,%3}, [%4];"
        : "=r"(r[0]), "=r"(r[1]), "=r"(r[2]), "=r"(r[3]) : "r"(addr));
}
__device__ __forceinline__ void cpasync16(uint32_t dst, const void* src, unsigned sz) {
    asm volatile("cp.async.cg.shared.global [%0], [%1], 16, %2;"
        :: "r"(dst), "l"(src), "r"(sz));
}
__device__ __forceinline__ void cpcommit() { asm volatile("cp.async.commit_group;"); }
__device__ __forceinline__ void cpwait0()  { asm volatile("cp.async.wait_group 0;"); }
__device__ __forceinline__ void cpwait1()  { asm volatile("cp.async.wait_group 1;"); }

// ---------------- reductions ----------------
__device__ __forceinline__ float blockReduceSum(float v, float* sh) {
    __syncthreads();
    int lane = threadIdx.x & 31, w = threadIdx.x >> 5;
    #pragma unroll
    for (int o = 16; o > 0; o >>= 1) v += __shfl_xor_sync(0xffffffffu, v, o);
    if (lane == 0) sh[w] = v;
    __syncthreads();
    int nw = (blockDim.x + 31) >> 5;
    if (w == 0) {
        v = (lane < nw) ? sh[lane] : 0.f;
        #pragma unroll
        for (int o = 16; o > 0; o >>= 1) v += __shfl_xor_sync(0xffffffffu, v, o);
        if (lane == 0) sh[0] = v;
    }
    __syncthreads();
    return sh[0];
}

// ---------------- W prep: fused 7-way transpose [K][N] fp32 -> [N][K] fp16 --
struct TP7 {
    const float* in[7];
    __half* out[7];
    int K[7], N[7];
    int cum[8];
};
__global__ void transpose_all_kernel(TP7 p) {
    __shared__ float tile[64][33];
    int flat = blockIdx.x;
    int s = 0;
    #pragma unroll
    for (int i = 1; i < 7; i++) s += (flat >= p.cum[i]);
    int id = flat - p.cum[s];
    int K = p.K[s], N = p.N[s];
    int ntl = N >> 5;
    int k0 = (id / ntl) * 64, n0 = (id % ntl) * 32;
    const float* in = p.in[s];
    __half* out = p.out[s];
    int tx = threadIdx.x, ty = threadIdx.y;   // (32, 8)
    #pragma unroll
    for (int i = 0; i < 64; i += 8)
        tile[ty + i][tx] = in[(size_t)(k0 + ty + i) * N + n0 + tx];
    __syncthreads();
    #pragma unroll
    for (int i = 0; i < 32; i += 8) {
        int n = n0 + ty + i;
        __half2 v = __floats2half2_rn(tile[tx*2][ty + i], tile[tx*2 + 1][ty + i]);
        *reinterpret_cast<__half2*>(&out[(size_t)n * K + k0 + tx*2]) = v;
    }
}

__global__ void bias_concat_kernel(const float* __restrict__ bk, const float* __restrict__ bv,
                                   const float* __restrict__ bm) {
    int d = blockIdx.x * 256 + threadIdx.x;
    float v = (d < 768) ? bk[d] : ((d < 1536) ? bv[d - 768] : bm[d - 1536]);
    g_bkvm[d] = v;
}

// ---------------- K1: LN1 + router score ----------------
__global__ void ln1_router_kernel(const float* __restrict__ x, const float* __restrict__ g1,
                                  const float* __restrict__ b1, const float* __restrict__ Wr,
                                  const float* __restrict__ br) {
    int tok = blockIdx.x;
    int t = threadIdx.x;   // 256
    const float* xr = x + (size_t)tok * D_;
    __shared__ float sh[32];
    float v[3]; float s = 0.f, sq = 0.f;
    #pragma unroll
    for (int i = 0; i < 3; i++) { float u = xr[t + 256*i]; v[i] = u; s += u; sq += u*u; }
    s  = blockReduceSum(s,  sh);
    sq = blockReduceSum(sq, sh);
    float mean = s * (1.f/D_);
    float var  = sq * (1.f/D_) - mean*mean;
    float rstd = rsqrtf(var + 1e-5f);
    float dot = 0.f;
    #pragma unroll
    for (int i = 0; i < 3; i++) {
        int d = t + 256*i;
        float nv = (v[i] - mean) * rstd * g1[d] + b1[d];
        g_nh[(size_t)tok*D_ + d] = __float2half_rn(nv);
        dot += nv * Wr[d];
    }
    dot = blockReduceSum(dot, sh);
    if (t == 0) g_scores[tok] = 1.f / (1.f + expf(-(dot + br[0])));
}

// ---------------- K2: exact top-k via histogram select ----------------------
// Selection SET identical to full sort by (score,idx); slot order within the
// "strictly below threshold" group is atomic-arbitrary, which only permutes an
// intermediate layout (all consumers map via selidx/selpos consistently).
__global__ void topk_kernel() {
    int b = blockIdx.x, t = threadIdx.x;   // 1024 threads
    __shared__ int hist[2048];
    __shared__ unsigned long long cand[2048];
    __shared__ float sh[32];
    __shared__ int s_thr, s_below, s_ncand, s_ndir;
    hist[t] = 0; hist[t + 1024] = 0;
    if (t == 0) { s_ncand = 0; s_ndir = 0; }
    float s0 = g_scores[b*L_ + t];
    float s1 = g_scores[b*L_ + t + 1024];
    g_selpos[b*L_ + t] = -1;
    g_selpos[b*L_ + t + 1024] = -1;
    float tot = blockReduceSum(s0 + s1, sh);   // includes syncs; hist init done before
    if (t == 0) g_ssum[b] = tot + 1e-6f;
    __syncthreads();
    unsigned u0 = __float_as_uint(s0) >> 21;   // 11-bit bin, monotonic for s >= 0
    unsigned u1 = __float_as_uint(s1) >> 21;
    atomicAdd(&hist[u0], 1);
    atomicAdd(&hist[u1], 1);
    __syncthreads();
    // inclusive prefix (Hillis-Steele over 2048, 2 elems/thread)
    for (int off = 1; off < 2048; off <<= 1) {
        int e0 = t, e1 = t + 1024;
        int v0 = (e0 >= off) ? hist[e0 - off] : 0;
        int v1 = (e1 >= off) ? hist[e1 - off] : 0;
        __syncthreads();
        hist[e0] += v0;
        hist[e1] += v1;
        __syncthreads();
    }
    // threshold bin: first bin with cum >= KS_
    #pragma unroll
    for (int q = 0; q < 2; q++) {
        int bin = t + q*1024;
        int below = (bin == 0) ? 0 : hist[bin - 1];
        if (hist[bin] >= KS_ && below < KS_) { s_thr = bin; s_below = below; }
    }
    __syncthreads();
    const int thr = s_thr, below = s_below;
    // pass 2: direct-select below-threshold; collect threshold-bin candidates
    #pragma unroll
    for (int q = 0; q < 2; q++) {
        int tok = t + q*1024;
        float sv = q ? s1 : s0;
        unsigned uv = q ? u1 : u0;
        if ((int)uv < thr) {
            int slot = atomicAdd(&s_ndir, 1);
            g_selidx[b*KS_ + slot] = b*L_ + tok;
            g_selpos[b*L_ + tok] = b*KS_ + slot;
        } else if ((int)uv == thr) {
            int c = atomicAdd(&s_ncand, 1);
            cand[c] = ((unsigned long long)__float_as_uint(sv) << 32) | (unsigned)tok;
        }
    }
    __syncthreads();
    // sort candidates (ascending by (score,idx)), take first (KS_ - below)
    int ncand = s_ncand;
    int P = 1; while (P < ncand) P <<= 1;
    for (int i = t; i < P; i += 1024)
        if (i >= ncand) cand[i] = 0xFFFFFFFFFFFFFFFFULL;
    __syncthreads();
    for (int k = 2; k <= P; k <<= 1) {
        for (int j = k >> 1; j > 0; j >>= 1) {
            for (int i = t; i < P; i += 1024) {
                int ixj = i ^ j;
                if (ixj > i) {
                    unsigned long long a = cand[i], c = cand[ixj];
                    bool up = ((i & k) == 0);
                    if ((a > c) == up) { cand[i] = c; cand[ixj] = a; }
                }
            }
            __syncthreads();
        }
    }
    int need = KS_ - below;
    if (t < need) {
        int tok = (int)(unsigned)(cand[t] & 0xffffffffULL);
        int slot = below + t;
        g_selidx[b*KS_ + slot] = b*L_ + tok;
        g_selpos[b*L_ + tok] = b*KS_ + slot;
    }
}

// ---------------- K3: coherence-weighted pooling (reads fp16 normed) -------
__global__ void pooled_part_kernel() {
    int b = blockIdx.y, ch = blockIdx.x;
    int d = threadIdx.x;
    float acc = 0.f;
    int l0 = ch * (L_/16);
    for (int l = l0; l < l0 + L_/16; l++)
        acc += g_scores[b*L_ + l] * __half2float(g_nh[((size_t)(b*L_ + l))*D_ + d]);
    g_ppart[(b*16 + ch)*D_ + d] = acc;
}
__global__ void pooled_fin_kernel() {
    int b = blockIdx.x; int d = threadIdx.x;
    float acc = 0.f;
    #pragma unroll
    for (int c = 0; c < 16; c++) acc += g_ppart[(b*16 + c)*D_ + d];
    g_pooled[b*D_ + d] = acc / g_ssum[b];
}
__global__ void pooledwm_kernel(const float* __restrict__ Wm) {
    int b = blockIdx.y;
    int n = blockIdx.x*256 + threadIdx.x;
    float acc = 0.f;
    for (int d = 0; d < D_; d++) acc += g_pooled[b*D_ + d] * Wm[d*D_ + n];
    g_pooledWm[b*D_ + n] = acc;
}

// ---------------- fp16 GEMM: mma m16n8k16, dual ldmatrix, 3-stage ----------
// C[M,N] = epi( A[M,K] @ Bt[N,K]^T + bias[N] )
// OUT: 0 = f32 C; 1 = GELU -> fp16 Ch; 3 = fp16 Ch; 4 = raw f32 partial (split-K via gridDim.z).
#define RS_  40                   // smem row stride in halves (80 B)
#define HSTG_ (128*RS_*2)         // bytes per stage per operand = 10240
template<int OUT, bool GATHER>
__global__ __launch_bounds__(128)
void gemm_h(const __half* __restrict__ A, const int* __restrict__ gidx,
            const __half* __restrict__ Bt, const float* __restrict__ bias,
            float* __restrict__ C, __half* __restrict__ Ch, int M, int N, int K) {
    __shared__ __align__(128) __half As[3][128][RS_];
    __shared__ __align__(128) __half Bs[3][128][RS_];
    const int tid = threadIdx.x, lane = tid & 31, wid = tid >> 5;
    const int wm = wid & 1, wn = wid >> 1;
    const int g = lane >> 2, t = lane & 3;
    const int m0 = blockIdx.y * 128, n0 = blockIdx.x * 128;
    const int zk = K / (int)gridDim.z;
    const int z0 = blockIdx.z * zk;

    uint32_t sA = smem_u32(&As[0][0][0]);
    uint32_t sB = smem_u32(&Bs[0][0][0]);

    const __half* asrc[4]; unsigned asz[4]; uint32_t a_dst[4];
    const __half* bsrc[4]; uint32_t b_dst[4];
    #pragma unroll
    for (int j = 0; j < 4; j++) {
        int rl = j*32 + (tid >> 2);
        int ck = (tid & 3) * 8;
        int r = m0 + rl;
        bool v = r < M;
        int gr = v ? (GATHER ? gidx[r] : r) : 0;
        asrc[j]  = A + (size_t)gr*K + z0 + ck;
        asz[j]   = v ? 16u : 0u;
        a_dst[j] = sA + (uint32_t)(rl*RS_ + ck) * 2;
        bsrc[j]  = Bt + (size_t)(n0 + rl)*K + z0 + ck;
        b_dst[j] = sB + (uint32_t)(rl*RS_ + ck) * 2;
    }

    uint32_t a_ld = sA + (uint32_t)((wm*64 + (lane & 7) + ((lane >> 3) & 1)*8)*RS_
                                    + ((lane >> 4) & 1)*8) * 2;
    uint32_t b_ld = sB + (uint32_t)((wn*64 + (lane & 7) + ((lane >> 4) & 1)*8)*RS_
                                    + ((lane >> 3) & 1)*8) * 2;

    float acc[4][8][4] = {};
    const int ntiles = zk >> 5;

    auto issue = [&](int stage, int k0) {
        #pragma unroll
        for (int j = 0; j < 4; j++) cpasync16(a_dst[j] + stage*HSTG_, asrc[j] + k0, asz[j]);
        #pragma unroll
        for (int j = 0; j < 4; j++) cpasync16(b_dst[j] + stage*HSTG_, bsrc[j] + k0, 16u);
        cpcommit();
    };

    issue(0, 0);
    if (ntiles > 1) issue(1, 32);
    for (int it = 0; it < ntiles; it++) {
        int st = it % 3;
        if (it == ntiles - 1) cpwait0(); else cpwait1();
        __syncthreads();
        if (it + 2 < ntiles) issue((it + 2) % 3, (it + 2) << 5);
        #pragma unroll
        for (int kk = 0; kk < 32; kk += 16) {
            uint32_t a[4][4], bb[4][4];
            #pragma unroll
            for (int mt = 0; mt < 4; mt++)
                ldsm4(a[mt], a_ld + st*HSTG_ + mt*(16*RS_*2) + kk*2);
            #pragma unroll
            for (int np = 0; np < 4; np++)
                ldsm4(bb[np], b_ld + st*HSTG_ + np*(16*RS_*2) + kk*2);
            #pragma unroll
            for (int mt = 0; mt < 4; mt++)
                #pragma unroll
                for (int nt = 0; nt < 8; nt++) {
                    uint32_t bf[2] = { bb[nt >> 1][(nt & 1)*2], bb[nt >> 1][(nt & 1)*2 + 1] };
                    mma16n8k16h(acc[mt][nt], a[mt], bf);
                }
        }
        __syncthreads();
    }

    // ---- epilogue ----
    const size_t zout = (OUT == 4) ? (size_t)blockIdx.z * M * N : 0;
    #pragma unroll
    for (int mt = 0; mt < 4; mt++) {
        #pragma unroll
        for (int nt = 0; nt < 8; nt++) {
            int n = n0 + wn*64 + nt*8 + t*2;
            float bi0 = (OUT == 4) ? 0.f : bias[n];
            float bi1 = (OUT == 4) ? 0.f : bias[n + 1];
            #pragma unroll
            for (int half = 0; half < 2; half++) {
                int m = m0 + wm*64 + mt*16 + g + half*8;
                if (m < M) {
                    float v0 = acc[mt][nt][half*2 + 0] + bi0;
                    float v1 = acc[mt][nt][half*2 + 1] + bi1;
                    size_t off = (size_t)m * N + n;
                    if (OUT == 1 || OUT == 3) {
                        if (OUT == 1) {
                            v0 = 0.5f * v0 * (1.f + erff(v0 * 0.70710678118654752f));
                            v1 = 0.5f * v1 * (1.f + erff(v1 * 0.70710678118654752f));
                        }
                        *reinterpret_cast<__half2*>(Ch + off) = __floats2half2_rn(v0, v1);
                    } else {
                        float2 o; o.x = v0; o.y = v1;
                        *(float2*)&C[zout + off] = o;
                    }
                }
            }
        }
    }
}

// finish split-K=QZ_ Q partials -> fp16 qselh (+ bias)
__global__ __launch_bounds__(256) void qfin(const float* __restrict__ bq) {
    int i = blockIdx.x * 256 + threadIdx.x;      // over MSEL_*D_
    if (i < MSEL_*D_) {
        float acc = 0.f;
        #pragma unroll
        for (int z = 0; z < QZ_; z++) acc += g_fp2[(size_t)z*MSEL_*D_ + i];
        g_qselh[i] = __float2half_rn(acc + bq[i % D_]);
    }
}
// finish split-K=QZ_ Wo partials -> f32 attno (+ bias)
__global__ __launch_bounds__(256) void wofin(const float* __restrict__ bo) {
    int i = blockIdx.x * 256 + threadIdx.x;
    if (i < MSEL_*D_) {
        float acc = 0.f;
        #pragma unroll
        for (int z = 0; z < QZ_; z++) acc += g_fp2[(size_t)z*MSEL_*D_ + i];
        g_attno[i] = acc + bo[i % D_];
    }
}

// FFN2 finish: out = part0 + part1 + bias + h  (float4 over 8192x768)
__global__ __launch_bounds__(256) void ffn2_fin(const float* __restrict__ bf2,
                                                float* __restrict__ out) {
    int i = blockIdx.x * 256 + threadIdx.x;
    const float4* p0 = (const float4*)g_fp2;
    const float4* p1 = (const float4*)(g_fp2 + (size_t)BL_*D_);
    const float4* ph = (const float4*)g_h;
    float4 a = p0[i], b = p1[i], hh = ph[i];
    float4 bi = ((const float4*)bf2)[i % (D_/4)];
    float4 o;
    o.x = a.x + b.x + hh.x + bi.x;
    o.y = a.y + b.y + hh.y + bi.y;
    o.z = a.z + b.z + hh.z + bi.z;
    o.w = a.w + b.w + hh.w + bi.w;
    ((float4*)out)[i] = o;
}

// ---------------- flash attention, split-KV, fp16 mma (validated) ----------
#define QST_ 72
#define VST_ 40
__global__ __launch_bounds__(128) void flash_attn() {
    const int it = blockIdx.x, bh = blockIdx.y, sp = blockIdx.z;
    const int b = bh / H_, h = bh % H_;
    const int i0 = it * 64;
    __shared__ __align__(128) __half Qh[64][QST_];
    __shared__ __align__(128) __half Kh[32][QST_];
    __shared__ __align__(128) __half Vt[64][VST_];
    __shared__ __align__(128) __half Ph[4][16][VST_];
    const int tid = threadIdx.x, lane = tid & 31, w = tid >> 5;
    const int g = lane >> 2, t = lane & 3;

    #pragma unroll
    for (int q = 0; q < 4; q++) {
        int idx = q*128 + tid;
        int r = idx >> 3, c8 = (idx & 7) * 8;
        int i = i0 + r;
        uint4 v = make_uint4(0u, 0u, 0u, 0u);
        if (i < KS_) v = *(const uint4*)&g_qselh[((size_t)(b*KS_ + i))*D_ + h*DH_ + c8];
        *(uint4*)&Qh[r][c8] = v;
    }

    const uint32_t a_ldQ = smem_u32(&Qh[0][0])
        + (uint32_t)((w*16 + (lane & 7) + ((lane >> 3) & 1)*8)*QST_ + ((lane >> 4) & 1)*8) * 2;
    const uint32_t b_ldK = smem_u32(&Kh[0][0])
        + (uint32_t)(((lane & 7) + ((lane >> 4) & 1)*8)*QST_ + ((lane >> 3) & 1)*8) * 2;
    const uint32_t b_ldV = smem_u32(&Vt[0][0])
        + (uint32_t)(((lane & 7) + ((lane >> 4) & 1)*8)*VST_ + ((lane >> 3) & 1)*8) * 2;
    const uint32_t a_ldP = smem_u32(&Ph[w][0][0])
        + (uint32_t)(((lane & 7) + ((lane >> 3) & 1)*8)*VST_ + ((lane >> 4) & 1)*8) * 2;

    float accO[8][4] = {};
    float m0r = -1e30f, m1r = -1e30f, l0r = 0.f, l1r = 0.f;
    __syncthreads();

    for (int j0 = sp * JSEG_; j0 < (sp + 1) * JSEG_; j0 += 32) {
        #pragma unroll
        for (int q = 0; q < 4; q++) {
            int idx = q*128 + tid;
            int r = idx >> 4, c4 = (idx & 15) * 4;
            float4 kv = *(const float4*)&g_kvm[((size_t)(b*L_ + j0 + r))*NKVM_ + h*DH_ + c4];
            *reinterpret_cast<__half2*>(&Kh[r][c4])     = __floats2half2_rn(kv.x, kv.y);
            *reinterpret_cast<__half2*>(&Kh[r][c4 + 2]) = __floats2half2_rn(kv.z, kv.w);
        }
        #pragma unroll
        for (int q = 0; q < 4; q++) {
            int r = tid & 31;
            int c0 = (q*4 + (tid >> 5)) * 4;
            float4 vv = *(const float4*)&g_kvm[((size_t)(b*L_ + j0 + r))*NKVM_ + 768 + h*DH_ + c0];
            Vt[c0+0][r] = __float2half_rn(vv.x);
            Vt[c0+1][r] = __float2half_rn(vv.y);
            Vt[c0+2][r] = __float2half_rn(vv.z);
            Vt[c0+3][r] = __float2half_rn(vv.w);
        }
        __syncthreads();

        float sacc[4][4] = {};
        #pragma unroll
        for (int ks = 0; ks < 4; ks++) {
            uint32_t a[4], bb[2][4];
            ldsm4(a, a_ldQ + ks*32);
            ldsm4(bb[0], b_ldK + ks*32);
            ldsm4(bb[1], b_ldK + 16*QST_*2 + ks*32);
            #pragma unroll
            for (int nt = 0; nt < 4; nt++) {
                uint32_t bf[2] = { bb[nt >> 1][(nt & 1)*2], bb[nt >> 1][(nt & 1)*2 + 1] };
                mma16n8k16h(sacc[nt], a, bf);
            }
        }
        float cm0 = -1e30f, cm1 = -1e30f;
        #pragma unroll
        for (int nt = 0; nt < 4; nt++) {
            sacc[nt][0] *= 0.125f; sacc[nt][1] *= 0.125f;
            sacc[nt][2] *= 0.125f; sacc[nt][3] *= 0.125f;
            cm0 = fmaxf(cm0, fmaxf(sacc[nt][0], sacc[nt][1]));
            cm1 = fmaxf(cm1, fmaxf(sacc[nt][2], sacc[nt][3]));
        }
        cm0 = fmaxf(cm0, __shfl_xor_sync(0xffffffffu, cm0, 1));
        cm0 = fmaxf(cm0, __shfl_xor_sync(0xffffffffu, cm0, 2));
        cm1 = fmaxf(cm1, __shfl_xor_sync(0xffffffffu, cm1, 1));
        cm1 = fmaxf(cm1, __shfl_xor_sync(0xffffffffu, cm1, 2));
        float mn0 = fmaxf(m0r, cm0), mn1 = fmaxf(m1r, cm1);
        float al0 = expf(m0r - mn0), al1 = expf(m1r - mn1);
        m0r = mn0; m1r = mn1;
        float s0 = 0.f, s1 = 0.f;
        #pragma unroll
        for (int nt = 0; nt < 4; nt++) {
            float p0 = expf(sacc[nt][0] - mn0);
            float p1 = expf(sacc[nt][1] - mn0);
            float p2 = expf(sacc[nt][2] - mn1);
            float p3 = expf(sacc[nt][3] - mn1);
            s0 += p0 + p1; s1 += p2 + p3;
            int c = nt*8 + t*2;
            *reinterpret_cast<__half2*>(&Ph[w][g][c])     = __floats2half2_rn(p0, p1);
            *reinterpret_cast<__half2*>(&Ph[w][g + 8][c]) = __floats2half2_rn(p2, p3);
        }
        s0 += __shfl_xor_sync(0xffffffffu, s0, 1);
        s0 += __shfl_xor_sync(0xffffffffu, s0, 2);
        s1 += __shfl_xor_sync(0xffffffffu, s1, 1);
        s1 += __shfl_xor_sync(0xffffffffu, s1, 2);
        l0r = l0r*al0 + s0; l1r = l1r*al1 + s1;
        #pragma unroll
        for (int nt = 0; nt < 8; nt++) {
            accO[nt][0] *= al0; accO[nt][1] *= al0;
            accO[nt][2] *= al1; accO[nt][3] *= al1;
        }
        __syncwarp();
        #pragma unroll
        for (int ks = 0; ks < 2; ks++) {
            uint32_t a[4];
            ldsm4(a, a_ldP + ks*32);
            uint32_t bb[4][4];
            #pragma unroll
            for (int np = 0; np < 4; np++)
                ldsm4(bb[np], b_ldV + np*(16*VST_*2) + ks*32);
            #pragma unroll
            for (int nt = 0; nt < 8; nt++) {
                uint32_t bf[2] = { bb[nt >> 1][(nt & 1)*2], bb[nt >> 1][(nt & 1)*2 + 1] };
                mma16n8k16h(accO[nt], a, bf);
            }
        }
        __syncthreads();
    }

    const size_t slot0 = (size_t)(bh*NSPL_ + sp)*320 + it*64 + w*16 + g;
    const size_t slot1 = slot0 + 8;
    if (t == 0) {
        g_pm[slot0] = m0r; g_pl[slot0] = l0r;
        g_pm[slot1] = m1r; g_pl[slot1] = l1r;
    }
    #pragma unroll
    for (int nt = 0; nt < 8; nt++) {
        int c = nt*8 + t*2;
        g_po[slot0*64 + c]     = accO[nt][0];
        g_po[slot0*64 + c + 1] = accO[nt][1];
        g_po[slot1*64 + c]     = accO[nt][2];
        g_po[slot1*64 + c + 1] = accO[nt][3];
    }
}

// combine split-KV partials -> g_ctxh (fp16, feeds Wo GEMM)
__global__ __launch_bounds__(256) void attn_combine() {
    const int it = blockIdx.x, bh = blockIdx.y;
    const int b = bh / H_, h = bh % H_;
    __shared__ float ws[64][NSPL_];
    __shared__ float linv[64];
    const int tid = threadIdx.x;
    if (tid < 64) {
        size_t base = (size_t)(bh*NSPL_)*320 + it*64 + tid;
        float mv[NSPL_]; float m = -1e30f;
        #pragma unroll
        for (int s = 0; s < NSPL_; s++) { mv[s] = g_pm[base + (size_t)s*320]; m = fmaxf(m, mv[s]); }
        float l = 0.f;
        #pragma unroll
        for (int s = 0; s < NSPL_; s++) {
            float wv = expf(mv[s] - m);
            ws[tid][s] = wv;
            l += g_pl[base + (size_t)s*320] * wv;
        }
        linv[tid] = 1.f / l;
    }
    __syncthreads();
    #pragma unroll
    for (int q = 0; q < 16; q++) {
        int idx = q*256 + tid;
        int r = idx >> 6, c = idx & 63;
        int i = it*64 + r;
        if (i < KS_) {
            size_t slot = (size_t)(bh*NSPL_)*320 + it*64 + r;
            float acc = 0.f;
            #pragma unroll
            for (int s = 0; s < NSPL_; s++)
                acc += g_po[(slot + (size_t)s*320)*64 + c] * ws[r][s];
            g_ctxh[((size_t)(b*KS_ + i))*D_ + h*DH_ + c] = __float2half_rn(acc * linv[r]);
        }
    }
}

// ---------------- merge paths + residual + LN2 ----------------
__global__ void merge_ln2_kernel(const float* __restrict__ x, const float* __restrict__ g2,
                                 const float* __restrict__ b2) {
    int tok = blockIdx.x;
    int b = tok >> 11;
    int t = threadIdx.x;
    int pos = g_selpos[tok];
    float sc = g_scores[tok];
    __shared__ float sh[32];
    float hv[3]; float s = 0.f, sq = 0.f;
    #pragma unroll
    for (int i = 0; i < 3; i++) {
        int d = t + 256*i;
        float mg;
        if (pos >= 0) mg = g_attno[(size_t)pos*D_ + d];
        else          mg = g_kvm[(size_t)tok*NKVM_ + 1536 + d] + sc * g_pooledWm[b*D_ + d];
        float u = x[(size_t)tok*D_ + d] + mg;
        hv[i] = u;
        g_h[(size_t)tok*D_ + d] = u;
        s += u; sq += u*u;
    }
    s  = blockReduceSum(s,  sh);
    sq = blockReduceSum(sq, sh);
    float mean = s * (1.f/D_);
    float rstd = rsqrtf(sq*(1.f/D_) - mean*mean + 1e-5f);
    #pragma unroll
    for (int i = 0; i < 3; i++) {
        int d = t + 256*i;
        g_n2h[(size_t)tok*D_ + d] = __float2half_rn((hv[i] - mean) * rstd * g2[d] + b2[d]);
    }
}

// ---------------- host launch ----------------
extern "C" void kernel_launch(void* const* d_in, const int* in_sizes, int n_in,
                              void* d_out, int out_size) {
    (void)in_sizes; (void)n_in; (void)out_size;
    const float* x   = (const float*)d_in[0];
    const float* g1  = (const float*)d_in[1];
    const float* b1  = (const float*)d_in[2];
    const float* g2  = (const float*)d_in[3];
    const float* b2  = (const float*)d_in[4];
    const float* Wr  = (const float*)d_in[5];
    const float* br  = (const float*)d_in[6];
    const float* Wq  = (const float*)d_in[7];
    const float* bq  = (const float*)d_in[8];
    const float* Wk  = (const float*)d_in[9];
    const float* bk  = (const float*)d_in[10];
    const float* Wv  = (const float*)d_in[11];
    const float* bv  = (const float*)d_in[12];
    const float* Wo  = (const float*)d_in[13];
    const float* bo  = (const float*)d_in[14];
    const float* Wm  = (const float*)d_in[15];
    const float* bm  = (const float*)d_in[16];
    const float* W1  = (const float*)d_in[17];
    const float* bf1 = (const float*)d_in[18];
    const float* W2  = (const float*)d_in[19];
    const float* bf2 = (const float*)d_in[20];
    float* out = (float*)d_out;

    float *p_kvm, *p_bkvm, *p_fp2;
    __half *p_nh, *p_qselh, *p_ctxh, *p_n2h, *p_th, *p_whuf;
    int* p_selidx;
    cudaGetSymbolAddress((void**)&p_nh,     g_nh);
    cudaGetSymbolAddress((void**)&p_kvm,    g_kvm);
    cudaGetSymbolAddress((void**)&p_bkvm,   g_bkvm);
    cudaGetSymbolAddress((void**)&p_qselh,  g_qselh);
    cudaGetSymbolAddress((void**)&p_ctxh,   g_ctxh);
    cudaGetSymbolAddress((void**)&p_n2h,    g_n2h);
    cudaGetSymbolAddress((void**)&p_th,     g_th);
    cudaGetSymbolAddress((void**)&p_whuf,   g_whuf);
    cudaGetSymbolAddress((void**)&p_selidx, g_selidx);
    cudaGetSymbolAddress((void**)&p_fp2,    g_fp2);

    __half* rKVM = p_whuf;                         // [2304][768]
    __half* rWq  = p_whuf + 3*(size_t)WSZ_;
    __half* rWo  = p_whuf + 4*(size_t)WSZ_;
    __half* rW1  = p_whuf + 5*(size_t)WSZ_;
    __half* rW2  = rW1 + (size_t)W1SZ_;

    // 0. fused weight prep (single launch)
    TP7 tp;
    tp.in[0]=Wk; tp.out[0]=rKVM + 0*(size_t)WSZ_; tp.K[0]=D_; tp.N[0]=D_;
    tp.in[1]=Wv; tp.out[1]=rKVM + 1*(size_t)WSZ_; tp.K[1]=D_; tp.N[1]=D_;
    tp.in[2]=Wm; tp.out[2]=rKVM + 2*(size_t)WSZ_; tp.K[2]=D_; tp.N[2]=D_;
    tp.in[3]=Wq; tp.out[3]=rWq;                   tp.K[3]=D_; tp.N[3]=D_;
    tp.in[4]=Wo; tp.out[4]=rWo;                   tp.K[4]=D_; tp.N[4]=D_;
    tp.in[5]=W1; tp.out[5]=rW1;                   tp.K[5]=D_; tp.N[5]=F_;
    tp.in[6]=W2; tp.out[6]=rW2;                   tp.K[6]=F_; tp.N[6]=D_;
    int total = 0;
    for (int s = 0; s < 7; s++) {
        tp.cum[s] = total;
        total += (tp.K[s]/64) * (tp.N[s]/32);
    }
    tp.cum[7] = total;
    transpose_all_kernel<<<total, dim3(32, 8)>>>(tp);
    bias_concat_kernel<<<9, 256>>>(bk, bv, bm);
    // 1. LN1 + router
    ln1_router_kernel<<<BL_, 256>>>(x, g1, b1, Wr, br);
    // 2. top-k (histogram select)
    topk_kernel<<<B_, 1024>>>();
    // 3. pooling path
    pooled_part_kernel<<<dim3(16, B_), D_>>>();
    pooled_fin_kernel<<<B_, D_>>>();
    pooledwm_kernel<<<dim3(3, B_), 256>>>(Wm);
    // 4. fused K|V|mix projection (N=2304), fp16 mma
    gemm_h<0,false><<<dim3(NKVM_/128, BL_/128), 128>>>(p_nh, nullptr, rKVM, p_bkvm, p_kvm, nullptr, BL_, NKVM_, D_);
    // 5. Q for selected rows (gather, split-K=4) -> fin -> fp16
    gemm_h<4,true ><<<dim3(D_/128, (MSEL_+127)/128, QZ_), 128>>>(p_nh, p_selidx, rWq, nullptr, p_fp2, nullptr, MSEL_, D_, D_);
    qfin<<<(MSEL_*D_ + 255)/256, 256>>>(bq);
    // 6. flash attention (split-KV, fp16 mma) + combine
    flash_attn<<<dim3(5, B_*H_, NSPL_), 128>>>();
    attn_combine<<<dim3(5, B_*H_), 256>>>();
    // Wo projection (split-K=4) -> fin -> f32 attno
    gemm_h<4,false><<<dim3(D_/128, (MSEL_+127)/128, QZ_), 128>>>(p_ctxh, nullptr, rWo, nullptr, p_fp2, nullptr, MSEL_, D_, D_);
    wofin<<<(MSEL_*D_ + 255)/256, 256>>>(bo);
    // 7. merge + residual + LN2
    merge_ln2_kernel<<<BL_, 256>>>(x, g2, b2);
    // 8. FFN: FFN1 GELU -> fp16; FFN2 split-K=2 -> partials -> fin(out)
    gemm_h<1,false><<<dim3(F_/128, BL_/128), 128>>>(p_n2h, nullptr, rW1, bf1, nullptr, p_th, BL_, F_, D_);
    gemm_h<4,false><<<dim3(D_/128, BL_/128, 2), 128>>>(p_th, nullptr, rW2, nullptr, p_fp2, nullptr, BL_, D_, F_);
    ffn2_fin<<<(BL_*D_/4)/256, 256>>>(bf2, out);
}

// round 13
// speedup vs baseline: 2.5516x; 1.0422x over previous
#include <cuda_runtime.h>
#include <cuda_fp16.h>
#include <math.h>
#include <stdint.h>

// Problem constants
#define B_    4
#define L_    2048
#define D_    768
#define H_    12
#define DH_   64
#define F_    3072
#define KS_   307              // round(0.15 * 2048)
#define BL_   (B_*L_)          // 8192
#define MSEL_ (B_*KS_)         // 1228
#define NKVM_ 2304             // 3*D concat (K,V,M)
#define NSPL_ 4                // KV splits in flash attention
#define JSEG_ (L_/NSPL_)       // 512
#define QZ_   4                // split-K for Q/Wo GEMMs

#define WSZ_  589824           // 768*768
#define W1SZ_ 2359296          // 768*3072

// ---------------- scratch (static device globals; allocation-free) ----------
__device__ __align__(16) __half g_nh[BL_*(size_t)D_];   // fp16 LN1 output
__device__ float g_scores[BL_];
__device__ float g_ssum[B_];
__device__ int   g_selidx[MSEL_];
__device__ int   g_selpos[BL_];
__device__ float g_ppart[B_*16*D_];
__device__ float g_pooled[B_*D_];
__device__ float g_pooledWm[B_*D_];
__device__ __align__(16) __half g_khf[BL_*(size_t)D_];  // fp16 K
__device__ __align__(16) __half g_vhf[BL_*(size_t)D_];  // fp16 V
__device__ float g_mixb[BL_*(size_t)D_];                // fp32 mix base
__device__ float g_bkvm[NKVM_];
__device__ __align__(16) __half g_qselh[MSEL_*(size_t)D_];
__device__ float g_po[(size_t)B_*H_*NSPL_*320*64];   // attention partial O
__device__ float g_pm[B_*H_*NSPL_*320];
__device__ float g_pl[B_*H_*NSPL_*320];
__device__ __align__(16) __half g_ctxh[MSEL_*(size_t)D_];
__device__ float g_attno[MSEL_*(size_t)D_];
__device__ float g_h[BL_*(size_t)D_];
__device__ __align__(16) __half g_n2h[BL_*(size_t)D_];
__device__ __align__(16) __half g_th[BL_*(size_t)F_];
__device__ float g_fp2[2*(size_t)BL_*D_];     // split-K partials (reused: Q, Wo, FFN2)
__device__ __align__(16) __half g_whuf[5*(size_t)WSZ_ + 2*(size_t)W1SZ_];  // fp16 [N][K] weights

// ---------------- small helpers ----------------
__device__ __forceinline__ uint32_t smem_u32(const void* p) {
    uint32_t a;
    asm("{ .reg .u64 t; cvta.to.shared.u64 t, %1; cvt.u32.u64 %0, t; }"
        : "=r"(a) : "l"(p));
    return a;
}
__device__ __forceinline__ void mma16n8k16h(float* c, const uint32_t* a, const uint32_t* b) {
    asm volatile(
        "mma.sync.aligned.m16n8k16.row.col.f32.f16.f16.f32 "
        "{%0,%1,%2,%3}, {%4,%5,%6,%7}, {%8,%9}, {%0,%1,%2,%3};"
        : "+f"(c[0]), "+f"(c[1]), "+f"(c[2]), "+f"(c[3])
        : "r"(a[0]), "r"(a[1]), "r"(a[2]), "r"(a[3]), "r"(b[0]), "r"(b[1]));
}
__device__ __forceinline__ void ldsm4(uint32_t* r, uint32_t addr) {
    asm volatile("ldmatrix.sync.aligned.m8n8.x4.shared.b16 {%0,%1,%2,%3}, [%4];"
        : "=r"(r[0]), "=r"(r[1]), "=r"(r[2]), "=r"(r[3]) : "r"(addr));
}
__device__ __forceinline__ void cpasync16(uint32_t dst, const void* src, unsigned sz) {
    asm volatile("cp.async.cg.shared.global [%0], [%1], 16, %2;"
        :: "r"(dst), "l"(src), "r"(sz));
}
__device__ __forceinline__ void cpcommit() { asm volatile("cp.async.commit_group;"); }
__device__ __forceinline__ void cpwait0()  { asm volatile("cp.async.wait_group 0;"); }
__device__ __forceinline__ void cpwait1()  { asm volatile("cp.async.wait_group 1;"); }

// ---------------- reductions ----------------
__device__ __forceinline__ float blockReduceSum(float v, float* sh) {
    __syncthreads();
    int lane = threadIdx.x & 31, w = threadIdx.x >> 5;
    #pragma unroll
    for (int o = 16; o > 0; o >>= 1) v += __shfl_xor_sync(0xffffffffu, v, o);
    if (lane == 0) sh[w] = v;
    __syncthreads();
    int nw = (blockDim.x + 31) >> 5;
    if (w == 0) {
        v = (lane < nw) ? sh[lane] : 0.f;
        #pragma unroll
        for (int o = 16; o > 0; o >>= 1) v += __shfl_xor_sync(0xffffffffu, v, o);
        if (lane == 0) sh[0] = v;
    }
    __syncthreads();
    return sh[0];
}

// ---------------- W prep: fused 7-way transpose [K][N] fp32 -> [N][K] fp16 --
struct TP7 {
    const float* in[7];
    __half* out[7];
    int K[7], N[7];
    int cum[8];
};
__global__ void transpose_all_kernel(TP7 p) {
    __shared__ float tile[64][33];
    int flat = blockIdx.x;
    int s = 0;
    #pragma unroll
    for (int i = 1; i < 7; i++) s += (flat >= p.cum[i]);
    int id = flat - p.cum[s];
    int K = p.K[s], N = p.N[s];
    int ntl = N >> 5;
    int k0 = (id / ntl) * 64, n0 = (id % ntl) * 32;
    const float* in = p.in[s];
    __half* out = p.out[s];
    int tx = threadIdx.x, ty = threadIdx.y;   // (32, 8)
    #pragma unroll
    for (int i = 0; i < 64; i += 8)
        tile[ty + i][tx] = in[(size_t)(k0 + ty + i) * N + n0 + tx];
    __syncthreads();
    #pragma unroll
    for (int i = 0; i < 32; i += 8) {
        int n = n0 + ty + i;
        __half2 v = __floats2half2_rn(tile[tx*2][ty + i], tile[tx*2 + 1][ty + i]);
        *reinterpret_cast<__half2*>(&out[(size_t)n * K + k0 + tx*2]) = v;
    }
}

__global__ void bias_concat_kernel(const float* __restrict__ bk, const float* __restrict__ bv,
                                   const float* __restrict__ bm) {
    int d = blockIdx.x * 256 + threadIdx.x;
    float v = (d < 768) ? bk[d] : ((d < 1536) ? bv[d - 768] : bm[d - 1536]);
    g_bkvm[d] = v;
}

// ---------------- K1: LN1 + router score ----------------
__global__ void ln1_router_kernel(const float* __restrict__ x, const float* __restrict__ g1,
                                  const float* __restrict__ b1, const float* __restrict__ Wr,
                                  const float* __restrict__ br) {
    int tok = blockIdx.x;
    int t = threadIdx.x;   // 256
    const float* xr = x + (size_t)tok * D_;
    __shared__ float sh[32];
    float v[3]; float s = 0.f, sq = 0.f;
    #pragma unroll
    for (int i = 0; i < 3; i++) { float u = xr[t + 256*i]; v[i] = u; s += u; sq += u*u; }
    s  = blockReduceSum(s,  sh);
    sq = blockReduceSum(sq, sh);
    float mean = s * (1.f/D_);
    float var  = sq * (1.f/D_) - mean*mean;
    float rstd = rsqrtf(var + 1e-5f);
    float dot = 0.f;
    #pragma unroll
    for (int i = 0; i < 3; i++) {
        int d = t + 256*i;
        float nv = (v[i] - mean) * rstd * g1[d] + b1[d];
        g_nh[(size_t)tok*D_ + d] = __float2half_rn(nv);
        dot += nv * Wr[d];
    }
    dot = blockReduceSum(dot, sh);
    if (t == 0) g_scores[tok] = 1.f / (1.f + expf(-(dot + br[0])));
}

// ---------------- K2: exact top-k via histogram select + rank counting -----
__global__ void topk_kernel() {
    int b = blockIdx.x, t = threadIdx.x;   // 1024 threads
    __shared__ int hist[2048];
    __shared__ unsigned long long cand[2048];
    __shared__ float sh[32];
    __shared__ int wsum[32];
    __shared__ int s_thr, s_below, s_ncand, s_ndir;
    hist[t] = 0; hist[t + 1024] = 0;
    if (t == 0) { s_ncand = 0; s_ndir = 0; }
    float s0 = g_scores[b*L_ + t];
    float s1 = g_scores[b*L_ + t + 1024];
    g_selpos[b*L_ + t] = -1;
    g_selpos[b*L_ + t + 1024] = -1;
    float tot = blockReduceSum(s0 + s1, sh);   // includes syncs; hist init done before
    if (t == 0) g_ssum[b] = tot + 1e-6f;
    __syncthreads();
    unsigned u0 = __float_as_uint(s0) >> 21;   // 11-bit bin, monotonic for s >= 0
    unsigned u1 = __float_as_uint(s1) >> 21;
    atomicAdd(&hist[u0], 1);
    atomicAdd(&hist[u1], 1);
    __syncthreads();
    // 3-sync shfl scan: thread t owns bins 2t, 2t+1
    int h0 = hist[2*t], h1 = hist[2*t + 1];
    int pair = h0 + h1;
    int lane = t & 31, wrp = t >> 5;
    int v = pair;
    #pragma unroll
    for (int o = 1; o < 32; o <<= 1) {
        int u = __shfl_up_sync(0xffffffffu, v, o);
        if (lane >= o) v += u;
    }
    if (lane == 31) wsum[wrp] = v;
    __syncthreads();
    if (wrp == 0) {
        int u = wsum[lane];
        #pragma unroll
        for (int o = 1; o < 32; o <<= 1) {
            int z = __shfl_up_sync(0xffffffffu, u, o);
            if (lane >= o) u += z;
        }
        wsum[lane] = u;
    }
    __syncthreads();
    int incl_pair = v + (wrp ? wsum[wrp - 1] : 0);
    int excl = incl_pair - pair;
    int incl0 = excl + h0;
    if (incl0 >= KS_ && excl < KS_)       { s_thr = 2*t;     s_below = excl; }
    if (incl_pair >= KS_ && incl0 < KS_)  { s_thr = 2*t + 1; s_below = incl0; }
    __syncthreads();
    const int thr = s_thr, below = s_below;
    // pass 2: direct-select strictly-below; collect threshold-bin candidates
    #pragma unroll
    for (int q = 0; q < 2; q++) {
        int tok = t + q*1024;
        float sv = q ? s1 : s0;
        unsigned uv = q ? u1 : u0;
        if ((int)uv < thr) {
            int slot = atomicAdd(&s_ndir, 1);
            g_selidx[b*KS_ + slot] = b*L_ + tok;
            g_selpos[b*L_ + tok] = b*KS_ + slot;
        } else if ((int)uv == thr) {
            int c = atomicAdd(&s_ncand, 1);
            cand[c] = ((unsigned long long)__float_as_uint(sv) << 32) | (unsigned)tok;
        }
    }
    __syncthreads();
    // rank counting: unique keys -> unique ranks -> deterministic slots
    int ncand = s_ncand;
    int need = KS_ - below;
    for (int c = t; c < ncand; c += 1024) {
        unsigned long long key = cand[c];
        int rank = 0;
        for (int j = 0; j < ncand; j++) rank += (cand[j] < key);
        if (rank < need) {
            int tok = (int)(unsigned)(key & 0xffffffffULL);
            int slot = below + rank;
            g_selidx[b*KS_ + slot] = b*L_ + tok;
            g_selpos[b*L_ + tok] = b*KS_ + slot;
        }
    }
}

// ---------------- K3: coherence-weighted pooling (reads fp16 normed) -------
__global__ void pooled_part_kernel() {
    int b = blockIdx.y, ch = blockIdx.x;
    int d = threadIdx.x;
    float acc = 0.f;
    int l0 = ch * (L_/16);
    for (int l = l0; l < l0 + L_/16; l++)
        acc += g_scores[b*L_ + l] * __half2float(g_nh[((size_t)(b*L_ + l))*D_ + d]);
    g_ppart[(b*16 + ch)*D_ + d] = acc;
}
__global__ void pooled_fin_kernel() {
    int b = blockIdx.x; int d = threadIdx.x;
    float acc = 0.f;
    #pragma unroll
    for (int c = 0; c < 16; c++) acc += g_ppart[(b*16 + c)*D_ + d];
    g_pooled[b*D_ + d] = acc / g_ssum[b];
}
__global__ void pooledwm_kernel(const float* __restrict__ Wm) {
    int b = blockIdx.y;
    int n = blockIdx.x*256 + threadIdx.x;
    float acc = 0.f;
    for (int d = 0; d < D_; d++) acc += g_pooled[b*D_ + d] * Wm[d*D_ + n];
    g_pooledWm[b*D_ + n] = acc;
}

// ---------------- fp16 GEMM: mma m16n8k16, dual ldmatrix, 3-stage ----------
// OUT: 1 = GELU -> fp16 Ch; 4 = raw f32 partial (split-K via gridDim.z);
//      5 = KVM epilogue (K,V -> fp16 g_khf/g_vhf, mix -> f32 g_mixb; + bias).
#define RS_  40                   // smem row stride in halves (80 B)
#define HSTG_ (128*RS_*2)         // bytes per stage per operand = 10240
template<int OUT, bool GATHER>
__global__ __launch_bounds__(128)
void gemm_h(const __half* __restrict__ A, const int* __restrict__ gidx,
            const __half* __restrict__ Bt, const float* __restrict__ bias,
            float* __restrict__ C, __half* __restrict__ Ch, int M, int N, int K) {
    __shared__ __align__(128) __half As[3][128][RS_];
    __shared__ __align__(128) __half Bs[3][128][RS_];
    const int tid = threadIdx.x, lane = tid & 31, wid = tid >> 5;
    const int wm = wid & 1, wn = wid >> 1;
    const int g = lane >> 2, t = lane & 3;
    const int m0 = blockIdx.y * 128, n0 = blockIdx.x * 128;
    const int zk = K / (int)gridDim.z;
    const int z0 = blockIdx.z * zk;

    uint32_t sA = smem_u32(&As[0][0][0]);
    uint32_t sB = smem_u32(&Bs[0][0][0]);

    const __half* asrc[4]; unsigned asz[4]; uint32_t a_dst[4];
    const __half* bsrc[4]; uint32_t b_dst[4];
    #pragma unroll
    for (int j = 0; j < 4; j++) {
        int rl = j*32 + (tid >> 2);
        int ck = (tid & 3) * 8;
        int r = m0 + rl;
        bool v = r < M;
        int gr = v ? (GATHER ? gidx[r] : r) : 0;
        asrc[j]  = A + (size_t)gr*K + z0 + ck;
        asz[j]   = v ? 16u : 0u;
        a_dst[j] = sA + (uint32_t)(rl*RS_ + ck) * 2;
        bsrc[j]  = Bt + (size_t)(n0 + rl)*K + z0 + ck;
        b_dst[j] = sB + (uint32_t)(rl*RS_ + ck) * 2;
    }

    uint32_t a_ld = sA + (uint32_t)((wm*64 + (lane & 7) + ((lane >> 3) & 1)*8)*RS_
                                    + ((lane >> 4) & 1)*8) * 2;
    uint32_t b_ld = sB + (uint32_t)((wn*64 + (lane & 7) + ((lane >> 4) & 1)*8)*RS_
                                    + ((lane >> 3) & 1)*8) * 2;

    float acc[4][8][4] = {};
    const int ntiles = zk >> 5;

    auto issue = [&](int stage, int k0) {
        #pragma unroll
        for (int j = 0; j < 4; j++) cpasync16(a_dst[j] + stage*HSTG_, asrc[j] + k0, asz[j]);
        #pragma unroll
        for (int j = 0; j < 4; j++) cpasync16(b_dst[j] + stage*HSTG_, bsrc[j] + k0, 16u);
        cpcommit();
    };

    issue(0, 0);
    if (ntiles > 1) issue(1, 32);
    for (int it = 0; it < ntiles; it++) {
        int st = it % 3;
        if (it == ntiles - 1) cpwait0(); else cpwait1();
        __syncthreads();
        if (it + 2 < ntiles) issue((it + 2) % 3, (it + 2) << 5);
        #pragma unroll
        for (int kk = 0; kk < 32; kk += 16) {
            uint32_t a[4][4], bb[4][4];
            #pragma unroll
            for (int mt = 0; mt < 4; mt++)
                ldsm4(a[mt], a_ld + st*HSTG_ + mt*(16*RS_*2) + kk*2);
            #pragma unroll
            for (int np = 0; np < 4; np++)
                ldsm4(bb[np], b_ld + st*HSTG_ + np*(16*RS_*2) + kk*2);
            #pragma unroll
            for (int mt = 0; mt < 4; mt++)
                #pragma unroll
                for (int nt = 0; nt < 8; nt++) {
                    uint32_t bf[2] = { bb[nt >> 1][(nt & 1)*2], bb[nt >> 1][(nt & 1)*2 + 1] };
                    mma16n8k16h(acc[mt][nt], a[mt], bf);
                }
        }
        __syncthreads();
    }

    // ---- epilogue ----
    const size_t zout = (OUT == 4) ? (size_t)blockIdx.z * M * N : 0;
    const int seg = n0 / 768;                 // uniform per block (128 | 768)
    #pragma unroll
    for (int mt = 0; mt < 4; mt++) {
        #pragma unroll
        for (int nt = 0; nt < 8; nt++) {
            int n = n0 + wn*64 + nt*8 + t*2;
            float bi0 = (OUT == 4) ? 0.f : bias[n];
            float bi1 = (OUT == 4) ? 0.f : bias[n + 1];
            #pragma unroll
            for (int half = 0; half < 2; half++) {
                int m = m0 + wm*64 + mt*16 + g + half*8;
                if (m < M) {
                    float v0 = acc[mt][nt][half*2 + 0] + bi0;
                    float v1 = acc[mt][nt][half*2 + 1] + bi1;
                    size_t off = (size_t)m * N + n;
                    if (OUT == 1) {
                        v0 = 0.5f * v0 * (1.f + erff(v0 * 0.70710678118654752f));
                        v1 = 0.5f * v1 * (1.f + erff(v1 * 0.70710678118654752f));
                        *reinterpret_cast<__half2*>(Ch + off) = __floats2half2_rn(v0, v1);
                    } else if (OUT == 5) {
                        size_t off2 = (size_t)m * D_ + (n - seg*768);
                        if (seg == 0)
                            *reinterpret_cast<__half2*>(g_khf + off2) = __floats2half2_rn(v0, v1);
                        else if (seg == 1)
                            *reinterpret_cast<__half2*>(g_vhf + off2) = __floats2half2_rn(v0, v1);
                        else {
                            float2 o; o.x = v0; o.y = v1;
                            *(float2*)&g_mixb[off2] = o;
                        }
                    } else {
                        float2 o; o.x = v0; o.y = v1;
                        *(float2*)&C[zout + off] = o;
                    }
                }
            }
        }
    }
}

// finish split-K=QZ_ Q partials -> fp16 qselh (+ bias)
__global__ __launch_bounds__(256) void qfin(const float* __restrict__ bq) {
    int i = blockIdx.x * 256 + threadIdx.x;
    if (i < MSEL_*D_) {
        float acc = 0.f;
        #pragma unroll
        for (int z = 0; z < QZ_; z++) acc += g_fp2[(size_t)z*MSEL_*D_ + i];
        g_qselh[i] = __float2half_rn(acc + bq[i % D_]);
    }
}
// finish split-K=QZ_ Wo partials -> f32 attno (+ bias)
__global__ __launch_bounds__(256) void wofin(const float* __restrict__ bo) {
    int i = blockIdx.x * 256 + threadIdx.x;
    if (i < MSEL_*D_) {
        float acc = 0.f;
        #pragma unroll
        for (int z = 0; z < QZ_; z++) acc += g_fp2[(size_t)z*MSEL_*D_ + i];
        g_attno[i] = acc + bo[i % D_];
    }
}

// FFN2 finish: out = part0 + part1 + bias + h
__global__ __launch_bounds__(256) void ffn2_fin(const float* __restrict__ bf2,
                                                float* __restrict__ out) {
    int i = blockIdx.x * 256 + threadIdx.x;
    const float4* p0 = (const float4*)g_fp2;
    const float4* p1 = (const float4*)(g_fp2 + (size_t)BL_*D_);
    const float4* ph = (const float4*)g_h;
    float4 a = p0[i], b = p1[i], hh = ph[i];
    float4 bi = ((const float4*)bf2)[i % (D_/4)];
    float4 o;
    o.x = a.x + b.x + hh.x + bi.x;
    o.y = a.y + b.y + hh.y + bi.y;
    o.z = a.z + b.z + hh.z + bi.z;
    o.w = a.w + b.w + hh.w + bi.w;
    ((float4*)out)[i] = o;
}

// ---------------- flash attention, split-KV, fp16 mma ----------------------
#define QST_ 72
#define VST_ 40
__global__ __launch_bounds__(128) void flash_attn() {
    const int it = blockIdx.x, bh = blockIdx.y, sp = blockIdx.z;
    const int b = bh / H_, h = bh % H_;
    const int i0 = it * 64;
    __shared__ __align__(128) __half Qh[64][QST_];
    __shared__ __align__(128) __half Kh[32][QST_];
    __shared__ __align__(128) __half Vt[64][VST_];
    __shared__ __align__(128) __half Ph[4][16][VST_];
    const int tid = threadIdx.x, lane = tid & 31, w = tid >> 5;
    const int g = lane >> 2, t = lane & 3;

    #pragma unroll
    for (int q = 0; q < 4; q++) {
        int idx = q*128 + tid;
        int r = idx >> 3, c8 = (idx & 7) * 8;
        int i = i0 + r;
        uint4 v = make_uint4(0u, 0u, 0u, 0u);
        if (i < KS_) v = *(const uint4*)&g_qselh[((size_t)(b*KS_ + i))*D_ + h*DH_ + c8];
        *(uint4*)&Qh[r][c8] = v;
    }

    const uint32_t a_ldQ = smem_u32(&Qh[0][0])
        + (uint32_t)((w*16 + (lane & 7) + ((lane >> 3) & 1)*8)*QST_ + ((lane >> 4) & 1)*8) * 2;
    const uint32_t b_ldK = smem_u32(&Kh[0][0])
        + (uint32_t)(((lane & 7) + ((lane >> 4) & 1)*8)*QST_ + ((lane >> 3) & 1)*8) * 2;
    const uint32_t b_ldV = smem_u32(&Vt[0][0])
        + (uint32_t)(((lane & 7) + ((lane >> 4) & 1)*8)*VST_ + ((lane >> 3) & 1)*8) * 2;
    const uint32_t a_ldP = smem_u32(&Ph[w][0][0])
        + (uint32_t)(((lane & 7) + ((lane >> 3) & 1)*8)*VST_ + ((lane >> 4) & 1)*8) * 2;

    float accO[8][4] = {};
    float m0r = -1e30f, m1r = -1e30f, l0r = 0.f, l1r = 0.f;
    __syncthreads();

    for (int j0 = sp * JSEG_; j0 < (sp + 1) * JSEG_; j0 += 32) {
        // K chunk: straight fp16 copy (32 rows x 64 halves)
        #pragma unroll
        for (int q = 0; q < 2; q++) {
            int idx = q*128 + tid;
            int r = idx >> 3, c8 = (idx & 7) * 8;
            *(uint4*)&Kh[r][c8] =
                *(const uint4*)&g_khf[((size_t)(b*L_ + j0 + r))*D_ + h*DH_ + c8];
        }
        // V chunk transposed: Vt[dh][j], fp16 source
        #pragma unroll
        for (int q = 0; q < 2; q++) {
            int idx = q*128 + tid;
            int r = idx & 31, c0 = (idx >> 5) * 8;
            uint4 vv = *(const uint4*)&g_vhf[((size_t)(b*L_ + j0 + r))*D_ + h*DH_ + c0];
            const __half* hp = reinterpret_cast<const __half*>(&vv);
            #pragma unroll
            for (int i = 0; i < 8; i++) Vt[c0 + i][r] = hp[i];
        }
        __syncthreads();

        float sacc[4][4] = {};
        #pragma unroll
        for (int ks = 0; ks < 4; ks++) {
            uint32_t a[4], bb[2][4];
            ldsm4(a, a_ldQ + ks*32);
            ldsm4(bb[0], b_ldK + ks*32);
            ldsm4(bb[1], b_ldK + 16*QST_*2 + ks*32);
            #pragma unroll
            for (int nt = 0; nt < 4; nt++) {
                uint32_t bf[2] = { bb[nt >> 1][(nt & 1)*2], bb[nt >> 1][(nt & 1)*2 + 1] };
                mma16n8k16h(sacc[nt], a, bf);
            }
        }
        float cm0 = -1e30f, cm1 = -1e30f;
        #pragma unroll
        for (int nt = 0; nt < 4; nt++) {
            sacc[nt][0] *= 0.125f; sacc[nt][1] *= 0.125f;
            sacc[nt][2] *= 0.125f; sacc[nt][3] *= 0.125f;
            cm0 = fmaxf(cm0, fmaxf(sacc[nt][0], sacc[nt][1]));
            cm1 = fmaxf(cm1, fmaxf(sacc[nt][2], sacc[nt][3]));
        }
        cm0 = fmaxf(cm0, __shfl_xor_sync(0xffffffffu, cm0, 1));
        cm0 = fmaxf(cm0, __shfl_xor_sync(0xffffffffu, cm0, 2));
        cm1 = fmaxf(cm1, __shfl_xor_sync(0xffffffffu, cm1, 1));
        cm1 = fmaxf(cm1, __shfl_xor_sync(0xffffffffu, cm1, 2));
        float mn0 = fmaxf(m0r, cm0), mn1 = fmaxf(m1r, cm1);
        float al0 = expf(m0r - mn0), al1 = expf(m1r - mn1);
        m0r = mn0; m1r = mn1;
        float s0 = 0.f, s1 = 0.f;
        #pragma unroll
        for (int nt = 0; nt < 4; nt++) {
            float p0 = expf(sacc[nt][0] - mn0);
            float p1 = expf(sacc[nt][1] - mn0);
            float p2 = expf(sacc[nt][2] - mn1);
            float p3 = expf(sacc[nt][3] - mn1);
            s0 += p0 + p1; s1 += p2 + p3;
            int c = nt*8 + t*2;
            *reinterpret_cast<__half2*>(&Ph[w][g][c])     = __floats2half2_rn(p0, p1);
            *reinterpret_cast<__half2*>(&Ph[w][g + 8][c]) = __floats2half2_rn(p2, p3);
        }
        s0 += __shfl_xor_sync(0xffffffffu, s0, 1);
        s0 += __shfl_xor_sync(0xffffffffu, s0, 2);
        s1 += __shfl_xor_sync(0xffffffffu, s1, 1);
        s1 += __shfl_xor_sync(0xffffffffu, s1, 2);
        l0r = l0r*al0 + s0; l1r = l1r*al1 + s1;
        #pragma unroll
        for (int nt = 0; nt < 8; nt++) {
            accO[nt][0] *= al0; accO[nt][1] *= al0;
            accO[nt][2] *= al1; accO[nt][3] *= al1;
        }
        __syncwarp();
        #pragma unroll
        for (int ks = 0; ks < 2; ks++) {
            uint32_t a[4];
            ldsm4(a, a_ldP + ks*32);
            uint32_t bb[4][4];
            #pragma unroll
            for (int np = 0; np < 4; np++)
                ldsm4(bb[np], b_ldV + np*(16*VST_*2) + ks*32);
            #pragma unroll
            for (int nt = 0; nt < 8; nt++) {
                uint32_t bf[2] = { bb[nt >> 1][(nt & 1)*2], bb[nt >> 1][(nt & 1)*2 + 1] };
                mma16n8k16h(accO[nt], a, bf);
            }
        }
        __syncthreads();
    }

    const size_t slot0 = (size_t)(bh*NSPL_ + sp)*320 + it*64 + w*16 + g;
    const size_t slot1 = slot0 + 8;
    if (t == 0) {
        g_pm[slot0] = m0r; g_pl[slot0] = l0r;
        g_pm[slot1] = m1r; g_pl[slot1] = l1r;
    }
    #pragma unroll
    for (int nt = 0; nt < 8; nt++) {
        int c = nt*8 + t*2;
        g_po[slot0*64 + c]     = accO[nt][0];
        g_po[slot0*64 + c + 1] = accO[nt][1];
        g_po[slot1*64 + c]     = accO[nt][2];
        g_po[slot1*64 + c + 1] = accO[nt][3];
    }
}

// combine split-KV partials -> g_ctxh (fp16, feeds Wo GEMM)
__global__ __launch_bounds__(256) void attn_combine() {
    const int it = blockIdx.x, bh = blockIdx.y;
    const int b = bh / H_, h = bh % H_;
    __shared__ float ws[64][NSPL_];
    __shared__ float linv[64];
    const int tid = threadIdx.x;
    if (tid < 64) {
        size_t base = (size_t)(bh*NSPL_)*320 + it*64 + tid;
        float mv[NSPL_]; float m = -1e30f;
        #pragma unroll
        for (int s = 0; s < NSPL_; s++) { mv[s] = g_pm[base + (size_t)s*320]; m = fmaxf(m, mv[s]); }
        float l = 0.f;
        #pragma unroll
        for (int s = 0; s < NSPL_; s++) {
            float wv = expf(mv[s] - m);
            ws[tid][s] = wv;
            l += g_pl[base + (size_t)s*320] * wv;
        }
        linv[tid] = 1.f / l;
    }
    __syncthreads();
    #pragma unroll
    for (int q = 0; q < 16; q++) {
        int idx = q*256 + tid;
        int r = idx >> 6, c = idx & 63;
        int i = it*64 + r;
        if (i < KS_) {
            size_t slot = (size_t)(bh*NSPL_)*320 + it*64 + r;
            float acc = 0.f;
            #pragma unroll
            for (int s = 0; s < NSPL_; s++)
                acc += g_po[(slot + (size_t)s*320)*64 + c] * ws[r][s];
            g_ctxh[((size_t)(b*KS_ + i))*D_ + h*DH_ + c] = __float2half_rn(acc * linv[r]);
        }
    }
}

// ---------------- merge paths + residual + LN2 ----------------
__global__ void merge_ln2_kernel(const float* __restrict__ x, const float* __restrict__ g2,
                                 const float* __restrict__ b2) {
    int tok = blockIdx.x;
    int b = tok >> 11;
    int t = threadIdx.x;
    int pos = g_selpos[tok];
    float sc = g_scores[tok];
    __shared__ float sh[32];
    float hv[3]; float s = 0.f, sq = 0.f;
    #pragma unroll
    for (int i = 0; i < 3; i++) {
        int d = t + 256*i;
        float mg;
        if (pos >= 0) mg = g_attno[(size_t)pos*D_ + d];
        else          mg = g_mixb[(size_t)tok*D_ + d] + sc * g_pooledWm[b*D_ + d];
        float u = x[(size_t)tok*D_ + d] + mg;
        hv[i] = u;
        g_h[(size_t)tok*D_ + d] = u;
        s += u; sq += u*u;
    }
    s  = blockReduceSum(s,  sh);
    sq = blockReduceSum(sq, sh);
    float mean = s * (1.f/D_);
    float rstd = rsqrtf(sq*(1.f/D_) - mean*mean + 1e-5f);
    #pragma unroll
    for (int i = 0; i < 3; i++) {
        int d = t + 256*i;
        g_n2h[(size_t)tok*D_ + d] = __float2half_rn((hv[i] - mean) * rstd * g2[d] + b2[d]);
    }
}

// ---------------- host launch ----------------
extern "C" void kernel_launch(void* const* d_in, const int* in_sizes, int n_in,
                              void* d_out, int out_size) {
    (void)in_sizes; (void)n_in; (void)out_size;
    const float* x   = (const float*)d_in[0];
    const float* g1  = (const float*)d_in[1];
    const float* b1  = (const float*)d_in[2];
    const float* g2  = (const float*)d_in[3];
    const float* b2  = (const float*)d_in[4];
    const float* Wr  = (const float*)d_in[5];
    const float* br  = (const float*)d_in[6];
    const float* Wq  = (const float*)d_in[7];
    const float* bq  = (const float*)d_in[8];
    const float* Wk  = (const float*)d_in[9];
    const float* bk  = (const float*)d_in[10];
    const float* Wv  = (const float*)d_in[11];
    const float* bv  = (const float*)d_in[12];
    const float* Wo  = (const float*)d_in[13];
    const float* bo  = (const float*)d_in[14];
    const float* Wm  = (const float*)d_in[15];
    const float* bm  = (const float*)d_in[16];
    const float* W1  = (const float*)d_in[17];
    const float* bf1 = (const float*)d_in[18];
    const float* W2  = (const float*)d_in[19];
    const float* bf2 = (const float*)d_in[20];
    float* out = (float*)d_out;

    float *p_bkvm, *p_fp2;
    __half *p_nh, *p_qselh, *p_ctxh, *p_n2h, *p_th, *p_whuf;
    int* p_selidx;
    cudaGetSymbolAddress((void**)&p_nh,     g_nh);
    cudaGetSymbolAddress((void**)&p_bkvm,   g_bkvm);
    cudaGetSymbolAddress((void**)&p_qselh,  g_qselh);
    cudaGetSymbolAddress((void**)&p_ctxh,   g_ctxh);
    cudaGetSymbolAddress((void**)&p_n2h,    g_n2h);
    cudaGetSymbolAddress((void**)&p_th,     g_th);
    cudaGetSymbolAddress((void**)&p_whuf,   g_whuf);
    cudaGetSymbolAddress((void**)&p_selidx, g_selidx);
    cudaGetSymbolAddress((void**)&p_fp2,    g_fp2);

    __half* rKVM = p_whuf;                         // [2304][768]
    __half* rWq  = p_whuf + 3*(size_t)WSZ_;
    __half* rWo  = p_whuf + 4*(size_t)WSZ_;
    __half* rW1  = p_whuf + 5*(size_t)WSZ_;
    __half* rW2  = rW1 + (size_t)W1SZ_;

    // 0. fused weight prep (single launch)
    TP7 tp;
    tp.in[0]=Wk; tp.out[0]=rKVM + 0*(size_t)WSZ_; tp.K[0]=D_; tp.N[0]=D_;
    tp.in[1]=Wv; tp.out[1]=rKVM + 1*(size_t)WSZ_; tp.K[1]=D_; tp.N[1]=D_;
    tp.in[2]=Wm; tp.out[2]=rKVM + 2*(size_t)WSZ_; tp.K[2]=D_; tp.N[2]=D_;
    tp.in[3]=Wq; tp.out[3]=rWq;                   tp.K[3]=D_; tp.N[3]=D_;
    tp.in[4]=Wo; tp.out[4]=rWo;                   tp.K[4]=D_; tp.N[4]=D_;
    tp.in[5]=W1; tp.out[5]=rW1;                   tp.K[5]=D_; tp.N[5]=F_;
    tp.in[6]=W2; tp.out[6]=rW2;                   tp.K[6]=F_; tp.N[6]=D_;
    int total = 0;
    for (int s = 0; s < 7; s++) {
        tp.cum[s] = total;
        total += (tp.K[s]/64) * (tp.N[s]/32);
    }
    tp.cum[7] = total;
    transpose_all_kernel<<<total, dim3(32, 8)>>>(tp);
    bias_concat_kernel<<<9, 256>>>(bk, bv, bm);
    // 1. LN1 + router
    ln1_router_kernel<<<BL_, 256>>>(x, g1, b1, Wr, br);
    // 2. top-k (histogram select + rank counting)
    topk_kernel<<<B_, 1024>>>();
    // 3. pooling path
    pooled_part_kernel<<<dim3(16, B_), D_>>>();
    pooled_fin_kernel<<<B_, D_>>>();
    pooledwm_kernel<<<dim3(3, B_), 256>>>(Wm);
    // 4. fused K|V|mix projection (N=2304): K,V -> fp16, mix -> f32
    gemm_h<5,false><<<dim3(NKVM_/128, BL_/128), 128>>>(p_nh, nullptr, rKVM, p_bkvm, nullptr, nullptr, BL_, NKVM_, D_);
    // 5. Q for selected rows (gather, split-K=4) -> fin -> fp16
    gemm_h<4,true ><<<dim3(D_/128, (MSEL_+127)/128, QZ_), 128>>>(p_nh, p_selidx, rWq, nullptr, p_fp2, nullptr, MSEL_, D_, D_);
    qfin<<<(MSEL_*D_ + 255)/256, 256>>>(bq);
    // 6. flash attention (split-KV, fp16 mma) + combine
    flash_attn<<<dim3(5, B_*H_, NSPL_), 128>>>();
    attn_combine<<<dim3(5, B_*H_), 256>>>();
    // Wo projection (split-K=4) -> fin -> f32 attno
    gemm_h<4,false><<<dim3(D_/128, (MSEL_+127)/128, QZ_), 128>>>(p_ctxh, nullptr, rWo, nullptr, p_fp2, nullptr, MSEL_, D_, D_);
    wofin<<<(MSEL_*D_ + 255)/256, 256>>>(bo);
    // 7. merge + residual + LN2
    merge_ln2_kernel<<<BL_, 256>>>(x, g2, b2);
    // 8. FFN: FFN1 GELU -> fp16; FFN2 split-K=2 -> partials -> fin(out)
    gemm_h<1,false><<<dim3(F_/128, BL_/128), 128>>>(p_n2h, nullptr, rW1, bf1, nullptr, p_th, BL_, F_, D_);
    gemm_h<4,false><<<dim3(D_/128, BL_/128, 2), 128>>>(p_th, nullptr, rW2, nullptr, p_fp2, nullptr, BL_, D_, F_);
    ffn2_fin<<<(BL_*D_/4)/256, 256>>>(bf2, out);
}